// round 1
// baseline (speedup 1.0000x reference)
#include <cuda_runtime.h>
#include <cstdint>

// ============================================================================
// DIN scorer, fused fp32 baseline.
//
// Shapes: B=2048, L=200, D=128. Output: float[2048].
//
// Kernel 1 (din_attention_kernel): one CTA per batch b.
//   Algebra: key @ aw1 + ab1  ==  s @ Mb + cvec   where
//     Mb[k][j]  = t[k]*aw1[128+k][j] - aw1[256+k][j]     (per-batch, 64KB smem)
//     cvec[j]   = ab1[j] + sum_k t[k]*(aw1[k][j] + aw1[256+k][j])
//   Then per 128-row chunk of the L=200 sequence:
//     stage gathered s rows -> GEMM1 (128x128x128, 8x8 microtile) -> sigmoid
//     -> GEMM2 (x aw2, 128->64) -> sigmoid -> dot afw -> score (masked)
//     -> attn[d] += score[row]*s[row][d]
//   attn written to scratch g_attn.
//
// Then: attn2+cat kernel, three tiled sigmoid-GEMMs (dw1,dw2,dw3), final dot.
// ============================================================================

#define BB 2048
#define LL 200
#define DD 128

// ---- global scratch (static __device__: no allocations anywhere) ----
__device__ float g_attn[BB * 128];   // attn_seq (pre-nw)
__device__ float g_cat [BB * 384];   // [attn2 | t | t*attn2]
__device__ float g_g1  [BB * 512];
__device__ float g_g2  [BB * 256];
__device__ float g_g3  [BB * 128];

__device__ __forceinline__ float sigm(float x) {
    return 1.0f / (1.0f + __expf(-x));
}

// ---- smem layout for kernel 1 (float offsets) ----
#define SM_MB   0          // Mb[128][128]            65536 B
#define SM_S    16384      // sBuf[128][128]          65536 B
#define SM_H1   32768      // h1Buf[128][128]         65536 B
#define SM_AW2  49152      // aw2s[128][64]           32768 B
#define SM_T    57344      // t[128]
#define SM_C    57472      // cvec[128]
#define SM_SC   57600      // score[128]
#define SM_AFW  57728      // afw[64]
#define SM_AB2  57792      // ab2[64]
#define SM_TOT  57856      // 231,424 bytes  (<= 232,448 max dyn smem)

__global__ __launch_bounds__(256, 1)
void din_attention_kernel(const int*   __restrict__ in_item_id,
                          const int*   __restrict__ item_id,
                          const float* __restrict__ item_emb,
                          const float* __restrict__ aw1,
                          const float* __restrict__ ab1,
                          const float* __restrict__ aw2,
                          const float* __restrict__ ab2,
                          const float* __restrict__ afw,
                          const float* __restrict__ afb)
{
    extern __shared__ float sm[];
    const int b   = blockIdx.x;
    const int tid = threadIdx.x;
    float* Mb = sm + SM_MB;

    // ---- stage t, aw2, afw, ab2 ----
    if (tid < 128) {
        long id = (long)item_id[b];
        sm[SM_T + tid] = item_emb[id * 128 + tid];
    }
    for (int e = tid; e < 128 * 64; e += 256) sm[SM_AW2 + e] = __ldg(&aw2[e]);
    if (tid < 64) {
        sm[SM_AFW + tid] = __ldg(&afw[tid]);
        sm[SM_AB2 + tid] = __ldg(&ab2[tid]);
    }
    __syncthreads();

    // ---- build Mb = t .* A1 - A2  (A1 = aw1[128:256], A2 = aw1[256:384]) ----
    for (int e = tid; e < 128 * 128; e += 256) {
        int k = e >> 7, j = e & 127;
        Mb[e] = sm[SM_T + k] * __ldg(&aw1[(128 + k) * 128 + j])
                             - __ldg(&aw1[(256 + k) * 128 + j]);
    }
    // ---- cvec = ab1 + t @ (A0 + A2) ----
    if (tid < 128) {
        int j = tid;
        float acc = __ldg(&ab1[j]);
        #pragma unroll 4
        for (int k = 0; k < 128; ++k)
            acc += sm[SM_T + k] * (__ldg(&aw1[k * 128 + j]) +
                                   __ldg(&aw1[(256 + k) * 128 + j]));
        sm[SM_C + j] = acc;
    }
    const float afb0 = __ldg(&afb[0]);

    const int jg = tid & 15;       // 0..15
    const int rg = tid >> 4;       // 0..15
    const int r0 = rg * 8;
    const int j0 = jg * 8;         // GEMM1 output cols
    const int j2 = jg * 4;         // GEMM2 output cols

    float attnReg = 0.0f;          // valid for tid < 128 (d = tid)
    __syncthreads();

    for (int chunk = 0; chunk < 2; ++chunk) {
        const int base = chunk * 128;
        const int cr   = (chunk == 0) ? 128 : (LL - 128);   // 128 then 72
        const bool act = (r0 < cr);

        // ---- stage gathered sequence rows (cr x 128 floats, vec4) ----
        for (int e = tid; e < cr * 32; e += 256) {
            int row = e >> 5, q = e & 31;
            long id = (long)__ldg(&in_item_id[b * LL + base + row]);
            const float4* src = reinterpret_cast<const float4*>(item_emb + id * 128);
            reinterpret_cast<float4*>(sm + SM_S)[row * 32 + q] = __ldg(&src[q]);
        }
        __syncthreads();

        // ================= GEMM1: h1 = sigmoid(s @ Mb + cvec) ===============
        if (act) {
            float acc[8][8];
            #pragma unroll
            for (int r = 0; r < 8; ++r)
                #pragma unroll
                for (int j = 0; j < 8; ++j) acc[r][j] = 0.0f;

            #pragma unroll 2
            for (int k = 0; k < 128; k += 4) {
                float4 a4[8];
                #pragma unroll
                for (int r = 0; r < 8; ++r)
                    a4[r] = *reinterpret_cast<const float4*>(sm + SM_S + (r0 + r) * 128 + k);
                #pragma unroll
                for (int kk = 0; kk < 4; ++kk) {
                    const float* mrow = Mb + (k + kk) * 128 + j0;
                    float4 b0 = *reinterpret_cast<const float4*>(mrow);
                    float4 b1 = *reinterpret_cast<const float4*>(mrow + 4);
                    #pragma unroll
                    for (int r = 0; r < 8; ++r) {
                        float av = (&a4[r].x)[kk];
                        acc[r][0] += av * b0.x; acc[r][1] += av * b0.y;
                        acc[r][2] += av * b0.z; acc[r][3] += av * b0.w;
                        acc[r][4] += av * b1.x; acc[r][5] += av * b1.y;
                        acc[r][6] += av * b1.z; acc[r][7] += av * b1.w;
                    }
                }
            }
            // epilogue: sigmoid + store h1
            #pragma unroll
            for (int r = 0; r < 8; ++r) {
                float4 h0, h1v;
                h0.x  = sigm(acc[r][0] + sm[SM_C + j0 + 0]);
                h0.y  = sigm(acc[r][1] + sm[SM_C + j0 + 1]);
                h0.z  = sigm(acc[r][2] + sm[SM_C + j0 + 2]);
                h0.w  = sigm(acc[r][3] + sm[SM_C + j0 + 3]);
                h1v.x = sigm(acc[r][4] + sm[SM_C + j0 + 4]);
                h1v.y = sigm(acc[r][5] + sm[SM_C + j0 + 5]);
                h1v.z = sigm(acc[r][6] + sm[SM_C + j0 + 6]);
                h1v.w = sigm(acc[r][7] + sm[SM_C + j0 + 7]);
                *reinterpret_cast<float4*>(sm + SM_H1 + (r0 + r) * 128 + j0)     = h0;
                *reinterpret_cast<float4*>(sm + SM_H1 + (r0 + r) * 128 + j0 + 4) = h1v;
            }
        }
        __syncthreads();

        // ========== GEMM2: h2 = sigmoid(h1 @ aw2 + ab2);  p = h2 @ afw ======
        float acc2[8][4];
        #pragma unroll
        for (int r = 0; r < 8; ++r)
            #pragma unroll
            for (int j = 0; j < 4; ++j) acc2[r][j] = 0.0f;

        if (act) {
            #pragma unroll 2
            for (int k = 0; k < 128; k += 4) {
                float4 a4[8];
                #pragma unroll
                for (int r = 0; r < 8; ++r)
                    a4[r] = *reinterpret_cast<const float4*>(sm + SM_H1 + (r0 + r) * 128 + k);
                #pragma unroll
                for (int kk = 0; kk < 4; ++kk) {
                    float4 bq = *reinterpret_cast<const float4*>(sm + SM_AW2 + (k + kk) * 64 + j2);
                    #pragma unroll
                    for (int r = 0; r < 8; ++r) {
                        float av = (&a4[r].x)[kk];
                        acc2[r][0] += av * bq.x; acc2[r][1] += av * bq.y;
                        acc2[r][2] += av * bq.z; acc2[r][3] += av * bq.w;
                    }
                }
            }
        }
        // partial score per thread; ALL threads join the shuffles
        #pragma unroll
        for (int r = 0; r < 8; ++r) {
            float v = 0.0f;
            if (act) {
                #pragma unroll
                for (int j = 0; j < 4; ++j)
                    v += sigm(acc2[r][j] + sm[SM_AB2 + j2 + j]) * sm[SM_AFW + j2 + j];
            }
            v += __shfl_xor_sync(0xffffffffu, v, 1);
            v += __shfl_xor_sync(0xffffffffu, v, 2);
            v += __shfl_xor_sync(0xffffffffu, v, 4);
            v += __shfl_xor_sync(0xffffffffu, v, 8);
            if (jg == 0 && act) sm[SM_SC + r0 + r] = v;
        }
        __syncthreads();

        // ---- finalize score: +afb, mask where id==0 ----
        if (tid < cr) {
            int id = __ldg(&in_item_id[b * LL + base + tid]);
            sm[SM_SC + tid] = (id == 0) ? 0.0f : (sm[SM_SC + tid] + afb0);
        }
        __syncthreads();

        // ---- attn[d] += sum_row score[row]*s[row][d] ----
        if (tid < 128) {
            #pragma unroll 4
            for (int row = 0; row < cr; ++row)
                attnReg += sm[SM_SC + row] * sm[SM_S + row * 128 + tid];
        }
        __syncthreads();   // before sBuf is overwritten by next chunk
    }

    if (tid < 128) g_attn[b * 128 + tid] = attnReg;
}

// ============================================================================
// attn2 = attn @ nw + nb;  cat = [attn2 | t | t*attn2]   (16 batches / block)
// ============================================================================
__global__ __launch_bounds__(128)
void attn2_cat_kernel(const int*   __restrict__ item_id,
                      const float* __restrict__ item_emb,
                      const float* __restrict__ nw,
                      const float* __restrict__ nb)
{
    __shared__ float attnS[16 * 128];
    __shared__ float tS[16 * 128];
    const int b0  = blockIdx.x * 16;
    const int tid = threadIdx.x;

    for (int e = tid; e < 16 * 128; e += 128) {
        int bb = e >> 7, j = e & 127;
        attnS[e] = g_attn[(b0 + bb) * 128 + j];
        long id  = (long)__ldg(&item_id[b0 + bb]);
        tS[e]    = __ldg(&item_emb[id * 128 + j]);
    }
    __syncthreads();

    const int j = tid;
    float acc[16];
    float nbj = __ldg(&nb[j]);
    #pragma unroll
    for (int bb = 0; bb < 16; ++bb) acc[bb] = nbj;

    #pragma unroll 4
    for (int k = 0; k < 128; ++k) {
        float w = __ldg(&nw[k * 128 + j]);
        #pragma unroll
        for (int bb = 0; bb < 16; ++bb) acc[bb] += attnS[bb * 128 + k] * w;
    }
    #pragma unroll
    for (int bb = 0; bb < 16; ++bb) {
        int b = b0 + bb;
        float a2 = acc[bb];
        float t  = tS[bb * 128 + j];
        g_cat[b * 384 + j]       = a2;
        g_cat[b * 384 + 128 + j] = t;
        g_cat[b * 384 + 256 + j] = t * a2;
    }
}

// ============================================================================
// Generic tiled sigmoid GEMM: out = sigmoid(A(2048xK) @ W(KxNTOT) + bias)
// Tile: M=64, N=128, 8x8 microtile, 128 threads. SEL picks scratch buffers.
// ============================================================================
template<int K, int NTOT, int SEL>
__global__ __launch_bounds__(128)
void mlp_sig_kernel(const float* __restrict__ W,
                    const float* __restrict__ bias)
{
    const float* A = (SEL == 0) ? g_cat : (SEL == 1) ? g_g1 : g_g2;
    float*       O = (SEL == 0) ? g_g1  : (SEL == 1) ? g_g2 : g_g3;

    __shared__ float As[32 * 68];      // [kk][row], padded stride 68
    __shared__ float Ws[32 * 128];     // [kk][j]

    const int m0  = blockIdx.x * 64;
    const int n0  = blockIdx.y * 128;
    const int tid = threadIdx.x;
    const int jg  = tid & 15;          // 0..15 -> j0 = jg*8
    const int rg  = tid >> 4;          // 0..7  -> r0 = rg*8
    const int r0  = rg * 8, j0 = jg * 8;

    float acc[8][8];
    #pragma unroll
    for (int r = 0; r < 8; ++r)
        #pragma unroll
        for (int j = 0; j < 8; ++j) acc[r][j] = 0.0f;

    for (int k0 = 0; k0 < K; k0 += 32) {
        for (int e = tid; e < 64 * 32; e += 128) {
            int row = e >> 5, kk = e & 31;
            As[kk * 68 + row] = __ldg(&A[(long)(m0 + row) * K + k0 + kk]);
        }
        for (int e = tid; e < 32 * 128; e += 128) {
            int kk = e >> 7, j = e & 127;
            Ws[kk * 128 + j] = __ldg(&W[(long)(k0 + kk) * NTOT + n0 + j]);
        }
        __syncthreads();
        #pragma unroll 8
        for (int kk = 0; kk < 32; ++kk) {
            float4 a0 = *reinterpret_cast<const float4*>(As + kk * 68 + r0);
            float4 a1 = *reinterpret_cast<const float4*>(As + kk * 68 + r0 + 4);
            float4 b0 = *reinterpret_cast<const float4*>(Ws + kk * 128 + j0);
            float4 b1 = *reinterpret_cast<const float4*>(Ws + kk * 128 + j0 + 4);
            float av[8] = {a0.x, a0.y, a0.z, a0.w, a1.x, a1.y, a1.z, a1.w};
            #pragma unroll
            for (int r = 0; r < 8; ++r) {
                acc[r][0] += av[r] * b0.x; acc[r][1] += av[r] * b0.y;
                acc[r][2] += av[r] * b0.z; acc[r][3] += av[r] * b0.w;
                acc[r][4] += av[r] * b1.x; acc[r][5] += av[r] * b1.y;
                acc[r][6] += av[r] * b1.z; acc[r][7] += av[r] * b1.w;
            }
        }
        __syncthreads();
    }

    #pragma unroll
    for (int r = 0; r < 8; ++r) {
        float4 o0, o1;
        o0.x = sigm(acc[r][0] + __ldg(&bias[n0 + j0 + 0]));
        o0.y = sigm(acc[r][1] + __ldg(&bias[n0 + j0 + 1]));
        o0.z = sigm(acc[r][2] + __ldg(&bias[n0 + j0 + 2]));
        o0.w = sigm(acc[r][3] + __ldg(&bias[n0 + j0 + 3]));
        o1.x = sigm(acc[r][4] + __ldg(&bias[n0 + j0 + 4]));
        o1.y = sigm(acc[r][5] + __ldg(&bias[n0 + j0 + 5]));
        o1.z = sigm(acc[r][6] + __ldg(&bias[n0 + j0 + 6]));
        o1.w = sigm(acc[r][7] + __ldg(&bias[n0 + j0 + 7]));
        *reinterpret_cast<float4*>(O + (long)(m0 + r0 + r) * NTOT + n0 + j0)     = o0;
        *reinterpret_cast<float4*>(O + (long)(m0 + r0 + r) * NTOT + n0 + j0 + 4) = o1;
    }
}

// ============================================================================
// out[b] = g3[b] . fw + fb + item_bias_tab[item_id[b]]   (one warp per batch)
// ============================================================================
__global__ __launch_bounds__(128)
void out_kernel(const float* __restrict__ item_bias_tab,
                const int*   __restrict__ item_id,
                const float* __restrict__ fw,
                const float* __restrict__ fb,
                float*       __restrict__ out)
{
    const int b    = blockIdx.x * 4 + (threadIdx.x >> 5);
    const int lane = threadIdx.x & 31;
    float v = 0.0f;
    #pragma unroll
    for (int i = 0; i < 4; ++i)
        v += g_g3[b * 128 + lane + 32 * i] * __ldg(&fw[lane + 32 * i]);
    #pragma unroll
    for (int m = 16; m > 0; m >>= 1) v += __shfl_xor_sync(0xffffffffu, v, m);
    if (lane == 0)
        out[b] = v + __ldg(&fb[0]) + __ldg(&item_bias_tab[item_id[b]]);
}

// ============================================================================
extern "C" void kernel_launch(void* const* d_in, const int* in_sizes, int n_in,
                              void* d_out, int out_size)
{
    const int*   in_item_id    = (const int*)  d_in[0];
    const int*   item_id       = (const int*)  d_in[1];
    const float* item_emb      = (const float*)d_in[2];
    const float* item_bias_tab = (const float*)d_in[3];
    const float* aw1 = (const float*)d_in[4];
    const float* ab1 = (const float*)d_in[5];
    const float* aw2 = (const float*)d_in[6];
    const float* ab2 = (const float*)d_in[7];
    const float* afw = (const float*)d_in[8];
    const float* afb = (const float*)d_in[9];
    const float* nw  = (const float*)d_in[10];
    const float* nb  = (const float*)d_in[11];
    const float* dw1 = (const float*)d_in[12];
    const float* db1 = (const float*)d_in[13];
    const float* dw2 = (const float*)d_in[14];
    const float* db2 = (const float*)d_in[15];
    const float* dw3 = (const float*)d_in[16];
    const float* db3 = (const float*)d_in[17];
    const float* fw  = (const float*)d_in[18];
    const float* fb  = (const float*)d_in[19];
    float* out = (float*)d_out;

    const size_t smem1 = SM_TOT * sizeof(float);   // 231,424 B
    cudaFuncSetAttribute(din_attention_kernel,
                         cudaFuncAttributeMaxDynamicSharedMemorySize, (int)smem1);

    din_attention_kernel<<<BB, 256, smem1>>>(in_item_id, item_id, item_emb,
                                             aw1, ab1, aw2, ab2, afw, afb);
    attn2_cat_kernel<<<BB / 16, 128>>>(item_id, item_emb, nw, nb);
    mlp_sig_kernel<384, 512, 0><<<dim3(32, 4), 128>>>(dw1, db1);
    mlp_sig_kernel<512, 256, 1><<<dim3(32, 2), 128>>>(dw2, db2);
    mlp_sig_kernel<256, 128, 2><<<dim3(32, 1), 128>>>(dw3, db3);
    out_kernel<<<BB / 4, 128>>>(item_bias_tab, item_id, fw, fb, out);
}

// round 2
// speedup vs baseline: 1.1574x; 1.1574x over previous
#include <cuda_runtime.h>
#include <cstdint>

// ============================================================================
// DIN scorer. Kernel 1 (per-batch fused attention) unchanged from R0 baseline.
// R1: entire MLP tail (attn2/nw, cat, dw1, dw2, dw3, fw, biases) fused into a
// single kernel: 128 CTAs x 256 threads, 16 batches per CTA, all activations
// in smem, weights streamed from L2 with 16-batch register blocking.
// ============================================================================

#define BB 2048
#define LL 200
#define DD 128

// ---- global scratch (static __device__: no allocations anywhere) ----
__device__ float g_attn[BB * 128];   // attn_seq (pre-nw)

__device__ __forceinline__ float sigm(float x) {
    return 1.0f / (1.0f + __expf(-x));
}

// ---- smem layout for kernel 1 (float offsets) ----
#define SM_MB   0          // Mb[128][128]            65536 B
#define SM_S    16384      // sBuf[128][128]          65536 B
#define SM_H1   32768      // h1Buf[128][128]         65536 B
#define SM_AW2  49152      // aw2s[128][64]           32768 B
#define SM_T    57344      // t[128]
#define SM_C    57472      // cvec[128]
#define SM_SC   57600      // score[128]
#define SM_AFW  57728      // afw[64]
#define SM_AB2  57792      // ab2[64]
#define SM_TOT  57856      // 231,424 bytes

__global__ __launch_bounds__(256, 1)
void din_attention_kernel(const int*   __restrict__ in_item_id,
                          const int*   __restrict__ item_id,
                          const float* __restrict__ item_emb,
                          const float* __restrict__ aw1,
                          const float* __restrict__ ab1,
                          const float* __restrict__ aw2,
                          const float* __restrict__ ab2,
                          const float* __restrict__ afw,
                          const float* __restrict__ afb)
{
    extern __shared__ float sm[];
    const int b   = blockIdx.x;
    const int tid = threadIdx.x;
    float* Mb = sm + SM_MB;

    // ---- stage t, aw2, afw, ab2 ----
    if (tid < 128) {
        long id = (long)item_id[b];
        sm[SM_T + tid] = item_emb[id * 128 + tid];
    }
    for (int e = tid; e < 128 * 64; e += 256) sm[SM_AW2 + e] = __ldg(&aw2[e]);
    if (tid < 64) {
        sm[SM_AFW + tid] = __ldg(&afw[tid]);
        sm[SM_AB2 + tid] = __ldg(&ab2[tid]);
    }
    __syncthreads();

    // ---- build Mb = t .* A1 - A2  (A1 = aw1[128:256], A2 = aw1[256:384]) ----
    for (int e = tid; e < 128 * 128; e += 256) {
        int k = e >> 7, j = e & 127;
        Mb[e] = sm[SM_T + k] * __ldg(&aw1[(128 + k) * 128 + j])
                             - __ldg(&aw1[(256 + k) * 128 + j]);
    }
    // ---- cvec = ab1 + t @ (A0 + A2) ----
    if (tid < 128) {
        int j = tid;
        float acc = __ldg(&ab1[j]);
        #pragma unroll 4
        for (int k = 0; k < 128; ++k)
            acc += sm[SM_T + k] * (__ldg(&aw1[k * 128 + j]) +
                                   __ldg(&aw1[(256 + k) * 128 + j]));
        sm[SM_C + j] = acc;
    }
    const float afb0 = __ldg(&afb[0]);

    const int jg = tid & 15;       // 0..15
    const int rg = tid >> 4;       // 0..15
    const int r0 = rg * 8;
    const int j0 = jg * 8;         // GEMM1 output cols
    const int j2 = jg * 4;         // GEMM2 output cols

    float attnReg = 0.0f;          // valid for tid < 128 (d = tid)
    __syncthreads();

    for (int chunk = 0; chunk < 2; ++chunk) {
        const int base = chunk * 128;
        const int cr   = (chunk == 0) ? 128 : (LL - 128);   // 128 then 72
        const bool act = (r0 < cr);

        // ---- stage gathered sequence rows (cr x 128 floats, vec4) ----
        for (int e = tid; e < cr * 32; e += 256) {
            int row = e >> 5, q = e & 31;
            long id = (long)__ldg(&in_item_id[b * LL + base + row]);
            const float4* src = reinterpret_cast<const float4*>(item_emb + id * 128);
            reinterpret_cast<float4*>(sm + SM_S)[row * 32 + q] = __ldg(&src[q]);
        }
        __syncthreads();

        // ================= GEMM1: h1 = sigmoid(s @ Mb + cvec) ===============
        if (act) {
            float acc[8][8];
            #pragma unroll
            for (int r = 0; r < 8; ++r)
                #pragma unroll
                for (int j = 0; j < 8; ++j) acc[r][j] = 0.0f;

            #pragma unroll 2
            for (int k = 0; k < 128; k += 4) {
                float4 a4[8];
                #pragma unroll
                for (int r = 0; r < 8; ++r)
                    a4[r] = *reinterpret_cast<const float4*>(sm + SM_S + (r0 + r) * 128 + k);
                #pragma unroll
                for (int kk = 0; kk < 4; ++kk) {
                    const float* mrow = Mb + (k + kk) * 128 + j0;
                    float4 b0 = *reinterpret_cast<const float4*>(mrow);
                    float4 b1 = *reinterpret_cast<const float4*>(mrow + 4);
                    #pragma unroll
                    for (int r = 0; r < 8; ++r) {
                        float av = (&a4[r].x)[kk];
                        acc[r][0] += av * b0.x; acc[r][1] += av * b0.y;
                        acc[r][2] += av * b0.z; acc[r][3] += av * b0.w;
                        acc[r][4] += av * b1.x; acc[r][5] += av * b1.y;
                        acc[r][6] += av * b1.z; acc[r][7] += av * b1.w;
                    }
                }
            }
            // epilogue: sigmoid + store h1
            #pragma unroll
            for (int r = 0; r < 8; ++r) {
                float4 h0, h1v;
                h0.x  = sigm(acc[r][0] + sm[SM_C + j0 + 0]);
                h0.y  = sigm(acc[r][1] + sm[SM_C + j0 + 1]);
                h0.z  = sigm(acc[r][2] + sm[SM_C + j0 + 2]);
                h0.w  = sigm(acc[r][3] + sm[SM_C + j0 + 3]);
                h1v.x = sigm(acc[r][4] + sm[SM_C + j0 + 4]);
                h1v.y = sigm(acc[r][5] + sm[SM_C + j0 + 5]);
                h1v.z = sigm(acc[r][6] + sm[SM_C + j0 + 6]);
                h1v.w = sigm(acc[r][7] + sm[SM_C + j0 + 7]);
                *reinterpret_cast<float4*>(sm + SM_H1 + (r0 + r) * 128 + j0)     = h0;
                *reinterpret_cast<float4*>(sm + SM_H1 + (r0 + r) * 128 + j0 + 4) = h1v;
            }
        }
        __syncthreads();

        // ========== GEMM2: h2 = sigmoid(h1 @ aw2 + ab2);  p = h2 @ afw ======
        float acc2[8][4];
        #pragma unroll
        for (int r = 0; r < 8; ++r)
            #pragma unroll
            for (int j = 0; j < 4; ++j) acc2[r][j] = 0.0f;

        if (act) {
            #pragma unroll 2
            for (int k = 0; k < 128; k += 4) {
                float4 a4[8];
                #pragma unroll
                for (int r = 0; r < 8; ++r)
                    a4[r] = *reinterpret_cast<const float4*>(sm + SM_H1 + (r0 + r) * 128 + k);
                #pragma unroll
                for (int kk = 0; kk < 4; ++kk) {
                    float4 bq = *reinterpret_cast<const float4*>(sm + SM_AW2 + (k + kk) * 64 + j2);
                    #pragma unroll
                    for (int r = 0; r < 8; ++r) {
                        float av = (&a4[r].x)[kk];
                        acc2[r][0] += av * bq.x; acc2[r][1] += av * bq.y;
                        acc2[r][2] += av * bq.z; acc2[r][3] += av * bq.w;
                    }
                }
            }
        }
        // partial score per thread; ALL threads join the shuffles
        #pragma unroll
        for (int r = 0; r < 8; ++r) {
            float v = 0.0f;
            if (act) {
                #pragma unroll
                for (int j = 0; j < 4; ++j)
                    v += sigm(acc2[r][j] + sm[SM_AB2 + j2 + j]) * sm[SM_AFW + j2 + j];
            }
            v += __shfl_xor_sync(0xffffffffu, v, 1);
            v += __shfl_xor_sync(0xffffffffu, v, 2);
            v += __shfl_xor_sync(0xffffffffu, v, 4);
            v += __shfl_xor_sync(0xffffffffu, v, 8);
            if (jg == 0 && act) sm[SM_SC + r0 + r] = v;
        }
        __syncthreads();

        // ---- finalize score: +afb, mask where id==0 ----
        if (tid < cr) {
            int id = __ldg(&in_item_id[b * LL + base + tid]);
            sm[SM_SC + tid] = (id == 0) ? 0.0f : (sm[SM_SC + tid] + afb0);
        }
        __syncthreads();

        // ---- attn[d] += sum_row score[row]*s[row][d] ----
        if (tid < 128) {
            #pragma unroll 4
            for (int row = 0; row < cr; ++row)
                attnReg += sm[SM_SC + row] * sm[SM_S + row * 128 + tid];
        }
        __syncthreads();   // before sBuf is overwritten by next chunk
    }

    if (tid < 128) g_attn[b * 128 + tid] = attnReg;
}

// ============================================================================
// Fused MLP tail: per CTA of 16 batches (128 CTAs x 256 threads):
//   attn2 = attn @ nw + nb
//   cat   = [attn2 | t | t*attn2]                           (smem)
//   g1    = sigmoid(cat @ dw1 + db1)      384 -> 512        (smem)
//   g2    = sigmoid(g1  @ dw2 + db2)      512 -> 256        (smem)
//   g3    = sigmoid(g2  @ dw3 + db3)      256 -> 128        (smem)
//   out   = g3 . fw + fb + item_bias_tab[item_id]
// Weights streamed from L2, coalesced, each value reused across 16 batches.
// A-operand smem loads are warp-uniform (broadcast, conflict-free).
// ============================================================================

// float-offset smem layout (24576 floats = 98304 B dynamic)
#define TM_ATTN 0                 // [16][128]
#define TM_T    2048              // [16][128]
#define TM_CAT  4096              // [16][384]
#define TM_H1   10240             // [16][512]
#define TM_H2   18432             // [16][256]
#define TM_H3   22528             // [16][128]
#define TM_TOT  24576

__global__ __launch_bounds__(256, 1)
void mlp_tail_kernel(const int*   __restrict__ item_id,
                     const float* __restrict__ item_emb,
                     const float* __restrict__ nw,
                     const float* __restrict__ nb,
                     const float* __restrict__ dw1,
                     const float* __restrict__ db1,
                     const float* __restrict__ dw2,
                     const float* __restrict__ db2,
                     const float* __restrict__ dw3,
                     const float* __restrict__ db3,
                     const float* __restrict__ fw,
                     const float* __restrict__ fb,
                     const float* __restrict__ item_bias_tab,
                     float*       __restrict__ out)
{
    extern __shared__ float sm[];
    const int b0  = blockIdx.x * 16;
    const int tid = threadIdx.x;

    // ---- stage attn (from scratch) and t (gather) ----
    for (int e = tid; e < 16 * 128; e += 256) {
        int bb = e >> 7, j = e & 127;
        sm[TM_ATTN + e] = g_attn[(b0 + bb) * 128 + j];
        long id = (long)__ldg(&item_id[b0 + bb]);
        sm[TM_T + e]    = __ldg(&item_emb[id * 128 + j]);
    }
    __syncthreads();

    // ======== Phase A: attn2 = attn @ nw + nb ; build cat ========
    {
        const int j = tid & 127;
        const int rbase = (tid >> 7) * 8;          // 0 or 8
        float acc[8];
        float nbj = __ldg(&nb[j]);
        #pragma unroll
        for (int i = 0; i < 8; ++i) acc[i] = nbj;

        for (int k = 0; k < 128; k += 4) {
            float w0 = __ldg(&nw[(k + 0) * 128 + j]);
            float w1 = __ldg(&nw[(k + 1) * 128 + j]);
            float w2 = __ldg(&nw[(k + 2) * 128 + j]);
            float w3 = __ldg(&nw[(k + 3) * 128 + j]);
            #pragma unroll
            for (int i = 0; i < 8; ++i) {
                float4 a = *reinterpret_cast<const float4*>(sm + TM_ATTN + (rbase + i) * 128 + k);
                acc[i] += a.x * w0 + a.y * w1 + a.z * w2 + a.w * w3;
            }
        }
        #pragma unroll
        for (int i = 0; i < 8; ++i) {
            int r = rbase + i;
            float a2 = acc[i];
            float t  = sm[TM_T + r * 128 + j];
            sm[TM_CAT + r * 384 + j]       = a2;
            sm[TM_CAT + r * 384 + 128 + j] = t;
            sm[TM_CAT + r * 384 + 256 + j] = t * a2;
        }
    }
    __syncthreads();

    // ======== Phase B: g1 = sigmoid(cat @ dw1 + db1)  (384 -> 512) ========
    {
        const int j = tid;                          // cols j and j+256
        float acc0[16], acc1[16];
        float bj0 = __ldg(&db1[j]), bj1 = __ldg(&db1[j + 256]);
        #pragma unroll
        for (int r = 0; r < 16; ++r) { acc0[r] = bj0; acc1[r] = bj1; }

        for (int k = 0; k < 384; k += 4) {
            float w0a = __ldg(&dw1[(k + 0) * 512 + j]);
            float w1a = __ldg(&dw1[(k + 1) * 512 + j]);
            float w2a = __ldg(&dw1[(k + 2) * 512 + j]);
            float w3a = __ldg(&dw1[(k + 3) * 512 + j]);
            float w0b = __ldg(&dw1[(k + 0) * 512 + j + 256]);
            float w1b = __ldg(&dw1[(k + 1) * 512 + j + 256]);
            float w2b = __ldg(&dw1[(k + 2) * 512 + j + 256]);
            float w3b = __ldg(&dw1[(k + 3) * 512 + j + 256]);
            #pragma unroll
            for (int r = 0; r < 16; ++r) {
                float4 a = *reinterpret_cast<const float4*>(sm + TM_CAT + r * 384 + k);
                acc0[r] += a.x * w0a + a.y * w1a + a.z * w2a + a.w * w3a;
                acc1[r] += a.x * w0b + a.y * w1b + a.z * w2b + a.w * w3b;
            }
        }
        #pragma unroll
        for (int r = 0; r < 16; ++r) {
            sm[TM_H1 + r * 512 + j]       = sigm(acc0[r]);
            sm[TM_H1 + r * 512 + j + 256] = sigm(acc1[r]);
        }
    }
    __syncthreads();

    // ======== Phase C: g2 = sigmoid(g1 @ dw2 + db2)  (512 -> 256) ========
    {
        const int j = tid;                          // one col each
        float acc[16];
        float bj = __ldg(&db2[j]);
        #pragma unroll
        for (int r = 0; r < 16; ++r) acc[r] = bj;

        for (int k = 0; k < 512; k += 4) {
            float w0 = __ldg(&dw2[(k + 0) * 256 + j]);
            float w1 = __ldg(&dw2[(k + 1) * 256 + j]);
            float w2 = __ldg(&dw2[(k + 2) * 256 + j]);
            float w3 = __ldg(&dw2[(k + 3) * 256 + j]);
            #pragma unroll
            for (int r = 0; r < 16; ++r) {
                float4 a = *reinterpret_cast<const float4*>(sm + TM_H1 + r * 512 + k);
                acc[r] += a.x * w0 + a.y * w1 + a.z * w2 + a.w * w3;
            }
        }
        #pragma unroll
        for (int r = 0; r < 16; ++r)
            sm[TM_H2 + r * 256 + j] = sigm(acc[r]);
    }
    __syncthreads();

    // ======== Phase D: g3 = sigmoid(g2 @ dw3 + db3)  (256 -> 128) ========
    {
        const int j = tid & 127;
        const int rbase = (tid >> 7) * 8;
        float acc[8];
        float bj = __ldg(&db3[j]);
        #pragma unroll
        for (int i = 0; i < 8; ++i) acc[i] = bj;

        for (int k = 0; k < 256; k += 4) {
            float w0 = __ldg(&dw3[(k + 0) * 128 + j]);
            float w1 = __ldg(&dw3[(k + 1) * 128 + j]);
            float w2 = __ldg(&dw3[(k + 2) * 128 + j]);
            float w3 = __ldg(&dw3[(k + 3) * 128 + j]);
            #pragma unroll
            for (int i = 0; i < 8; ++i) {
                float4 a = *reinterpret_cast<const float4*>(sm + TM_H2 + (rbase + i) * 256 + k);
                acc[i] += a.x * w0 + a.y * w1 + a.z * w2 + a.w * w3;
            }
        }
        #pragma unroll
        for (int i = 0; i < 8; ++i)
            sm[TM_H3 + (rbase + i) * 128 + j] = sigm(acc[i]);
    }
    __syncthreads();

    // ======== Phase E: out[b] = g3 . fw + fb + item_bias ========
    {
        const int wid  = tid >> 5;                  // 0..7 -> rows 2w, 2w+1
        const int lane = tid & 31;
        const float fb0 = __ldg(&fb[0]);
        #pragma unroll
        for (int rr = 0; rr < 2; ++rr) {
            int r = wid * 2 + rr;
            float v = 0.0f;
            #pragma unroll
            for (int q = 0; q < 4; ++q)
                v += sm[TM_H3 + r * 128 + lane + 32 * q] * __ldg(&fw[lane + 32 * q]);
            #pragma unroll
            for (int m = 16; m > 0; m >>= 1) v += __shfl_xor_sync(0xffffffffu, v, m);
            if (lane == 0) {
                int b = b0 + r;
                out[b] = v + fb0 + __ldg(&item_bias_tab[item_id[b]]);
            }
        }
    }
}

// ============================================================================
extern "C" void kernel_launch(void* const* d_in, const int* in_sizes, int n_in,
                              void* d_out, int out_size)
{
    const int*   in_item_id    = (const int*)  d_in[0];
    const int*   item_id       = (const int*)  d_in[1];
    const float* item_emb      = (const float*)d_in[2];
    const float* item_bias_tab = (const float*)d_in[3];
    const float* aw1 = (const float*)d_in[4];
    const float* ab1 = (const float*)d_in[5];
    const float* aw2 = (const float*)d_in[6];
    const float* ab2 = (const float*)d_in[7];
    const float* afw = (const float*)d_in[8];
    const float* afb = (const float*)d_in[9];
    const float* nw  = (const float*)d_in[10];
    const float* nb  = (const float*)d_in[11];
    const float* dw1 = (const float*)d_in[12];
    const float* db1 = (const float*)d_in[13];
    const float* dw2 = (const float*)d_in[14];
    const float* db2 = (const float*)d_in[15];
    const float* dw3 = (const float*)d_in[16];
    const float* db3 = (const float*)d_in[17];
    const float* fw  = (const float*)d_in[18];
    const float* fb  = (const float*)d_in[19];
    float* out = (float*)d_out;

    const size_t smem1 = SM_TOT * sizeof(float);     // 231,424 B
    cudaFuncSetAttribute(din_attention_kernel,
                         cudaFuncAttributeMaxDynamicSharedMemorySize, (int)smem1);
    const size_t smem2 = TM_TOT * sizeof(float);     // 98,304 B
    cudaFuncSetAttribute(mlp_tail_kernel,
                         cudaFuncAttributeMaxDynamicSharedMemorySize, (int)smem2);

    din_attention_kernel<<<BB, 256, smem1>>>(in_item_id, item_id, item_emb,
                                             aw1, ab1, aw2, ab2, afw, afb);
    mlp_tail_kernel<<<BB / 16, 256, smem2>>>(item_id, item_emb, nw, nb,
                                             dw1, db1, dw2, db2, dw3, db3,
                                             fw, fb, item_bias_tab, out);
}

// round 4
// speedup vs baseline: 1.6354x; 1.4129x over previous
#include <cuda_runtime.h>
#include <cuda_bf16.h>
#include <cstdint>

// ============================================================================
// DIN scorer R3: din_attention via warp-level mma.sync (bf16, 3-term split,
// fp32 accum). No tcgen05 (ptxas target is sm_100 base). h1 stays in
// registers (D-frag of GEMM1 == A-frag of GEMM2). Tail: 8 batches/CTA.
// ============================================================================

#define BB 2048
#define LL 200

__device__ float g_attn[BB * 128];

__device__ __forceinline__ float sigm(float x) { return 1.0f / (1.0f + __expf(-x)); }

// bf16 hi/lo split of two floats, packed low-first into bf16x2 words
__device__ __forceinline__ void split2(float a, float b, uint32_t& hi, uint32_t& lo) {
    __nv_bfloat16 ah = __float2bfloat16(a);
    __nv_bfloat16 bh = __float2bfloat16(b);
    __nv_bfloat16 al = __float2bfloat16(a - __bfloat162float(ah));
    __nv_bfloat16 bl = __float2bfloat16(b - __bfloat162float(bh));
    hi = ((uint32_t)__bfloat16_as_ushort(bh) << 16) | (uint32_t)__bfloat16_as_ushort(ah);
    lo = ((uint32_t)__bfloat16_as_ushort(bl) << 16) | (uint32_t)__bfloat16_as_ushort(al);
}

// m16n8k16 bf16 MMA, fp32 accumulate (in-place C)
__device__ __forceinline__ void mma_bf16(float* c, uint32_t a0, uint32_t a1,
                                         uint32_t a2, uint32_t a3,
                                         uint32_t b0, uint32_t b1) {
    asm("mma.sync.aligned.m16n8k16.row.col.f32.bf16.bf16.f32 "
        "{%0,%1,%2,%3}, {%4,%5,%6,%7}, {%8,%9}, {%0,%1,%2,%3};"
        : "+f"(c[0]), "+f"(c[1]), "+f"(c[2]), "+f"(c[3])
        : "r"(a0), "r"(a1), "r"(a2), "r"(a3), "r"(b0), "r"(b1));
}

// Swizzled plane index: plane is [row][64 pairs] of b32; swizzle keeps all
// fragment loads conflict-free and reduces to a per-thread constant 4*(row&7).
__device__ __forceinline__ int pidx(int row, int pair) {
    return row * 64 + (pair ^ ((row & 7) << 2));
}

// ---- smem byte offsets ----
#define OFF_SA_HI   0         // seq  [128][64] b32-pairs
#define OFF_SA_LO   32768
#define OFF_B1_HI   65536     // Mb   [n=128][kpair=64]
#define OFF_B1_LO   98304
#define OFF_B2_HI   131072    // aw2  [n=64][kpair=64]
#define OFF_B2_LO   147456
#define OFF_T       163840    // float[128]
#define OFF_CVEC    164352    // float[128]
#define OFF_SCORE   164864    // float[128]
#define OFF_AB2     165376    // float[64]
#define OFF_AFW     165632    // float[64]
#define OFF_RED     165888    // float[128]
#define SMEM_BYTES  166400

__global__ __launch_bounds__(256, 1)
void din_attention_mma(const int*   __restrict__ in_item_id,
                       const int*   __restrict__ item_id,
                       const float* __restrict__ item_emb,
                       const float* __restrict__ aw1,
                       const float* __restrict__ ab1,
                       const float* __restrict__ aw2,
                       const float* __restrict__ ab2,
                       const float* __restrict__ afw,
                       const float* __restrict__ afb)
{
    extern __shared__ char smem[];
    uint32_t* saHI = (uint32_t*)(smem + OFF_SA_HI);
    uint32_t* saLO = (uint32_t*)(smem + OFF_SA_LO);
    uint32_t* b1HI = (uint32_t*)(smem + OFF_B1_HI);
    uint32_t* b1LO = (uint32_t*)(smem + OFF_B1_LO);
    uint32_t* b2HI = (uint32_t*)(smem + OFF_B2_HI);
    uint32_t* b2LO = (uint32_t*)(smem + OFF_B2_LO);
    float* tS     = (float*)(smem + OFF_T);
    float* cvec   = (float*)(smem + OFF_CVEC);
    float* scoreS = (float*)(smem + OFF_SCORE);
    float* ab2S   = (float*)(smem + OFF_AB2);
    float* afwS   = (float*)(smem + OFF_AFW);
    float* redS   = (float*)(smem + OFF_RED);

    const int tid = threadIdx.x, wid = tid >> 5, lid = tid & 31;
    const int b = blockIdx.x;
    const int g  = lid >> 2;          // 0..7
    const int tg = lid & 3;           // 0..3
    const int sx = g << 2;            // swizzle const = 4*(row&7) for our rows

    // ---- stage t, ab2, afw ----
    if (tid < 128) {
        long id = (long)item_id[b];
        tS[tid] = item_emb[id * 128 + tid];
    }
    if (tid < 64) { ab2S[tid] = __ldg(&ab2[tid]); afwS[tid] = __ldg(&afw[tid]); }
    __syncthreads();

    // ---- B1 planes: Mb[k][j] = t[k]*A1[k][j] - A2[k][j], stored [j][kpair] ----
    for (int e = tid; e < 128 * 64; e += 256) {
        int j = e & 127, kp = e >> 7;
        int k0 = kp * 2, k1 = k0 + 1;
        float v0 = tS[k0] * __ldg(&aw1[(128 + k0) * 128 + j]) - __ldg(&aw1[(256 + k0) * 128 + j]);
        float v1 = tS[k1] * __ldg(&aw1[(128 + k1) * 128 + j]) - __ldg(&aw1[(256 + k1) * 128 + j]);
        uint32_t hi, lo; split2(v0, v1, hi, lo);
        int a = pidx(j, kp);
        b1HI[a] = hi; b1LO[a] = lo;
    }
    // ---- B2 planes: aw2[k][n] stored [n][kpair] ----
    for (int e = tid; e < 64 * 64; e += 256) {
        int n = e & 63, kp = e >> 6;
        float v0 = __ldg(&aw2[(kp * 2) * 64 + n]);
        float v1 = __ldg(&aw2[(kp * 2 + 1) * 64 + n]);
        uint32_t hi, lo; split2(v0, v1, hi, lo);
        int a = pidx(n, kp);
        b2HI[a] = hi; b2LO[a] = lo;
    }
    // ---- cvec = ab1 + t @ (A0 + A2) ----
    if (tid < 128) {
        int j = tid;
        float acc = __ldg(&ab1[j]);
        #pragma unroll 4
        for (int k = 0; k < 128; ++k)
            acc += tS[k] * (__ldg(&aw1[k * 128 + j]) + __ldg(&aw1[(256 + k) * 128 + j]));
        cvec[j] = acc;
    }
    const float afb0 = __ldg(&afb[0]);

    const int rA = wid * 16 + g;           // this thread's top row
    float attnReg = 0.0f;                  // d = tid & 127, rows split by tid>>7
    const int dAt  = tid & 127;
    const int half = tid >> 7;

    __syncthreads();

    for (int chunk = 0; chunk < 2; ++chunk) {
        const int base = chunk * 128;
        const int cr   = chunk ? (LL - 128) : 128;   // 128 then 72
        const bool act = (wid * 16 < cr);

        // ---- gather seq rows -> sA hi/lo planes ----
        for (int e = tid; e < cr * 32; e += 256) {
            int row = e >> 5, q = e & 31;
            long id = (long)__ldg(&in_item_id[b * LL + base + row]);
            float4 v = __ldg(reinterpret_cast<const float4*>(item_emb + id * 128) + q);
            uint32_t h0, l0, h1, l1;
            split2(v.x, v.y, h0, l0);
            split2(v.z, v.w, h1, l1);
            int a = pidx(row, q * 2);      // pairs 2q, 2q+1 stay adjacent after swizzle
            *(uint2*)(saHI + a) = make_uint2(h0, h1);
            *(uint2*)(saLO + a) = make_uint2(l0, l1);
        }
        __syncthreads();

        // h1 fragments (registers): [nt] -> rows g (top) / g+8 (bot)
        uint32_t hT_hi[16], hT_lo[16], hB_hi[16], hB_lo[16];

        if (act) {
            // ===== GEMM1: D1 = s @ Mb, 3-term bf16 split =====
            float acc[16][4];
            #pragma unroll
            for (int nt = 0; nt < 16; ++nt)
                #pragma unroll
                for (int i = 0; i < 4; ++i) acc[nt][i] = 0.0f;

            const int rTop = rA * 64, rBot = (rA + 8) * 64;
            #pragma unroll
            for (int ks = 0; ks < 8; ++ks) {
                const int p0 = (8 * ks + tg) ^ sx;
                const int p1 = p0 ^ 4;
                uint32_t ah0 = saHI[rTop + p0], ah1 = saHI[rBot + p0];
                uint32_t ah2 = saHI[rTop + p1], ah3 = saHI[rBot + p1];
                uint32_t al0 = saLO[rTop + p0], al1 = saLO[rBot + p0];
                uint32_t al2 = saLO[rTop + p1], al3 = saLO[rBot + p1];
                #pragma unroll
                for (int nt = 0; nt < 16; ++nt) {
                    const int nb = (8 * nt + g) * 64;
                    uint32_t bh0 = b1HI[nb + p0], bh1 = b1HI[nb + p1];
                    uint32_t bl0 = b1LO[nb + p0], bl1 = b1LO[nb + p1];
                    mma_bf16(acc[nt], ah0, ah1, ah2, ah3, bh0, bh1);
                    mma_bf16(acc[nt], al0, al1, al2, al3, bh0, bh1);
                    mma_bf16(acc[nt], ah0, ah1, ah2, ah3, bl0, bl1);
                }
            }
            // ===== epilogue 1: sigmoid(+cvec) -> bf16 split in registers =====
            #pragma unroll
            for (int nt = 0; nt < 16; ++nt) {
                const int c0 = 8 * nt + 2 * tg;
                float t0 = sigm(acc[nt][0] + cvec[c0]);
                float t1 = sigm(acc[nt][1] + cvec[c0 + 1]);
                float b0 = sigm(acc[nt][2] + cvec[c0]);
                float b1 = sigm(acc[nt][3] + cvec[c0 + 1]);
                split2(t0, t1, hT_hi[nt], hT_lo[nt]);
                split2(b0, b1, hB_hi[nt], hB_lo[nt]);
            }
        }

        // ===== GEMM2: D2 = h1 @ aw2 (A frags = GEMM1 D frags, in regs) =====
        float acc2[8][4];
        #pragma unroll
        for (int nt = 0; nt < 8; ++nt)
            #pragma unroll
            for (int i = 0; i < 4; ++i) acc2[nt][i] = 0.0f;

        if (act) {
            #pragma unroll
            for (int ks = 0; ks < 8; ++ks) {
                const int p0 = (8 * ks + tg) ^ sx;
                const int p1 = p0 ^ 4;
                uint32_t ah0 = hT_hi[2 * ks],     ah1 = hB_hi[2 * ks];
                uint32_t ah2 = hT_hi[2 * ks + 1], ah3 = hB_hi[2 * ks + 1];
                uint32_t al0 = hT_lo[2 * ks],     al1 = hB_lo[2 * ks];
                uint32_t al2 = hT_lo[2 * ks + 1], al3 = hB_lo[2 * ks + 1];
                #pragma unroll
                for (int nt = 0; nt < 8; ++nt) {
                    const int nb = (8 * nt + g) * 64;
                    uint32_t bh0 = b2HI[nb + p0], bh1 = b2HI[nb + p1];
                    uint32_t bl0 = b2LO[nb + p0], bl1 = b2LO[nb + p1];
                    mma_bf16(acc2[nt], ah0, ah1, ah2, ah3, bh0, bh1);
                    mma_bf16(acc2[nt], al0, al1, al2, al3, bh0, bh1);
                    mma_bf16(acc2[nt], ah0, ah1, ah2, ah3, bl0, bl1);
                }
            }
        }

        // ===== score: v = sum_j sigm(D2[j]+ab2[j])*afw[j], reduce over tg =====
        {
            float vT = 0.0f, vB = 0.0f;
            #pragma unroll
            for (int nt = 0; nt < 8; ++nt) {
                const int c0 = 8 * nt + 2 * tg;
                vT += sigm(acc2[nt][0] + ab2S[c0])     * afwS[c0];
                vT += sigm(acc2[nt][1] + ab2S[c0 + 1]) * afwS[c0 + 1];
                vB += sigm(acc2[nt][2] + ab2S[c0])     * afwS[c0];
                vB += sigm(acc2[nt][3] + ab2S[c0 + 1]) * afwS[c0 + 1];
            }
            vT += __shfl_xor_sync(0xffffffffu, vT, 1);
            vT += __shfl_xor_sync(0xffffffffu, vT, 2);
            vB += __shfl_xor_sync(0xffffffffu, vB, 1);
            vB += __shfl_xor_sync(0xffffffffu, vB, 2);
            if (tg == 0) {
                int r0 = rA, r1 = rA + 8;
                float s0 = 0.0f, s1 = 0.0f;
                if (act && r0 < cr) {
                    int id = __ldg(&in_item_id[b * LL + base + r0]);
                    s0 = (id == 0) ? 0.0f : (vT + afb0);
                }
                if (act && r1 < cr) {
                    int id = __ldg(&in_item_id[b * LL + base + r1]);
                    s1 = (id == 0) ? 0.0f : (vB + afb0);
                }
                scoreS[r0] = s0;
                scoreS[r1] = s1;
            }
        }
        __syncthreads();

        // ===== attn[d] += sum_row score[row]*s[row][d] (rows split in half) ====
        {
            const int h0 = half * (cr >> 1);
            const int h1 = h0 + (cr >> 1);
            const int pr = dAt >> 1, sel = (dAt & 1) * 16;
            for (int row = h0; row < h1; ++row) {
                float sc = scoreS[row];
                int a = pidx(row, pr);
                uint32_t whi = saHI[a], wlo = saLO[a];
                float s = __bfloat162float(__ushort_as_bfloat16((unsigned short)(whi >> sel)))
                        + __bfloat162float(__ushort_as_bfloat16((unsigned short)(wlo >> sel)));
                attnReg += sc * s;
            }
        }
        __syncthreads();   // before sA is overwritten next chunk
    }

    // combine the two row-halves
    if (tid >= 128) redS[dAt] = attnReg;
    __syncthreads();
    if (tid < 128) g_attn[b * 128 + tid] = attnReg + redS[tid];
}

// ============================================================================
// Fused MLP tail: 8 batches/CTA, 256 CTAs, 49,152 B dyn smem -> 2 CTAs/SM.
// ============================================================================
#define NB 8
#define TM_ATTN 0
#define TM_T    (NB*128)
#define TM_CAT  (2*NB*128)
#define TM_H1   (TM_CAT + NB*384)
#define TM_H2   (TM_H1 + NB*512)
#define TM_H3   (TM_H2 + NB*256)
#define TM_TOT  (TM_H3 + NB*128)   // 12288 floats = 49152 B

__global__ __launch_bounds__(256, 2)
void mlp_tail_kernel(const int*   __restrict__ item_id,
                     const float* __restrict__ item_emb,
                     const float* __restrict__ nw,
                     const float* __restrict__ nb,
                     const float* __restrict__ dw1,
                     const float* __restrict__ db1,
                     const float* __restrict__ dw2,
                     const float* __restrict__ db2,
                     const float* __restrict__ dw3,
                     const float* __restrict__ db3,
                     const float* __restrict__ fw,
                     const float* __restrict__ fb,
                     const float* __restrict__ item_bias_tab,
                     float*       __restrict__ out)
{
    extern __shared__ float sm[];
    const int b0  = blockIdx.x * NB;
    const int tid = threadIdx.x;

    for (int e = tid; e < NB * 128; e += 256) {
        int bb = e >> 7, j = e & 127;
        sm[TM_ATTN + e] = g_attn[(b0 + bb) * 128 + j];
        long id = (long)__ldg(&item_id[b0 + bb]);
        sm[TM_T + e]    = __ldg(&item_emb[id * 128 + j]);
    }
    __syncthreads();

    // Phase A: attn2 = attn @ nw + nb ; build cat
    {
        const int j = tid & 127;
        const int rbase = (tid >> 7) * 4;
        float acc[4];
        float nbj = __ldg(&nb[j]);
        #pragma unroll
        for (int i = 0; i < 4; ++i) acc[i] = nbj;
        #pragma unroll 2
        for (int k = 0; k < 128; k += 4) {
            float w0 = __ldg(&nw[(k + 0) * 128 + j]);
            float w1 = __ldg(&nw[(k + 1) * 128 + j]);
            float w2 = __ldg(&nw[(k + 2) * 128 + j]);
            float w3 = __ldg(&nw[(k + 3) * 128 + j]);
            #pragma unroll
            for (int i = 0; i < 4; ++i) {
                float4 a = *reinterpret_cast<const float4*>(sm + TM_ATTN + (rbase + i) * 128 + k);
                acc[i] += a.x * w0 + a.y * w1 + a.z * w2 + a.w * w3;
            }
        }
        #pragma unroll
        for (int i = 0; i < 4; ++i) {
            int r = rbase + i;
            float a2 = acc[i];
            float t  = sm[TM_T + r * 128 + j];
            sm[TM_CAT + r * 384 + j]       = a2;
            sm[TM_CAT + r * 384 + 128 + j] = t;
            sm[TM_CAT + r * 384 + 256 + j] = t * a2;
        }
    }
    __syncthreads();

    // Phase B: g1 = sigmoid(cat @ dw1 + db1)  384 -> 512
    {
        const int j = tid;
        float acc0[NB], acc1[NB];
        float bj0 = __ldg(&db1[j]), bj1 = __ldg(&db1[j + 256]);
        #pragma unroll
        for (int r = 0; r < NB; ++r) { acc0[r] = bj0; acc1[r] = bj1; }
        #pragma unroll 2
        for (int k = 0; k < 384; k += 4) {
            float w0a = __ldg(&dw1[(k + 0) * 512 + j]);
            float w1a = __ldg(&dw1[(k + 1) * 512 + j]);
            float w2a = __ldg(&dw1[(k + 2) * 512 + j]);
            float w3a = __ldg(&dw1[(k + 3) * 512 + j]);
            float w0b = __ldg(&dw1[(k + 0) * 512 + j + 256]);
            float w1b = __ldg(&dw1[(k + 1) * 512 + j + 256]);
            float w2b = __ldg(&dw1[(k + 2) * 512 + j + 256]);
            float w3b = __ldg(&dw1[(k + 3) * 512 + j + 256]);
            #pragma unroll
            for (int r = 0; r < NB; ++r) {
                float4 a = *reinterpret_cast<const float4*>(sm + TM_CAT + r * 384 + k);
                acc0[r] += a.x * w0a + a.y * w1a + a.z * w2a + a.w * w3a;
                acc1[r] += a.x * w0b + a.y * w1b + a.z * w2b + a.w * w3b;
            }
        }
        #pragma unroll
        for (int r = 0; r < NB; ++r) {
            sm[TM_H1 + r * 512 + j]       = sigm(acc0[r]);
            sm[TM_H1 + r * 512 + j + 256] = sigm(acc1[r]);
        }
    }
    __syncthreads();

    // Phase C: g2 = sigmoid(g1 @ dw2 + db2)  512 -> 256
    {
        const int j = tid;
        float acc[NB];
        float bj = __ldg(&db2[j]);
        #pragma unroll
        for (int r = 0; r < NB; ++r) acc[r] = bj;
        #pragma unroll 2
        for (int k = 0; k < 512; k += 4) {
            float w0 = __ldg(&dw2[(k + 0) * 256 + j]);
            float w1 = __ldg(&dw2[(k + 1) * 256 + j]);
            float w2 = __ldg(&dw2[(k + 2) * 256 + j]);
            float w3 = __ldg(&dw2[(k + 3) * 256 + j]);
            #pragma unroll
            for (int r = 0; r < NB; ++r) {
                float4 a = *reinterpret_cast<const float4*>(sm + TM_H1 + r * 512 + k);
                acc[r] += a.x * w0 + a.y * w1 + a.z * w2 + a.w * w3;
            }
        }
        #pragma unroll
        for (int r = 0; r < NB; ++r)
            sm[TM_H2 + r * 256 + j] = sigm(acc[r]);
    }
    __syncthreads();

    // Phase D: g3 = sigmoid(g2 @ dw3 + db3)  256 -> 128
    {
        const int j = tid & 127;
        const int rbase = (tid >> 7) * 4;
        float acc[4];
        float bj = __ldg(&db3[j]);
        #pragma unroll
        for (int i = 0; i < 4; ++i) acc[i] = bj;
        #pragma unroll 2
        for (int k = 0; k < 256; k += 4) {
            float w0 = __ldg(&dw3[(k + 0) * 128 + j]);
            float w1 = __ldg(&dw3[(k + 1) * 128 + j]);
            float w2 = __ldg(&dw3[(k + 2) * 128 + j]);
            float w3 = __ldg(&dw3[(k + 3) * 128 + j]);
            #pragma unroll
            for (int i = 0; i < 4; ++i) {
                float4 a = *reinterpret_cast<const float4*>(sm + TM_H2 + (rbase + i) * 256 + k);
                acc[i] += a.x * w0 + a.y * w1 + a.z * w2 + a.w * w3;
            }
        }
        #pragma unroll
        for (int i = 0; i < 4; ++i)
            sm[TM_H3 + (rbase + i) * 128 + j] = sigm(acc[i]);
    }
    __syncthreads();

    // Phase E: out = g3 . fw + fb + item_bias  (one warp per row)
    {
        const int wid  = tid >> 5;
        const int lane = tid & 31;
        float v = 0.0f;
        #pragma unroll
        for (int q = 0; q < 4; ++q)
            v += sm[TM_H3 + wid * 128 + lane + 32 * q] * __ldg(&fw[lane + 32 * q]);
        #pragma unroll
        for (int m = 16; m > 0; m >>= 1) v += __shfl_xor_sync(0xffffffffu, v, m);
        if (lane == 0) {
            int b = b0 + wid;
            out[b] = v + __ldg(&fb[0]) + __ldg(&item_bias_tab[item_id[b]]);
        }
    }
}

// ============================================================================
extern "C" void kernel_launch(void* const* d_in, const int* in_sizes, int n_in,
                              void* d_out, int out_size)
{
    const int*   in_item_id    = (const int*)  d_in[0];
    const int*   item_id       = (const int*)  d_in[1];
    const float* item_emb      = (const float*)d_in[2];
    const float* item_bias_tab = (const float*)d_in[3];
    const float* aw1 = (const float*)d_in[4];
    const float* ab1 = (const float*)d_in[5];
    const float* aw2 = (const float*)d_in[6];
    const float* ab2 = (const float*)d_in[7];
    const float* afw = (const float*)d_in[8];
    const float* afb = (const float*)d_in[9];
    const float* nw  = (const float*)d_in[10];
    const float* nb  = (const float*)d_in[11];
    const float* dw1 = (const float*)d_in[12];
    const float* db1 = (const float*)d_in[13];
    const float* dw2 = (const float*)d_in[14];
    const float* db2 = (const float*)d_in[15];
    const float* dw3 = (const float*)d_in[16];
    const float* db3 = (const float*)d_in[17];
    const float* fw  = (const float*)d_in[18];
    const float* fb  = (const float*)d_in[19];
    float* out = (float*)d_out;

    cudaFuncSetAttribute(din_attention_mma,
                         cudaFuncAttributeMaxDynamicSharedMemorySize, SMEM_BYTES);
    cudaFuncSetAttribute(mlp_tail_kernel,
                         cudaFuncAttributeMaxDynamicSharedMemorySize,
                         (int)(TM_TOT * sizeof(float)));

    din_attention_mma<<<BB, 256, SMEM_BYTES>>>(in_item_id, item_id, item_emb,
                                               aw1, ab1, aw2, ab2, afw, afb);
    mlp_tail_kernel<<<BB / NB, 256, TM_TOT * sizeof(float)>>>(
        item_id, item_emb, nw, nb, dw1, db1, dw2, db2, dw3, db3,
        fw, fb, item_bias_tab, out);
}

// round 5
// speedup vs baseline: 2.0123x; 1.2305x over previous
#include <cuda_runtime.h>
#include <cuda_bf16.h>
#include <cstdint>

// ============================================================================
// DIN scorer R4: R3 structure (mma.sync bf16 3-term split) +
//  - fast sigmoid (__fdividef instead of IEEE div)
//  - tail k-loop unroll x4
//  - nop-kernel sandwich so ncu (-s 5 -c 1) captures din_attention_mma
// ============================================================================

#define BB 2048
#define LL 200

__device__ float g_attn[BB * 128];

__device__ __forceinline__ float sigm(float x) {
    return __fdividef(1.0f, 1.0f + __expf(-x));
}

// bf16 hi/lo split of two floats, packed low-first into bf16x2 words
__device__ __forceinline__ void split2(float a, float b, uint32_t& hi, uint32_t& lo) {
    __nv_bfloat16 ah = __float2bfloat16(a);
    __nv_bfloat16 bh = __float2bfloat16(b);
    __nv_bfloat16 al = __float2bfloat16(a - __bfloat162float(ah));
    __nv_bfloat16 bl = __float2bfloat16(b - __bfloat162float(bh));
    hi = ((uint32_t)__bfloat16_as_ushort(bh) << 16) | (uint32_t)__bfloat16_as_ushort(ah);
    lo = ((uint32_t)__bfloat16_as_ushort(bl) << 16) | (uint32_t)__bfloat16_as_ushort(al);
}

// m16n8k16 bf16 MMA, fp32 accumulate (in-place C)
__device__ __forceinline__ void mma_bf16(float* c, uint32_t a0, uint32_t a1,
                                         uint32_t a2, uint32_t a3,
                                         uint32_t b0, uint32_t b1) {
    asm("mma.sync.aligned.m16n8k16.row.col.f32.bf16.bf16.f32 "
        "{%0,%1,%2,%3}, {%4,%5,%6,%7}, {%8,%9}, {%0,%1,%2,%3};"
        : "+f"(c[0]), "+f"(c[1]), "+f"(c[2]), "+f"(c[3])
        : "r"(a0), "r"(a1), "r"(a2), "r"(a3), "r"(b0), "r"(b1));
}

// Swizzled plane index: plane is [row][64 pairs] of b32.
__device__ __forceinline__ int pidx(int row, int pair) {
    return row * 64 + (pair ^ ((row & 7) << 2));
}

// ---- smem byte offsets ----
#define OFF_SA_HI   0
#define OFF_SA_LO   32768
#define OFF_B1_HI   65536
#define OFF_B1_LO   98304
#define OFF_B2_HI   131072
#define OFF_B2_LO   147456
#define OFF_T       163840
#define OFF_CVEC    164352
#define OFF_SCORE   164864
#define OFF_AB2     165376
#define OFF_AFW     165632
#define OFF_RED     165888
#define SMEM_BYTES  166400

__global__ void nop_kernel() {}

__global__ __launch_bounds__(256, 1)
void din_attention_mma(const int*   __restrict__ in_item_id,
                       const int*   __restrict__ item_id,
                       const float* __restrict__ item_emb,
                       const float* __restrict__ aw1,
                       const float* __restrict__ ab1,
                       const float* __restrict__ aw2,
                       const float* __restrict__ ab2,
                       const float* __restrict__ afw,
                       const float* __restrict__ afb)
{
    extern __shared__ char smem[];
    uint32_t* saHI = (uint32_t*)(smem + OFF_SA_HI);
    uint32_t* saLO = (uint32_t*)(smem + OFF_SA_LO);
    uint32_t* b1HI = (uint32_t*)(smem + OFF_B1_HI);
    uint32_t* b1LO = (uint32_t*)(smem + OFF_B1_LO);
    uint32_t* b2HI = (uint32_t*)(smem + OFF_B2_HI);
    uint32_t* b2LO = (uint32_t*)(smem + OFF_B2_LO);
    float* tS     = (float*)(smem + OFF_T);
    float* cvec   = (float*)(smem + OFF_CVEC);
    float* scoreS = (float*)(smem + OFF_SCORE);
    float* ab2S   = (float*)(smem + OFF_AB2);
    float* afwS   = (float*)(smem + OFF_AFW);
    float* redS   = (float*)(smem + OFF_RED);

    const int tid = threadIdx.x, wid = tid >> 5, lid = tid & 31;
    const int b = blockIdx.x;
    const int g  = lid >> 2;
    const int tg = lid & 3;
    const int sx = g << 2;

    if (tid < 128) {
        long id = (long)item_id[b];
        tS[tid] = item_emb[id * 128 + tid];
    }
    if (tid < 64) { ab2S[tid] = __ldg(&ab2[tid]); afwS[tid] = __ldg(&afw[tid]); }
    __syncthreads();

    // B1 planes: Mb[k][j] = t[k]*A1[k][j] - A2[k][j], stored [j][kpair]
    for (int e = tid; e < 128 * 64; e += 256) {
        int j = e & 127, kp = e >> 7;
        int k0 = kp * 2, k1 = k0 + 1;
        float v0 = tS[k0] * __ldg(&aw1[(128 + k0) * 128 + j]) - __ldg(&aw1[(256 + k0) * 128 + j]);
        float v1 = tS[k1] * __ldg(&aw1[(128 + k1) * 128 + j]) - __ldg(&aw1[(256 + k1) * 128 + j]);
        uint32_t hi, lo; split2(v0, v1, hi, lo);
        int a = pidx(j, kp);
        b1HI[a] = hi; b1LO[a] = lo;
    }
    // B2 planes: aw2[k][n] stored [n][kpair]
    for (int e = tid; e < 64 * 64; e += 256) {
        int n = e & 63, kp = e >> 6;
        float v0 = __ldg(&aw2[(kp * 2) * 64 + n]);
        float v1 = __ldg(&aw2[(kp * 2 + 1) * 64 + n]);
        uint32_t hi, lo; split2(v0, v1, hi, lo);
        int a = pidx(n, kp);
        b2HI[a] = hi; b2LO[a] = lo;
    }
    // cvec = ab1 + t @ (A0 + A2)
    if (tid < 128) {
        int j = tid;
        float acc = __ldg(&ab1[j]);
        #pragma unroll 4
        for (int k = 0; k < 128; ++k)
            acc += tS[k] * (__ldg(&aw1[k * 128 + j]) + __ldg(&aw1[(256 + k) * 128 + j]));
        cvec[j] = acc;
    }
    const float afb0 = __ldg(&afb[0]);

    const int rA = wid * 16 + g;
    float attnReg = 0.0f;
    const int dAt  = tid & 127;
    const int half = tid >> 7;

    __syncthreads();

    for (int chunk = 0; chunk < 2; ++chunk) {
        const int base = chunk * 128;
        const int cr   = chunk ? (LL - 128) : 128;
        const bool act = (wid * 16 < cr);

        for (int e = tid; e < cr * 32; e += 256) {
            int row = e >> 5, q = e & 31;
            long id = (long)__ldg(&in_item_id[b * LL + base + row]);
            float4 v = __ldg(reinterpret_cast<const float4*>(item_emb + id * 128) + q);
            uint32_t h0, l0, h1, l1;
            split2(v.x, v.y, h0, l0);
            split2(v.z, v.w, h1, l1);
            int a = pidx(row, q * 2);
            *(uint2*)(saHI + a) = make_uint2(h0, h1);
            *(uint2*)(saLO + a) = make_uint2(l0, l1);
        }
        __syncthreads();

        uint32_t hT_hi[16], hT_lo[16], hB_hi[16], hB_lo[16];

        if (act) {
            float acc[16][4];
            #pragma unroll
            for (int nt = 0; nt < 16; ++nt)
                #pragma unroll
                for (int i = 0; i < 4; ++i) acc[nt][i] = 0.0f;

            const int rTop = rA * 64, rBot = (rA + 8) * 64;
            #pragma unroll
            for (int ks = 0; ks < 8; ++ks) {
                const int p0 = (8 * ks + tg) ^ sx;
                const int p1 = p0 ^ 4;
                uint32_t ah0 = saHI[rTop + p0], ah1 = saHI[rBot + p0];
                uint32_t ah2 = saHI[rTop + p1], ah3 = saHI[rBot + p1];
                uint32_t al0 = saLO[rTop + p0], al1 = saLO[rBot + p0];
                uint32_t al2 = saLO[rTop + p1], al3 = saLO[rBot + p1];
                #pragma unroll
                for (int nt = 0; nt < 16; ++nt) {
                    const int nb = (8 * nt + g) * 64;
                    uint32_t bh0 = b1HI[nb + p0], bh1 = b1HI[nb + p1];
                    uint32_t bl0 = b1LO[nb + p0], bl1 = b1LO[nb + p1];
                    mma_bf16(acc[nt], ah0, ah1, ah2, ah3, bh0, bh1);
                    mma_bf16(acc[nt], al0, al1, al2, al3, bh0, bh1);
                    mma_bf16(acc[nt], ah0, ah1, ah2, ah3, bl0, bl1);
                }
            }
            #pragma unroll
            for (int nt = 0; nt < 16; ++nt) {
                const int c0 = 8 * nt + 2 * tg;
                float t0 = sigm(acc[nt][0] + cvec[c0]);
                float t1 = sigm(acc[nt][1] + cvec[c0 + 1]);
                float b0 = sigm(acc[nt][2] + cvec[c0]);
                float b1 = sigm(acc[nt][3] + cvec[c0 + 1]);
                split2(t0, t1, hT_hi[nt], hT_lo[nt]);
                split2(b0, b1, hB_hi[nt], hB_lo[nt]);
            }
        }

        float acc2[8][4];
        #pragma unroll
        for (int nt = 0; nt < 8; ++nt)
            #pragma unroll
            for (int i = 0; i < 4; ++i) acc2[nt][i] = 0.0f;

        if (act) {
            #pragma unroll
            for (int ks = 0; ks < 8; ++ks) {
                const int p0 = (8 * ks + tg) ^ sx;
                const int p1 = p0 ^ 4;
                uint32_t ah0 = hT_hi[2 * ks],     ah1 = hB_hi[2 * ks];
                uint32_t ah2 = hT_hi[2 * ks + 1], ah3 = hB_hi[2 * ks + 1];
                uint32_t al0 = hT_lo[2 * ks],     al1 = hB_lo[2 * ks];
                uint32_t al2 = hT_lo[2 * ks + 1], al3 = hB_lo[2 * ks + 1];
                #pragma unroll
                for (int nt = 0; nt < 8; ++nt) {
                    const int nb = (8 * nt + g) * 64;
                    uint32_t bh0 = b2HI[nb + p0], bh1 = b2HI[nb + p1];
                    uint32_t bl0 = b2LO[nb + p0], bl1 = b2LO[nb + p1];
                    mma_bf16(acc2[nt], ah0, ah1, ah2, ah3, bh0, bh1);
                    mma_bf16(acc2[nt], al0, al1, al2, al3, bh0, bh1);
                    mma_bf16(acc2[nt], ah0, ah1, ah2, ah3, bl0, bl1);
                }
            }
        }

        {
            float vT = 0.0f, vB = 0.0f;
            #pragma unroll
            for (int nt = 0; nt < 8; ++nt) {
                const int c0 = 8 * nt + 2 * tg;
                vT += sigm(acc2[nt][0] + ab2S[c0])     * afwS[c0];
                vT += sigm(acc2[nt][1] + ab2S[c0 + 1]) * afwS[c0 + 1];
                vB += sigm(acc2[nt][2] + ab2S[c0])     * afwS[c0];
                vB += sigm(acc2[nt][3] + ab2S[c0 + 1]) * afwS[c0 + 1];
            }
            vT += __shfl_xor_sync(0xffffffffu, vT, 1);
            vT += __shfl_xor_sync(0xffffffffu, vT, 2);
            vB += __shfl_xor_sync(0xffffffffu, vB, 1);
            vB += __shfl_xor_sync(0xffffffffu, vB, 2);
            if (tg == 0) {
                int r0 = rA, r1 = rA + 8;
                float s0 = 0.0f, s1 = 0.0f;
                if (act && r0 < cr) {
                    int id = __ldg(&in_item_id[b * LL + base + r0]);
                    s0 = (id == 0) ? 0.0f : (vT + afb0);
                }
                if (act && r1 < cr) {
                    int id = __ldg(&in_item_id[b * LL + base + r1]);
                    s1 = (id == 0) ? 0.0f : (vB + afb0);
                }
                scoreS[r0] = s0;
                scoreS[r1] = s1;
            }
        }
        __syncthreads();

        {
            const int h0 = half * (cr >> 1);
            const int h1 = h0 + (cr >> 1);
            const int pr = dAt >> 1, sel = (dAt & 1) * 16;
            for (int row = h0; row < h1; ++row) {
                float sc = scoreS[row];
                int a = pidx(row, pr);
                uint32_t whi = saHI[a], wlo = saLO[a];
                float s = __bfloat162float(__ushort_as_bfloat16((unsigned short)(whi >> sel)))
                        + __bfloat162float(__ushort_as_bfloat16((unsigned short)(wlo >> sel)));
                attnReg += sc * s;
            }
        }
        __syncthreads();
    }

    if (tid >= 128) redS[dAt] = attnReg;
    __syncthreads();
    if (tid < 128) g_attn[b * 128 + tid] = attnReg + redS[tid];
}

// ============================================================================
// Fused MLP tail: 8 batches/CTA, 256 CTAs, 2 CTAs/SM. Unroll x4 in B/C.
// ============================================================================
#define NB 8
#define TM_ATTN 0
#define TM_T    (NB*128)
#define TM_CAT  (2*NB*128)
#define TM_H1   (TM_CAT + NB*384)
#define TM_H2   (TM_H1 + NB*512)
#define TM_H3   (TM_H2 + NB*256)
#define TM_TOT  (TM_H3 + NB*128)   // 12288 floats = 49152 B

__global__ __launch_bounds__(256, 2)
void mlp_tail_kernel(const int*   __restrict__ item_id,
                     const float* __restrict__ item_emb,
                     const float* __restrict__ nw,
                     const float* __restrict__ nb,
                     const float* __restrict__ dw1,
                     const float* __restrict__ db1,
                     const float* __restrict__ dw2,
                     const float* __restrict__ db2,
                     const float* __restrict__ dw3,
                     const float* __restrict__ db3,
                     const float* __restrict__ fw,
                     const float* __restrict__ fb,
                     const float* __restrict__ item_bias_tab,
                     float*       __restrict__ out)
{
    extern __shared__ float sm[];
    const int b0  = blockIdx.x * NB;
    const int tid = threadIdx.x;

    for (int e = tid; e < NB * 128; e += 256) {
        int bb = e >> 7, j = e & 127;
        sm[TM_ATTN + e] = g_attn[(b0 + bb) * 128 + j];
        long id = (long)__ldg(&item_id[b0 + bb]);
        sm[TM_T + e]    = __ldg(&item_emb[id * 128 + j]);
    }
    __syncthreads();

    // Phase A
    {
        const int j = tid & 127;
        const int rbase = (tid >> 7) * 4;
        float acc[4];
        float nbj = __ldg(&nb[j]);
        #pragma unroll
        for (int i = 0; i < 4; ++i) acc[i] = nbj;
        #pragma unroll 4
        for (int k = 0; k < 128; k += 4) {
            float w0 = __ldg(&nw[(k + 0) * 128 + j]);
            float w1 = __ldg(&nw[(k + 1) * 128 + j]);
            float w2 = __ldg(&nw[(k + 2) * 128 + j]);
            float w3 = __ldg(&nw[(k + 3) * 128 + j]);
            #pragma unroll
            for (int i = 0; i < 4; ++i) {
                float4 a = *reinterpret_cast<const float4*>(sm + TM_ATTN + (rbase + i) * 128 + k);
                acc[i] += a.x * w0 + a.y * w1 + a.z * w2 + a.w * w3;
            }
        }
        #pragma unroll
        for (int i = 0; i < 4; ++i) {
            int r = rbase + i;
            float a2 = acc[i];
            float t  = sm[TM_T + r * 128 + j];
            sm[TM_CAT + r * 384 + j]       = a2;
            sm[TM_CAT + r * 384 + 128 + j] = t;
            sm[TM_CAT + r * 384 + 256 + j] = t * a2;
        }
    }
    __syncthreads();

    // Phase B: 384 -> 512
    {
        const int j = tid;
        float acc0[NB], acc1[NB];
        float bj0 = __ldg(&db1[j]), bj1 = __ldg(&db1[j + 256]);
        #pragma unroll
        for (int r = 0; r < NB; ++r) { acc0[r] = bj0; acc1[r] = bj1; }
        #pragma unroll 4
        for (int k = 0; k < 384; k += 4) {
            float w0a = __ldg(&dw1[(k + 0) * 512 + j]);
            float w1a = __ldg(&dw1[(k + 1) * 512 + j]);
            float w2a = __ldg(&dw1[(k + 2) * 512 + j]);
            float w3a = __ldg(&dw1[(k + 3) * 512 + j]);
            float w0b = __ldg(&dw1[(k + 0) * 512 + j + 256]);
            float w1b = __ldg(&dw1[(k + 1) * 512 + j + 256]);
            float w2b = __ldg(&dw1[(k + 2) * 512 + j + 256]);
            float w3b = __ldg(&dw1[(k + 3) * 512 + j + 256]);
            #pragma unroll
            for (int r = 0; r < NB; ++r) {
                float4 a = *reinterpret_cast<const float4*>(sm + TM_CAT + r * 384 + k);
                acc0[r] += a.x * w0a + a.y * w1a + a.z * w2a + a.w * w3a;
                acc1[r] += a.x * w0b + a.y * w1b + a.z * w2b + a.w * w3b;
            }
        }
        #pragma unroll
        for (int r = 0; r < NB; ++r) {
            sm[TM_H1 + r * 512 + j]       = sigm(acc0[r]);
            sm[TM_H1 + r * 512 + j + 256] = sigm(acc1[r]);
        }
    }
    __syncthreads();

    // Phase C: 512 -> 256
    {
        const int j = tid;
        float acc[NB];
        float bj = __ldg(&db2[j]);
        #pragma unroll
        for (int r = 0; r < NB; ++r) acc[r] = bj;
        #pragma unroll 4
        for (int k = 0; k < 512; k += 4) {
            float w0 = __ldg(&dw2[(k + 0) * 256 + j]);
            float w1 = __ldg(&dw2[(k + 1) * 256 + j]);
            float w2 = __ldg(&dw2[(k + 2) * 256 + j]);
            float w3 = __ldg(&dw2[(k + 3) * 256 + j]);
            #pragma unroll
            for (int r = 0; r < NB; ++r) {
                float4 a = *reinterpret_cast<const float4*>(sm + TM_H1 + r * 512 + k);
                acc[r] += a.x * w0 + a.y * w1 + a.z * w2 + a.w * w3;
            }
        }
        #pragma unroll
        for (int r = 0; r < NB; ++r)
            sm[TM_H2 + r * 256 + j] = sigm(acc[r]);
    }
    __syncthreads();

    // Phase D: 256 -> 128
    {
        const int j = tid & 127;
        const int rbase = (tid >> 7) * 4;
        float acc[4];
        float bj = __ldg(&db3[j]);
        #pragma unroll
        for (int i = 0; i < 4; ++i) acc[i] = bj;
        #pragma unroll 4
        for (int k = 0; k < 256; k += 4) {
            float w0 = __ldg(&dw3[(k + 0) * 128 + j]);
            float w1 = __ldg(&dw3[(k + 1) * 128 + j]);
            float w2 = __ldg(&dw3[(k + 2) * 128 + j]);
            float w3 = __ldg(&dw3[(k + 3) * 128 + j]);
            #pragma unroll
            for (int i = 0; i < 4; ++i) {
                float4 a = *reinterpret_cast<const float4*>(sm + TM_H2 + (rbase + i) * 256 + k);
                acc[i] += a.x * w0 + a.y * w1 + a.z * w2 + a.w * w3;
            }
        }
        #pragma unroll
        for (int i = 0; i < 4; ++i)
            sm[TM_H3 + (rbase + i) * 128 + j] = sigm(acc[i]);
    }
    __syncthreads();

    // Phase E
    {
        const int wid  = tid >> 5;
        const int lane = tid & 31;
        float v = 0.0f;
        #pragma unroll
        for (int q = 0; q < 4; ++q)
            v += sm[TM_H3 + wid * 128 + lane + 32 * q] * __ldg(&fw[lane + 32 * q]);
        #pragma unroll
        for (int m = 16; m > 0; m >>= 1) v += __shfl_xor_sync(0xffffffffu, v, m);
        if (lane == 0) {
            int b = b0 + wid;
            out[b] = v + __ldg(&fb[0]) + __ldg(&item_bias_tab[item_id[b]]);
        }
    }
}

// ============================================================================
extern "C" void kernel_launch(void* const* d_in, const int* in_sizes, int n_in,
                              void* d_out, int out_size)
{
    const int*   in_item_id    = (const int*)  d_in[0];
    const int*   item_id       = (const int*)  d_in[1];
    const float* item_emb      = (const float*)d_in[2];
    const float* item_bias_tab = (const float*)d_in[3];
    const float* aw1 = (const float*)d_in[4];
    const float* ab1 = (const float*)d_in[5];
    const float* aw2 = (const float*)d_in[6];
    const float* ab2 = (const float*)d_in[7];
    const float* afw = (const float*)d_in[8];
    const float* afb = (const float*)d_in[9];
    const float* nw  = (const float*)d_in[10];
    const float* nb  = (const float*)d_in[11];
    const float* dw1 = (const float*)d_in[12];
    const float* db1 = (const float*)d_in[13];
    const float* dw2 = (const float*)d_in[14];
    const float* db2 = (const float*)d_in[15];
    const float* dw3 = (const float*)d_in[16];
    const float* db3 = (const float*)d_in[17];
    const float* fw  = (const float*)d_in[18];
    const float* fb  = (const float*)d_in[19];
    float* out = (float*)d_out;

    cudaFuncSetAttribute(din_attention_mma,
                         cudaFuncAttributeMaxDynamicSharedMemorySize, SMEM_BYTES);
    cudaFuncSetAttribute(mlp_tail_kernel,
                         cudaFuncAttributeMaxDynamicSharedMemorySize,
                         (int)(TM_TOT * sizeof(float)));

    // Launch pattern [nop, din, nop, tail]: the 6th launch under ncu -s 5 -c 1
    // is din_attention_mma (2nd replay), so the big kernel finally gets profiled.
    nop_kernel<<<1, 32>>>();
    din_attention_mma<<<BB, 256, SMEM_BYTES>>>(in_item_id, item_id, item_emb,
                                               aw1, ab1, aw2, ab2, afw, afb);
    nop_kernel<<<1, 32>>>();
    mlp_tail_kernel<<<BB / NB, 256, TM_TOT * sizeof(float)>>>(
        item_id, item_emb, nw, nb, dw1, db1, dw2, db2, dw3, db3,
        fw, fb, item_bias_tab, out);
}

// round 6
// speedup vs baseline: 2.2769x; 1.1315x over previous
#include <cuda_runtime.h>
#include <cuda_bf16.h>
#include <cstdint>

// ============================================================================
// DIN scorer R5:
//  - cvec precomputed for all batches in one kernel (16-batch LDG amortization)
//  - din mainloop unchanged (mma.sync bf16 3-term split)
//  - tail: 4 batches/CTA, 4 CTAs/SM
// ============================================================================

#define BB 2048
#define LL 200

__device__ float g_attn[BB * 128];
__device__ float g_cvec[BB * 128];

__device__ __forceinline__ float sigm(float x) {
    return __fdividef(1.0f, 1.0f + __expf(-x));
}

__device__ __forceinline__ void split2(float a, float b, uint32_t& hi, uint32_t& lo) {
    __nv_bfloat16 ah = __float2bfloat16(a);
    __nv_bfloat16 bh = __float2bfloat16(b);
    __nv_bfloat16 al = __float2bfloat16(a - __bfloat162float(ah));
    __nv_bfloat16 bl = __float2bfloat16(b - __bfloat162float(bh));
    hi = ((uint32_t)__bfloat16_as_ushort(bh) << 16) | (uint32_t)__bfloat16_as_ushort(ah);
    lo = ((uint32_t)__bfloat16_as_ushort(bl) << 16) | (uint32_t)__bfloat16_as_ushort(al);
}

__device__ __forceinline__ void mma_bf16(float* c, uint32_t a0, uint32_t a1,
                                         uint32_t a2, uint32_t a3,
                                         uint32_t b0, uint32_t b1) {
    asm("mma.sync.aligned.m16n8k16.row.col.f32.bf16.bf16.f32 "
        "{%0,%1,%2,%3}, {%4,%5,%6,%7}, {%8,%9}, {%0,%1,%2,%3};"
        : "+f"(c[0]), "+f"(c[1]), "+f"(c[2]), "+f"(c[3])
        : "r"(a0), "r"(a1), "r"(a2), "r"(a3), "r"(b0), "r"(b1));
}

__device__ __forceinline__ int pidx(int row, int pair) {
    return row * 64 + (pair ^ ((row & 7) << 2));
}

// ============================================================================
// cvec_kernel: g_cvec[b][j] = ab1[j] + sum_k t[k]*(aw1[k][j] + aw1[256+k][j])
// 16 batches per CTA; aw1 loads amortized across 16 batches.
// ============================================================================
__global__ __launch_bounds__(256, 2)
void cvec_kernel(const int*   __restrict__ item_id,
                 const float* __restrict__ item_emb,
                 const float* __restrict__ aw1,
                 const float* __restrict__ ab1)
{
    __shared__ float tS[16 * 128];
    const int b0  = blockIdx.x * 16;
    const int tid = threadIdx.x;

    for (int e = tid; e < 16 * 128; e += 256) {
        int bb = e >> 7, j = e & 127;
        long id = (long)__ldg(&item_id[b0 + bb]);
        tS[e] = __ldg(&item_emb[id * 128 + j]);
    }
    __syncthreads();

    const int j    = tid & 127;
    const int half = tid >> 7;              // 0: batches 0-7, 1: batches 8-15
    float acc[8];
    #pragma unroll
    for (int r = 0; r < 8; ++r) acc[r] = 0.0f;

    #pragma unroll 4
    for (int k = 0; k < 128; ++k) {
        float w = __ldg(&aw1[k * 128 + j]) + __ldg(&aw1[(256 + k) * 128 + j]);
        #pragma unroll
        for (int r = 0; r < 8; ++r)
            acc[r] += tS[(half * 8 + r) * 128 + k] * w;
    }
    float bj = __ldg(&ab1[j]);
    #pragma unroll
    for (int r = 0; r < 8; ++r)
        g_cvec[(b0 + half * 8 + r) * 128 + j] = acc[r] + bj;
}

// ---- smem byte offsets (din) ----
#define OFF_SA_HI   0
#define OFF_SA_LO   32768
#define OFF_B1_HI   65536
#define OFF_B1_LO   98304
#define OFF_B2_HI   131072
#define OFF_B2_LO   147456
#define OFF_T       163840
#define OFF_CVEC    164352
#define OFF_SCORE   164864
#define OFF_AB2     165376
#define OFF_AFW     165632
#define OFF_RED     165888
#define SMEM_BYTES  166400

__global__ __launch_bounds__(256, 1)
void din_attention_mma(const int*   __restrict__ in_item_id,
                       const int*   __restrict__ item_id,
                       const float* __restrict__ item_emb,
                       const float* __restrict__ aw1,
                       const float* __restrict__ aw2,
                       const float* __restrict__ ab2,
                       const float* __restrict__ afw,
                       const float* __restrict__ afb)
{
    extern __shared__ char smem[];
    uint32_t* saHI = (uint32_t*)(smem + OFF_SA_HI);
    uint32_t* saLO = (uint32_t*)(smem + OFF_SA_LO);
    uint32_t* b1HI = (uint32_t*)(smem + OFF_B1_HI);
    uint32_t* b1LO = (uint32_t*)(smem + OFF_B1_LO);
    uint32_t* b2HI = (uint32_t*)(smem + OFF_B2_HI);
    uint32_t* b2LO = (uint32_t*)(smem + OFF_B2_LO);
    float* tS     = (float*)(smem + OFF_T);
    float* cvec   = (float*)(smem + OFF_CVEC);
    float* scoreS = (float*)(smem + OFF_SCORE);
    float* ab2S   = (float*)(smem + OFF_AB2);
    float* afwS   = (float*)(smem + OFF_AFW);
    float* redS   = (float*)(smem + OFF_RED);

    const int tid = threadIdx.x, wid = tid >> 5, lid = tid & 31;
    const int b = blockIdx.x;
    const int g  = lid >> 2;
    const int tg = lid & 3;
    const int sx = g << 2;

    if (tid < 128) {
        long id = (long)item_id[b];
        tS[tid]   = item_emb[id * 128 + tid];
        cvec[tid] = g_cvec[b * 128 + tid];
    }
    if (tid < 64) { ab2S[tid] = __ldg(&ab2[tid]); afwS[tid] = __ldg(&afw[tid]); }
    __syncthreads();

    // B1 planes: Mb[k][j] = t[k]*A1[k][j] - A2[k][j], stored [j][kpair]
    for (int e = tid; e < 128 * 64; e += 256) {
        int j = e & 127, kp = e >> 7;
        int k0 = kp * 2, k1 = k0 + 1;
        float v0 = tS[k0] * __ldg(&aw1[(128 + k0) * 128 + j]) - __ldg(&aw1[(256 + k0) * 128 + j]);
        float v1 = tS[k1] * __ldg(&aw1[(128 + k1) * 128 + j]) - __ldg(&aw1[(256 + k1) * 128 + j]);
        uint32_t hi, lo; split2(v0, v1, hi, lo);
        int a = pidx(j, kp);
        b1HI[a] = hi; b1LO[a] = lo;
    }
    // B2 planes: aw2[k][n] stored [n][kpair]
    for (int e = tid; e < 64 * 64; e += 256) {
        int n = e & 63, kp = e >> 6;
        float v0 = __ldg(&aw2[(kp * 2) * 64 + n]);
        float v1 = __ldg(&aw2[(kp * 2 + 1) * 64 + n]);
        uint32_t hi, lo; split2(v0, v1, hi, lo);
        int a = pidx(n, kp);
        b2HI[a] = hi; b2LO[a] = lo;
    }
    const float afb0 = __ldg(&afb[0]);

    const int rA = wid * 16 + g;
    float attnReg = 0.0f;
    const int dAt  = tid & 127;
    const int half = tid >> 7;

    __syncthreads();

    for (int chunk = 0; chunk < 2; ++chunk) {
        const int base = chunk * 128;
        const int cr   = chunk ? (LL - 128) : 128;
        const bool act = (wid * 16 < cr);

        for (int e = tid; e < cr * 32; e += 256) {
            int row = e >> 5, q = e & 31;
            long id = (long)__ldg(&in_item_id[b * LL + base + row]);
            float4 v = __ldg(reinterpret_cast<const float4*>(item_emb + id * 128) + q);
            uint32_t h0, l0, h1, l1;
            split2(v.x, v.y, h0, l0);
            split2(v.z, v.w, h1, l1);
            int a = pidx(row, q * 2);
            *(uint2*)(saHI + a) = make_uint2(h0, h1);
            *(uint2*)(saLO + a) = make_uint2(l0, l1);
        }
        __syncthreads();

        uint32_t hT_hi[16], hT_lo[16], hB_hi[16], hB_lo[16];

        if (act) {
            float acc[16][4];
            #pragma unroll
            for (int nt = 0; nt < 16; ++nt)
                #pragma unroll
                for (int i = 0; i < 4; ++i) acc[nt][i] = 0.0f;

            const int rTop = rA * 64, rBot = (rA + 8) * 64;
            #pragma unroll
            for (int ks = 0; ks < 8; ++ks) {
                const int p0 = (8 * ks + tg) ^ sx;
                const int p1 = p0 ^ 4;
                uint32_t ah0 = saHI[rTop + p0], ah1 = saHI[rBot + p0];
                uint32_t ah2 = saHI[rTop + p1], ah3 = saHI[rBot + p1];
                uint32_t al0 = saLO[rTop + p0], al1 = saLO[rBot + p0];
                uint32_t al2 = saLO[rTop + p1], al3 = saLO[rBot + p1];
                #pragma unroll
                for (int nt = 0; nt < 16; ++nt) {
                    const int nb = (8 * nt + g) * 64;
                    uint32_t bh0 = b1HI[nb + p0], bh1 = b1HI[nb + p1];
                    uint32_t bl0 = b1LO[nb + p0], bl1 = b1LO[nb + p1];
                    mma_bf16(acc[nt], ah0, ah1, ah2, ah3, bh0, bh1);
                    mma_bf16(acc[nt], al0, al1, al2, al3, bh0, bh1);
                    mma_bf16(acc[nt], ah0, ah1, ah2, ah3, bl0, bl1);
                }
            }
            #pragma unroll
            for (int nt = 0; nt < 16; ++nt) {
                const int c0 = 8 * nt + 2 * tg;
                float t0 = sigm(acc[nt][0] + cvec[c0]);
                float t1 = sigm(acc[nt][1] + cvec[c0 + 1]);
                float b0 = sigm(acc[nt][2] + cvec[c0]);
                float b1 = sigm(acc[nt][3] + cvec[c0 + 1]);
                split2(t0, t1, hT_hi[nt], hT_lo[nt]);
                split2(b0, b1, hB_hi[nt], hB_lo[nt]);
            }
        }

        float acc2[8][4];
        #pragma unroll
        for (int nt = 0; nt < 8; ++nt)
            #pragma unroll
            for (int i = 0; i < 4; ++i) acc2[nt][i] = 0.0f;

        if (act) {
            #pragma unroll
            for (int ks = 0; ks < 8; ++ks) {
                const int p0 = (8 * ks + tg) ^ sx;
                const int p1 = p0 ^ 4;
                uint32_t ah0 = hT_hi[2 * ks],     ah1 = hB_hi[2 * ks];
                uint32_t ah2 = hT_hi[2 * ks + 1], ah3 = hB_hi[2 * ks + 1];
                uint32_t al0 = hT_lo[2 * ks],     al1 = hB_lo[2 * ks];
                uint32_t al2 = hT_lo[2 * ks + 1], al3 = hB_lo[2 * ks + 1];
                #pragma unroll
                for (int nt = 0; nt < 8; ++nt) {
                    const int nb = (8 * nt + g) * 64;
                    uint32_t bh0 = b2HI[nb + p0], bh1 = b2HI[nb + p1];
                    uint32_t bl0 = b2LO[nb + p0], bl1 = b2LO[nb + p1];
                    mma_bf16(acc2[nt], ah0, ah1, ah2, ah3, bh0, bh1);
                    mma_bf16(acc2[nt], al0, al1, al2, al3, bh0, bh1);
                    mma_bf16(acc2[nt], ah0, ah1, ah2, ah3, bl0, bl1);
                }
            }
        }

        {
            float vT = 0.0f, vB = 0.0f;
            #pragma unroll
            for (int nt = 0; nt < 8; ++nt) {
                const int c0 = 8 * nt + 2 * tg;
                vT += sigm(acc2[nt][0] + ab2S[c0])     * afwS[c0];
                vT += sigm(acc2[nt][1] + ab2S[c0 + 1]) * afwS[c0 + 1];
                vB += sigm(acc2[nt][2] + ab2S[c0])     * afwS[c0];
                vB += sigm(acc2[nt][3] + ab2S[c0 + 1]) * afwS[c0 + 1];
            }
            vT += __shfl_xor_sync(0xffffffffu, vT, 1);
            vT += __shfl_xor_sync(0xffffffffu, vT, 2);
            vB += __shfl_xor_sync(0xffffffffu, vB, 1);
            vB += __shfl_xor_sync(0xffffffffu, vB, 2);
            if (tg == 0) {
                int r0 = rA, r1 = rA + 8;
                float s0 = 0.0f, s1 = 0.0f;
                if (act && r0 < cr) {
                    int id = __ldg(&in_item_id[b * LL + base + r0]);
                    s0 = (id == 0) ? 0.0f : (vT + afb0);
                }
                if (act && r1 < cr) {
                    int id = __ldg(&in_item_id[b * LL + base + r1]);
                    s1 = (id == 0) ? 0.0f : (vB + afb0);
                }
                scoreS[r0] = s0;
                scoreS[r1] = s1;
            }
        }
        __syncthreads();

        {
            const int h0 = half * (cr >> 1);
            const int h1 = h0 + (cr >> 1);
            const int pr = dAt >> 1, sel = (dAt & 1) * 16;
            for (int row = h0; row < h1; ++row) {
                float sc = scoreS[row];
                int a = pidx(row, pr);
                uint32_t whi = saHI[a], wlo = saLO[a];
                float s = __bfloat162float(__ushort_as_bfloat16((unsigned short)(whi >> sel)))
                        + __bfloat162float(__ushort_as_bfloat16((unsigned short)(wlo >> sel)));
                attnReg += sc * s;
            }
        }
        __syncthreads();
    }

    if (tid >= 128) redS[dAt] = attnReg;
    __syncthreads();
    if (tid < 128) g_attn[b * 128 + tid] = attnReg + redS[tid];
}

// ============================================================================
// Fused MLP tail: 4 batches/CTA, 512 CTAs, 24.6KB smem -> 4 CTAs/SM.
// ============================================================================
#define NB 4
#define TM_ATTN 0
#define TM_T    (NB*128)
#define TM_CAT  (2*NB*128)
#define TM_H1   (TM_CAT + NB*384)
#define TM_H2   (TM_H1 + NB*512)
#define TM_H3   (TM_H2 + NB*256)
#define TM_TOT  (TM_H3 + NB*128)   // 6144 floats = 24576 B

__global__ __launch_bounds__(256, 4)
void mlp_tail_kernel(const int*   __restrict__ item_id,
                     const float* __restrict__ item_emb,
                     const float* __restrict__ nw,
                     const float* __restrict__ nb,
                     const float* __restrict__ dw1,
                     const float* __restrict__ db1,
                     const float* __restrict__ dw2,
                     const float* __restrict__ db2,
                     const float* __restrict__ dw3,
                     const float* __restrict__ db3,
                     const float* __restrict__ fw,
                     const float* __restrict__ fb,
                     const float* __restrict__ item_bias_tab,
                     float*       __restrict__ out)
{
    extern __shared__ float sm[];
    const int b0  = blockIdx.x * NB;
    const int tid = threadIdx.x;

    for (int e = tid; e < NB * 128; e += 256) {
        int bb = e >> 7, j = e & 127;
        sm[TM_ATTN + e] = g_attn[(b0 + bb) * 128 + j];
        long id = (long)__ldg(&item_id[b0 + bb]);
        sm[TM_T + e]    = __ldg(&item_emb[id * 128 + j]);
    }
    __syncthreads();

    // Phase A: attn2 = attn @ nw + nb ; build cat
    {
        const int j = tid & 127;
        const int rbase = (tid >> 7) * 2;
        float acc[2];
        float nbj = __ldg(&nb[j]);
        acc[0] = nbj; acc[1] = nbj;
        #pragma unroll 4
        for (int k = 0; k < 128; k += 4) {
            float w0 = __ldg(&nw[(k + 0) * 128 + j]);
            float w1 = __ldg(&nw[(k + 1) * 128 + j]);
            float w2 = __ldg(&nw[(k + 2) * 128 + j]);
            float w3 = __ldg(&nw[(k + 3) * 128 + j]);
            #pragma unroll
            for (int i = 0; i < 2; ++i) {
                float4 a = *reinterpret_cast<const float4*>(sm + TM_ATTN + (rbase + i) * 128 + k);
                acc[i] += a.x * w0 + a.y * w1 + a.z * w2 + a.w * w3;
            }
        }
        #pragma unroll
        for (int i = 0; i < 2; ++i) {
            int r = rbase + i;
            float a2 = acc[i];
            float t  = sm[TM_T + r * 128 + j];
            sm[TM_CAT + r * 384 + j]       = a2;
            sm[TM_CAT + r * 384 + 128 + j] = t;
            sm[TM_CAT + r * 384 + 256 + j] = t * a2;
        }
    }
    __syncthreads();

    // Phase B: g1 = sigmoid(cat @ dw1 + db1)  384 -> 512
    {
        const int j = tid;
        float acc0[NB], acc1[NB];
        float bj0 = __ldg(&db1[j]), bj1 = __ldg(&db1[j + 256]);
        #pragma unroll
        for (int r = 0; r < NB; ++r) { acc0[r] = bj0; acc1[r] = bj1; }
        #pragma unroll 4
        for (int k = 0; k < 384; k += 4) {
            float w0a = __ldg(&dw1[(k + 0) * 512 + j]);
            float w1a = __ldg(&dw1[(k + 1) * 512 + j]);
            float w2a = __ldg(&dw1[(k + 2) * 512 + j]);
            float w3a = __ldg(&dw1[(k + 3) * 512 + j]);
            float w0b = __ldg(&dw1[(k + 0) * 512 + j + 256]);
            float w1b = __ldg(&dw1[(k + 1) * 512 + j + 256]);
            float w2b = __ldg(&dw1[(k + 2) * 512 + j + 256]);
            float w3b = __ldg(&dw1[(k + 3) * 512 + j + 256]);
            #pragma unroll
            for (int r = 0; r < NB; ++r) {
                float4 a = *reinterpret_cast<const float4*>(sm + TM_CAT + r * 384 + k);
                acc0[r] += a.x * w0a + a.y * w1a + a.z * w2a + a.w * w3a;
                acc1[r] += a.x * w0b + a.y * w1b + a.z * w2b + a.w * w3b;
            }
        }
        #pragma unroll
        for (int r = 0; r < NB; ++r) {
            sm[TM_H1 + r * 512 + j]       = sigm(acc0[r]);
            sm[TM_H1 + r * 512 + j + 256] = sigm(acc1[r]);
        }
    }
    __syncthreads();

    // Phase C: g2 = sigmoid(g1 @ dw2 + db2)  512 -> 256
    {
        const int j = tid;
        float acc[NB];
        float bj = __ldg(&db2[j]);
        #pragma unroll
        for (int r = 0; r < NB; ++r) acc[r] = bj;
        #pragma unroll 4
        for (int k = 0; k < 512; k += 4) {
            float w0 = __ldg(&dw2[(k + 0) * 256 + j]);
            float w1 = __ldg(&dw2[(k + 1) * 256 + j]);
            float w2 = __ldg(&dw2[(k + 2) * 256 + j]);
            float w3 = __ldg(&dw2[(k + 3) * 256 + j]);
            #pragma unroll
            for (int r = 0; r < NB; ++r) {
                float4 a = *reinterpret_cast<const float4*>(sm + TM_H1 + r * 512 + k);
                acc[r] += a.x * w0 + a.y * w1 + a.z * w2 + a.w * w3;
            }
        }
        #pragma unroll
        for (int r = 0; r < NB; ++r)
            sm[TM_H2 + r * 256 + j] = sigm(acc[r]);
    }
    __syncthreads();

    // Phase D: g3 = sigmoid(g2 @ dw3 + db3)  256 -> 128
    {
        const int j = tid & 127;
        const int rbase = (tid >> 7) * 2;
        float acc[2];
        float bj = __ldg(&db3[j]);
        acc[0] = bj; acc[1] = bj;
        #pragma unroll 4
        for (int k = 0; k < 256; k += 4) {
            float w0 = __ldg(&dw3[(k + 0) * 128 + j]);
            float w1 = __ldg(&dw3[(k + 1) * 128 + j]);
            float w2 = __ldg(&dw3[(k + 2) * 128 + j]);
            float w3 = __ldg(&dw3[(k + 3) * 128 + j]);
            #pragma unroll
            for (int i = 0; i < 2; ++i) {
                float4 a = *reinterpret_cast<const float4*>(sm + TM_H2 + (rbase + i) * 256 + k);
                acc[i] += a.x * w0 + a.y * w1 + a.z * w2 + a.w * w3;
            }
        }
        #pragma unroll
        for (int i = 0; i < 2; ++i)
            sm[TM_H3 + (rbase + i) * 128 + j] = sigm(acc[i]);
    }
    __syncthreads();

    // Phase E: out = g3 . fw + fb + item_bias  (warps 0-3, one row each)
    {
        const int wid  = tid >> 5;
        const int lane = tid & 31;
        if (wid < NB) {
            float v = 0.0f;
            #pragma unroll
            for (int q = 0; q < 4; ++q)
                v += sm[TM_H3 + wid * 128 + lane + 32 * q] * __ldg(&fw[lane + 32 * q]);
            #pragma unroll
            for (int m = 16; m > 0; m >>= 1) v += __shfl_xor_sync(0xffffffffu, v, m);
            if (lane == 0) {
                int b = b0 + wid;
                out[b] = v + __ldg(&fb[0]) + __ldg(&item_bias_tab[item_id[b]]);
            }
        }
    }
}

// ============================================================================
extern "C" void kernel_launch(void* const* d_in, const int* in_sizes, int n_in,
                              void* d_out, int out_size)
{
    const int*   in_item_id    = (const int*)  d_in[0];
    const int*   item_id       = (const int*)  d_in[1];
    const float* item_emb      = (const float*)d_in[2];
    const float* item_bias_tab = (const float*)d_in[3];
    const float* aw1 = (const float*)d_in[4];
    const float* ab1 = (const float*)d_in[5];
    const float* aw2 = (const float*)d_in[6];
    const float* ab2 = (const float*)d_in[7];
    const float* afw = (const float*)d_in[8];
    const float* afb = (const float*)d_in[9];
    const float* nw  = (const float*)d_in[10];
    const float* nb  = (const float*)d_in[11];
    const float* dw1 = (const float*)d_in[12];
    const float* db1 = (const float*)d_in[13];
    const float* dw2 = (const float*)d_in[14];
    const float* db2 = (const float*)d_in[15];
    const float* dw3 = (const float*)d_in[16];
    const float* db3 = (const float*)d_in[17];
    const float* fw  = (const float*)d_in[18];
    const float* fb  = (const float*)d_in[19];
    float* out = (float*)d_out;

    cudaFuncSetAttribute(din_attention_mma,
                         cudaFuncAttributeMaxDynamicSharedMemorySize, SMEM_BYTES);
    cudaFuncSetAttribute(mlp_tail_kernel,
                         cudaFuncAttributeMaxDynamicSharedMemorySize,
                         (int)(TM_TOT * sizeof(float)));

    cvec_kernel<<<BB / 16, 256>>>(item_id, item_emb, aw1, ab1);
    din_attention_mma<<<BB, 256, SMEM_BYTES>>>(in_item_id, item_id, item_emb,
                                               aw1, aw2, ab2, afw, afb);
    mlp_tail_kernel<<<BB / NB, 256, TM_TOT * sizeof(float)>>>(
        item_id, item_emb, nw, nb, dw1, db1, dw2, db2, dw3, db3,
        fw, fb, item_bias_tab, out);
}

// round 7
// speedup vs baseline: 2.5628x; 1.1255x over previous
#include <cuda_runtime.h>
#include <cuda_bf16.h>
#include <cstdint>

// ============================================================================
// DIN scorer R6:
//  - din: double-buffered gather (chunk1 LDGs issued before chunk0 compute),
//    prefetched id loads, single merged latency region for stage+B1+B2.
//  - cvec: 512 threads, 4-way k-split + smem reduction.
//  - tail: unchanged (4 batches/CTA).
// ============================================================================

#define BB 2048
#define LL 200

__device__ float g_attn[BB * 128];
__device__ float g_cvec[BB * 128];

__device__ __forceinline__ float sigm(float x) {
    return __fdividef(1.0f, 1.0f + __expf(-x));
}

__device__ __forceinline__ void split2(float a, float b, uint32_t& hi, uint32_t& lo) {
    __nv_bfloat16 ah = __float2bfloat16(a);
    __nv_bfloat16 bh = __float2bfloat16(b);
    __nv_bfloat16 al = __float2bfloat16(a - __bfloat162float(ah));
    __nv_bfloat16 bl = __float2bfloat16(b - __bfloat162float(bh));
    hi = ((uint32_t)__bfloat16_as_ushort(bh) << 16) | (uint32_t)__bfloat16_as_ushort(ah);
    lo = ((uint32_t)__bfloat16_as_ushort(bl) << 16) | (uint32_t)__bfloat16_as_ushort(al);
}

__device__ __forceinline__ void mma_bf16(float* c, uint32_t a0, uint32_t a1,
                                         uint32_t a2, uint32_t a3,
                                         uint32_t b0, uint32_t b1) {
    asm("mma.sync.aligned.m16n8k16.row.col.f32.bf16.bf16.f32 "
        "{%0,%1,%2,%3}, {%4,%5,%6,%7}, {%8,%9}, {%0,%1,%2,%3};"
        : "+f"(c[0]), "+f"(c[1]), "+f"(c[2]), "+f"(c[3])
        : "r"(a0), "r"(a1), "r"(a2), "r"(a3), "r"(b0), "r"(b1));
}

__device__ __forceinline__ int pidx(int row, int pair) {
    return row * 64 + (pair ^ ((row & 7) << 2));
}

// ============================================================================
// cvec_kernel: g_cvec[b][j] = ab1[j] + sum_k t[k]*(aw1[k][j] + aw1[256+k][j])
// 512 threads, 16 batches/CTA, 4-way k-split, transposed tS for LDS.128.
// ============================================================================
__global__ __launch_bounds__(512, 2)
void cvec_kernel(const int*   __restrict__ item_id,
                 const float* __restrict__ item_emb,
                 const float* __restrict__ aw1,
                 const float* __restrict__ ab1)
{
    __shared__ float tT[128 * 16];      // transposed: tT[k*16 + b]
    __shared__ float part[4 * 16 * 128];
    const int b0  = blockIdx.x * 16;
    const int tid = threadIdx.x;

    // load t transposed: e -> (k = e>>4, b = e&15)
    for (int e = tid; e < 128 * 16; e += 512) {
        int k = e >> 4, bb = e & 15;
        long id = (long)__ldg(&item_id[b0 + bb]);
        tT[e] = __ldg(&item_emb[id * 128 + k]);
    }
    __syncthreads();

    const int j  = tid & 127;
    const int kq = tid >> 7;            // 0..3, k range [kq*32, kq*32+32)
    float acc[16];
    #pragma unroll
    for (int r = 0; r < 16; ++r) acc[r] = 0.0f;

    #pragma unroll 8
    for (int kk = 0; kk < 32; ++kk) {
        int k = kq * 32 + kk;
        float w = __ldg(&aw1[k * 128 + j]) + __ldg(&aw1[(256 + k) * 128 + j]);
        const float4* tp = reinterpret_cast<const float4*>(tT + k * 16);
        #pragma unroll
        for (int q = 0; q < 4; ++q) {
            float4 tv = tp[q];
            acc[q * 4 + 0] += tv.x * w;
            acc[q * 4 + 1] += tv.y * w;
            acc[q * 4 + 2] += tv.z * w;
            acc[q * 4 + 3] += tv.w * w;
        }
    }
    #pragma unroll
    for (int r = 0; r < 16; ++r)
        part[(kq * 16 + r) * 128 + j] = acc[r];
    __syncthreads();

    for (int e = tid; e < 16 * 128; e += 512) {
        int bb = e >> 7, jj = e & 127;
        float s = part[(0 * 16 + bb) * 128 + jj] + part[(1 * 16 + bb) * 128 + jj]
                + part[(2 * 16 + bb) * 128 + jj] + part[(3 * 16 + bb) * 128 + jj]
                + __ldg(&ab1[jj]);
        g_cvec[(b0 + bb) * 128 + jj] = s;
    }
}

// ---- smem byte offsets (din) ----
#define OFF_SA0_HI  0         // chunk0 seq [128][64] b32-pairs
#define OFF_SA0_LO  32768
#define OFF_SA1_HI  65536     // chunk1 seq (80-row allocation, 72 used)
#define OFF_SA1_LO  86016
#define OFF_B1_HI   106496
#define OFF_B1_LO   139264
#define OFF_B2_HI   172032
#define OFF_B2_LO   188416
#define OFF_T       204800
#define OFF_CVEC    205312
#define OFF_SCORE   205824
#define OFF_AB2     206336
#define OFF_AFW     206592
#define OFF_RED     206848
#define SMEM_BYTES  207360

// Gather CR rows (CR*32 multiple of 256): prefetch ids, unrolled data loads.
template<int CR>
__device__ __forceinline__ void gather_chunk(char* smem, int offHI, int offLO,
                                             const int* __restrict__ ids,
                                             const float* __restrict__ item_emb,
                                             int tid)
{
    uint32_t* dHI = (uint32_t*)(smem + offHI);
    uint32_t* dLO = (uint32_t*)(smem + offLO);
    constexpr int NIT = CR * 32 / 256;
    int idv[NIT];
    #pragma unroll
    for (int i = 0; i < NIT; ++i)
        idv[i] = __ldg(&ids[(tid + i * 256) >> 5]);
    #pragma unroll
    for (int i = 0; i < NIT; ++i) {
        int e = tid + i * 256, row = e >> 5, q = e & 31;
        float4 v = __ldg(reinterpret_cast<const float4*>(item_emb + (long)idv[i] * 128) + q);
        uint32_t h0, l0, h1, l1;
        split2(v.x, v.y, h0, l0);
        split2(v.z, v.w, h1, l1);
        int a = pidx(row, q * 2);
        *(uint2*)(dHI + a) = make_uint2(h0, h1);
        *(uint2*)(dLO + a) = make_uint2(l0, l1);
    }
}

// Full per-chunk compute: GEMM1 -> sigmoid (regs) -> GEMM2 -> score -> attn.
template<int CR>
__device__ __forceinline__ void compute_chunk(char* smem, int offHI, int offLO,
                                              const int* __restrict__ ids,
                                              float afb0, float& attnReg,
                                              int tid, int wid, int g, int tg, int sx,
                                              int rA, int dAt, int half)
{
    uint32_t* saHI = (uint32_t*)(smem + offHI);
    uint32_t* saLO = (uint32_t*)(smem + offLO);
    uint32_t* b1HI = (uint32_t*)(smem + OFF_B1_HI);
    uint32_t* b1LO = (uint32_t*)(smem + OFF_B1_LO);
    uint32_t* b2HI = (uint32_t*)(smem + OFF_B2_HI);
    uint32_t* b2LO = (uint32_t*)(smem + OFF_B2_LO);
    float* cvec   = (float*)(smem + OFF_CVEC);
    float* scoreS = (float*)(smem + OFF_SCORE);
    float* ab2S   = (float*)(smem + OFF_AB2);
    float* afwS   = (float*)(smem + OFF_AFW);

    const bool act = (wid * 16 < CR);

    uint32_t hT_hi[16], hT_lo[16], hB_hi[16], hB_lo[16];

    if (act) {
        float acc[16][4];
        #pragma unroll
        for (int nt = 0; nt < 16; ++nt)
            #pragma unroll
            for (int i = 0; i < 4; ++i) acc[nt][i] = 0.0f;

        const int rTop = rA * 64, rBot = (rA + 8) * 64;
        #pragma unroll
        for (int ks = 0; ks < 8; ++ks) {
            const int p0 = (8 * ks + tg) ^ sx;
            const int p1 = p0 ^ 4;
            uint32_t ah0 = saHI[rTop + p0], ah1 = saHI[rBot + p0];
            uint32_t ah2 = saHI[rTop + p1], ah3 = saHI[rBot + p1];
            uint32_t al0 = saLO[rTop + p0], al1 = saLO[rBot + p0];
            uint32_t al2 = saLO[rTop + p1], al3 = saLO[rBot + p1];
            #pragma unroll
            for (int nt = 0; nt < 16; ++nt) {
                const int nb = (8 * nt + g) * 64;
                uint32_t bh0 = b1HI[nb + p0], bh1 = b1HI[nb + p1];
                uint32_t bl0 = b1LO[nb + p0], bl1 = b1LO[nb + p1];
                mma_bf16(acc[nt], ah0, ah1, ah2, ah3, bh0, bh1);
                mma_bf16(acc[nt], al0, al1, al2, al3, bh0, bh1);
                mma_bf16(acc[nt], ah0, ah1, ah2, ah3, bl0, bl1);
            }
        }
        #pragma unroll
        for (int nt = 0; nt < 16; ++nt) {
            const int c0 = 8 * nt + 2 * tg;
            float t0 = sigm(acc[nt][0] + cvec[c0]);
            float t1 = sigm(acc[nt][1] + cvec[c0 + 1]);
            float b0 = sigm(acc[nt][2] + cvec[c0]);
            float b1 = sigm(acc[nt][3] + cvec[c0 + 1]);
            split2(t0, t1, hT_hi[nt], hT_lo[nt]);
            split2(b0, b1, hB_hi[nt], hB_lo[nt]);
        }
    }

    float acc2[8][4];
    #pragma unroll
    for (int nt = 0; nt < 8; ++nt)
        #pragma unroll
        for (int i = 0; i < 4; ++i) acc2[nt][i] = 0.0f;

    if (act) {
        #pragma unroll
        for (int ks = 0; ks < 8; ++ks) {
            const int p0 = (8 * ks + tg) ^ sx;
            const int p1 = p0 ^ 4;
            uint32_t ah0 = hT_hi[2 * ks],     ah1 = hB_hi[2 * ks];
            uint32_t ah2 = hT_hi[2 * ks + 1], ah3 = hB_hi[2 * ks + 1];
            uint32_t al0 = hT_lo[2 * ks],     al1 = hB_lo[2 * ks];
            uint32_t al2 = hT_lo[2 * ks + 1], al3 = hB_lo[2 * ks + 1];
            #pragma unroll
            for (int nt = 0; nt < 8; ++nt) {
                const int nb = (8 * nt + g) * 64;
                uint32_t bh0 = b2HI[nb + p0], bh1 = b2HI[nb + p1];
                uint32_t bl0 = b2LO[nb + p0], bl1 = b2LO[nb + p1];
                mma_bf16(acc2[nt], ah0, ah1, ah2, ah3, bh0, bh1);
                mma_bf16(acc2[nt], al0, al1, al2, al3, bh0, bh1);
                mma_bf16(acc2[nt], ah0, ah1, ah2, ah3, bl0, bl1);
            }
        }
    }

    {
        float vT = 0.0f, vB = 0.0f;
        #pragma unroll
        for (int nt = 0; nt < 8; ++nt) {
            const int c0 = 8 * nt + 2 * tg;
            vT += sigm(acc2[nt][0] + ab2S[c0])     * afwS[c0];
            vT += sigm(acc2[nt][1] + ab2S[c0 + 1]) * afwS[c0 + 1];
            vB += sigm(acc2[nt][2] + ab2S[c0])     * afwS[c0];
            vB += sigm(acc2[nt][3] + ab2S[c0 + 1]) * afwS[c0 + 1];
        }
        vT += __shfl_xor_sync(0xffffffffu, vT, 1);
        vT += __shfl_xor_sync(0xffffffffu, vT, 2);
        vB += __shfl_xor_sync(0xffffffffu, vB, 1);
        vB += __shfl_xor_sync(0xffffffffu, vB, 2);
        if (tg == 0) {
            int r0 = rA, r1 = rA + 8;
            float s0 = 0.0f, s1 = 0.0f;
            if (act && r0 < CR) {
                int id = __ldg(&ids[r0]);
                s0 = (id == 0) ? 0.0f : (vT + afb0);
            }
            if (act && r1 < CR) {
                int id = __ldg(&ids[r1]);
                s1 = (id == 0) ? 0.0f : (vB + afb0);
            }
            scoreS[r0] = s0;
            if (r1 < 128) scoreS[r1] = s1;
        }
    }
    __syncthreads();

    {
        const int h0 = half * (CR >> 1);
        const int h1 = h0 + (CR >> 1);
        const int pr = dAt >> 1, sel = (dAt & 1) * 16;
        for (int row = h0; row < h1; ++row) {
            float sc = scoreS[row];
            int a = pidx(row, pr);
            uint32_t whi = saHI[a], wlo = saLO[a];
            float s = __bfloat162float(__ushort_as_bfloat16((unsigned short)(whi >> sel)))
                    + __bfloat162float(__ushort_as_bfloat16((unsigned short)(wlo >> sel)));
            attnReg += sc * s;
        }
    }
    __syncthreads();
}

__global__ __launch_bounds__(256, 1)
void din_attention_mma(const int*   __restrict__ in_item_id,
                       const int*   __restrict__ item_id,
                       const float* __restrict__ item_emb,
                       const float* __restrict__ aw1,
                       const float* __restrict__ aw2,
                       const float* __restrict__ ab2,
                       const float* __restrict__ afw,
                       const float* __restrict__ afb)
{
    extern __shared__ char smem[];
    uint32_t* b1HI = (uint32_t*)(smem + OFF_B1_HI);
    uint32_t* b1LO = (uint32_t*)(smem + OFF_B1_LO);
    uint32_t* b2HI = (uint32_t*)(smem + OFF_B2_HI);
    uint32_t* b2LO = (uint32_t*)(smem + OFF_B2_LO);
    float* tS     = (float*)(smem + OFF_T);
    float* cvec   = (float*)(smem + OFF_CVEC);
    float* ab2S   = (float*)(smem + OFF_AB2);
    float* afwS   = (float*)(smem + OFF_AFW);
    float* redS   = (float*)(smem + OFF_RED);

    const int tid = threadIdx.x, wid = tid >> 5, lid = tid & 31;
    const int b = blockIdx.x;
    const int g  = lid >> 2;
    const int tg = lid & 3;
    const int sx = g << 2;

    if (tid < 128) {
        long id = (long)item_id[b];
        tS[tid]   = item_emb[id * 128 + tid];
        cvec[tid] = g_cvec[b * 128 + tid];
    }
    if (tid < 64) { ab2S[tid] = __ldg(&ab2[tid]); afwS[tid] = __ldg(&afw[tid]); }
    __syncthreads();

    // ---- single latency region: chunk0 gather + B1 build + B2 build ----
    gather_chunk<128>(smem, OFF_SA0_HI, OFF_SA0_LO,
                      in_item_id + b * LL, item_emb, tid);

    for (int e = tid; e < 128 * 64; e += 256) {
        int j = e & 127, kp = e >> 7;
        int k0 = kp * 2, k1 = k0 + 1;
        float v0 = tS[k0] * __ldg(&aw1[(128 + k0) * 128 + j]) - __ldg(&aw1[(256 + k0) * 128 + j]);
        float v1 = tS[k1] * __ldg(&aw1[(128 + k1) * 128 + j]) - __ldg(&aw1[(256 + k1) * 128 + j]);
        uint32_t hi, lo; split2(v0, v1, hi, lo);
        int a = pidx(j, kp);
        b1HI[a] = hi; b1LO[a] = lo;
    }
    for (int e = tid; e < 64 * 64; e += 256) {
        int n = e & 63, kp = e >> 6;
        float v0 = __ldg(&aw2[(kp * 2) * 64 + n]);
        float v1 = __ldg(&aw2[(kp * 2 + 1) * 64 + n]);
        uint32_t hi, lo; split2(v0, v1, hi, lo);
        int a = pidx(n, kp);
        b2HI[a] = hi; b2LO[a] = lo;
    }
    const float afb0 = __ldg(&afb[0]);
    __syncthreads();

    // ---- prefetch chunk1 gather: LDGs fly during chunk0 compute ----
    gather_chunk<72>(smem, OFF_SA1_HI, OFF_SA1_LO,
                     in_item_id + b * LL + 128, item_emb, tid);

    const int rA   = wid * 16 + g;
    const int dAt  = tid & 127;
    const int half = tid >> 7;
    float attnReg = 0.0f;

    compute_chunk<128>(smem, OFF_SA0_HI, OFF_SA0_LO, in_item_id + b * LL,
                       afb0, attnReg, tid, wid, g, tg, sx, rA, dAt, half);
    compute_chunk<72>(smem, OFF_SA1_HI, OFF_SA1_LO, in_item_id + b * LL + 128,
                      afb0, attnReg, tid, wid, g, tg, sx, rA, dAt, half);

    if (tid >= 128) redS[dAt] = attnReg;
    __syncthreads();
    if (tid < 128) g_attn[b * 128 + tid] = attnReg + redS[tid];
}

// ============================================================================
// Fused MLP tail: 4 batches/CTA, 512 CTAs, 24.6KB smem -> 4 CTAs/SM.
// ============================================================================
#define NB 4
#define TM_ATTN 0
#define TM_T    (NB*128)
#define TM_CAT  (2*NB*128)
#define TM_H1   (TM_CAT + NB*384)
#define TM_H2   (TM_H1 + NB*512)
#define TM_H3   (TM_H2 + NB*256)
#define TM_TOT  (TM_H3 + NB*128)   // 6144 floats = 24576 B

__global__ __launch_bounds__(256, 4)
void mlp_tail_kernel(const int*   __restrict__ item_id,
                     const float* __restrict__ item_emb,
                     const float* __restrict__ nw,
                     const float* __restrict__ nb,
                     const float* __restrict__ dw1,
                     const float* __restrict__ db1,
                     const float* __restrict__ dw2,
                     const float* __restrict__ db2,
                     const float* __restrict__ dw3,
                     const float* __restrict__ db3,
                     const float* __restrict__ fw,
                     const float* __restrict__ fb,
                     const float* __restrict__ item_bias_tab,
                     float*       __restrict__ out)
{
    extern __shared__ float sm[];
    const int b0  = blockIdx.x * NB;
    const int tid = threadIdx.x;

    for (int e = tid; e < NB * 128; e += 256) {
        int bb = e >> 7, j = e & 127;
        sm[TM_ATTN + e] = g_attn[(b0 + bb) * 128 + j];
        long id = (long)__ldg(&item_id[b0 + bb]);
        sm[TM_T + e]    = __ldg(&item_emb[id * 128 + j]);
    }
    __syncthreads();

    // Phase A: attn2 = attn @ nw + nb ; build cat
    {
        const int j = tid & 127;
        const int rbase = (tid >> 7) * 2;
        float acc[2];
        float nbj = __ldg(&nb[j]);
        acc[0] = nbj; acc[1] = nbj;
        #pragma unroll 4
        for (int k = 0; k < 128; k += 4) {
            float w0 = __ldg(&nw[(k + 0) * 128 + j]);
            float w1 = __ldg(&nw[(k + 1) * 128 + j]);
            float w2 = __ldg(&nw[(k + 2) * 128 + j]);
            float w3 = __ldg(&nw[(k + 3) * 128 + j]);
            #pragma unroll
            for (int i = 0; i < 2; ++i) {
                float4 a = *reinterpret_cast<const float4*>(sm + TM_ATTN + (rbase + i) * 128 + k);
                acc[i] += a.x * w0 + a.y * w1 + a.z * w2 + a.w * w3;
            }
        }
        #pragma unroll
        for (int i = 0; i < 2; ++i) {
            int r = rbase + i;
            float a2 = acc[i];
            float t  = sm[TM_T + r * 128 + j];
            sm[TM_CAT + r * 384 + j]       = a2;
            sm[TM_CAT + r * 384 + 128 + j] = t;
            sm[TM_CAT + r * 384 + 256 + j] = t * a2;
        }
    }
    __syncthreads();

    // Phase B: g1 = sigmoid(cat @ dw1 + db1)  384 -> 512
    {
        const int j = tid;
        float acc0[NB], acc1[NB];
        float bj0 = __ldg(&db1[j]), bj1 = __ldg(&db1[j + 256]);
        #pragma unroll
        for (int r = 0; r < NB; ++r) { acc0[r] = bj0; acc1[r] = bj1; }
        #pragma unroll 4
        for (int k = 0; k < 384; k += 4) {
            float w0a = __ldg(&dw1[(k + 0) * 512 + j]);
            float w1a = __ldg(&dw1[(k + 1) * 512 + j]);
            float w2a = __ldg(&dw1[(k + 2) * 512 + j]);
            float w3a = __ldg(&dw1[(k + 3) * 512 + j]);
            float w0b = __ldg(&dw1[(k + 0) * 512 + j + 256]);
            float w1b = __ldg(&dw1[(k + 1) * 512 + j + 256]);
            float w2b = __ldg(&dw1[(k + 2) * 512 + j + 256]);
            float w3b = __ldg(&dw1[(k + 3) * 512 + j + 256]);
            #pragma unroll
            for (int r = 0; r < NB; ++r) {
                float4 a = *reinterpret_cast<const float4*>(sm + TM_CAT + r * 384 + k);
                acc0[r] += a.x * w0a + a.y * w1a + a.z * w2a + a.w * w3a;
                acc1[r] += a.x * w0b + a.y * w1b + a.z * w2b + a.w * w3b;
            }
        }
        #pragma unroll
        for (int r = 0; r < NB; ++r) {
            sm[TM_H1 + r * 512 + j]       = sigm(acc0[r]);
            sm[TM_H1 + r * 512 + j + 256] = sigm(acc1[r]);
        }
    }
    __syncthreads();

    // Phase C: g2 = sigmoid(g1 @ dw2 + db2)  512 -> 256
    {
        const int j = tid;
        float acc[NB];
        float bj = __ldg(&db2[j]);
        #pragma unroll
        for (int r = 0; r < NB; ++r) acc[r] = bj;
        #pragma unroll 4
        for (int k = 0; k < 512; k += 4) {
            float w0 = __ldg(&dw2[(k + 0) * 256 + j]);
            float w1 = __ldg(&dw2[(k + 1) * 256 + j]);
            float w2 = __ldg(&dw2[(k + 2) * 256 + j]);
            float w3 = __ldg(&dw2[(k + 3) * 256 + j]);
            #pragma unroll
            for (int r = 0; r < NB; ++r) {
                float4 a = *reinterpret_cast<const float4*>(sm + TM_H1 + r * 512 + k);
                acc[r] += a.x * w0 + a.y * w1 + a.z * w2 + a.w * w3;
            }
        }
        #pragma unroll
        for (int r = 0; r < NB; ++r)
            sm[TM_H2 + r * 256 + j] = sigm(acc[r]);
    }
    __syncthreads();

    // Phase D: g3 = sigmoid(g2 @ dw3 + db3)  256 -> 128
    {
        const int j = tid & 127;
        const int rbase = (tid >> 7) * 2;
        float acc[2];
        float bj = __ldg(&db3[j]);
        acc[0] = bj; acc[1] = bj;
        #pragma unroll 4
        for (int k = 0; k < 256; k += 4) {
            float w0 = __ldg(&dw3[(k + 0) * 128 + j]);
            float w1 = __ldg(&dw3[(k + 1) * 128 + j]);
            float w2 = __ldg(&dw3[(k + 2) * 128 + j]);
            float w3 = __ldg(&dw3[(k + 3) * 128 + j]);
            #pragma unroll
            for (int i = 0; i < 2; ++i) {
                float4 a = *reinterpret_cast<const float4*>(sm + TM_H2 + (rbase + i) * 256 + k);
                acc[i] += a.x * w0 + a.y * w1 + a.z * w2 + a.w * w3;
            }
        }
        #pragma unroll
        for (int i = 0; i < 2; ++i)
            sm[TM_H3 + (rbase + i) * 128 + j] = sigm(acc[i]);
    }
    __syncthreads();

    // Phase E: out = g3 . fw + fb + item_bias  (warps 0-3, one row each)
    {
        const int wid  = tid >> 5;
        const int lane = tid & 31;
        if (wid < NB) {
            float v = 0.0f;
            #pragma unroll
            for (int q = 0; q < 4; ++q)
                v += sm[TM_H3 + wid * 128 + lane + 32 * q] * __ldg(&fw[lane + 32 * q]);
            #pragma unroll
            for (int m = 16; m > 0; m >>= 1) v += __shfl_xor_sync(0xffffffffu, v, m);
            if (lane == 0) {
                int b = b0 + wid;
                out[b] = v + __ldg(&fb[0]) + __ldg(&item_bias_tab[item_id[b]]);
            }
        }
    }
}

// ============================================================================
extern "C" void kernel_launch(void* const* d_in, const int* in_sizes, int n_in,
                              void* d_out, int out_size)
{
    const int*   in_item_id    = (const int*)  d_in[0];
    const int*   item_id       = (const int*)  d_in[1];
    const float* item_emb      = (const float*)d_in[2];
    const float* item_bias_tab = (const float*)d_in[3];
    const float* aw1 = (const float*)d_in[4];
    const float* ab1 = (const float*)d_in[5];
    const float* aw2 = (const float*)d_in[6];
    const float* ab2 = (const float*)d_in[7];
    const float* afw = (const float*)d_in[8];
    const float* afb = (const float*)d_in[9];
    const float* nw  = (const float*)d_in[10];
    const float* nb  = (const float*)d_in[11];
    const float* dw1 = (const float*)d_in[12];
    const float* db1 = (const float*)d_in[13];
    const float* dw2 = (const float*)d_in[14];
    const float* db2 = (const float*)d_in[15];
    const float* dw3 = (const float*)d_in[16];
    const float* db3 = (const float*)d_in[17];
    const float* fw  = (const float*)d_in[18];
    const float* fb  = (const float*)d_in[19];
    float* out = (float*)d_out;

    cudaFuncSetAttribute(din_attention_mma,
                         cudaFuncAttributeMaxDynamicSharedMemorySize, SMEM_BYTES);
    cudaFuncSetAttribute(mlp_tail_kernel,
                         cudaFuncAttributeMaxDynamicSharedMemorySize,
                         (int)(TM_TOT * sizeof(float)));

    cvec_kernel<<<BB / 16, 512>>>(item_id, item_emb, aw1, ab1);
    din_attention_mma<<<BB, 256, SMEM_BYTES>>>(in_item_id, item_id, item_emb,
                                               aw1, aw2, ab2, afw, afb);
    mlp_tail_kernel<<<BB / NB, 256, TM_TOT * sizeof(float)>>>(
        item_id, item_emb, nw, nb, dw1, db1, dw2, db2, dw3, db3,
        fw, fb, item_bias_tab, out);
}

// round 8
// speedup vs baseline: 2.9373x; 1.1461x over previous
#include <cuda_runtime.h>
#include <cuda_fp16.h>
#include <cstdint>

// ============================================================================
// DIN scorer R7: fp16 2-term split MMAs (A = hi+lo exact, B = single fp16
// plane). 33% fewer MMA instructions than R6's bf16 3-term; B-plane LDS and
// smem halved. Error ~eps_fp16/sqrt(3) per GEMM elem -> ~1e-5 final rel_err.
// ============================================================================

#define BB 2048
#define LL 200

__device__ float g_attn[BB * 128];
__device__ float g_cvec[BB * 128];

__device__ __forceinline__ float sigm(float x) {
    return __fdividef(1.0f, 1.0f + __expf(-x));
}

// fp16 hi/lo split of two floats, packed low-first into half2 words
__device__ __forceinline__ void split2h(float a, float b, uint32_t& hi, uint32_t& lo) {
    __half ah = __float2half_rn(a);
    __half bh = __float2half_rn(b);
    __half al = __float2half_rn(a - __half2float(ah));
    __half bl = __float2half_rn(b - __half2float(bh));
    hi = ((uint32_t)__half_as_ushort(bh) << 16) | (uint32_t)__half_as_ushort(ah);
    lo = ((uint32_t)__half_as_ushort(bl) << 16) | (uint32_t)__half_as_ushort(al);
}
// single-plane fp16 quantization of two floats
__device__ __forceinline__ uint32_t pack2h(float a, float b) {
    return ((uint32_t)__half_as_ushort(__float2half_rn(b)) << 16)
         |  (uint32_t)__half_as_ushort(__float2half_rn(a));
}

// m16n8k16 fp16 MMA, fp32 accumulate (in-place C)
__device__ __forceinline__ void mma_f16(float* c, uint32_t a0, uint32_t a1,
                                        uint32_t a2, uint32_t a3,
                                        uint32_t b0, uint32_t b1) {
    asm("mma.sync.aligned.m16n8k16.row.col.f32.f16.f16.f32 "
        "{%0,%1,%2,%3}, {%4,%5,%6,%7}, {%8,%9}, {%0,%1,%2,%3};"
        : "+f"(c[0]), "+f"(c[1]), "+f"(c[2]), "+f"(c[3])
        : "r"(a0), "r"(a1), "r"(a2), "r"(a3), "r"(b0), "r"(b1));
}

__device__ __forceinline__ int pidx(int row, int pair) {
    return row * 64 + (pair ^ ((row & 7) << 2));
}

// ============================================================================
// cvec_kernel: unchanged from R6 (11.9us)
// ============================================================================
__global__ __launch_bounds__(512, 2)
void cvec_kernel(const int*   __restrict__ item_id,
                 const float* __restrict__ item_emb,
                 const float* __restrict__ aw1,
                 const float* __restrict__ ab1)
{
    __shared__ float tT[128 * 16];
    __shared__ float part[4 * 16 * 128];
    const int b0  = blockIdx.x * 16;
    const int tid = threadIdx.x;

    for (int e = tid; e < 128 * 16; e += 512) {
        int k = e >> 4, bb = e & 15;
        long id = (long)__ldg(&item_id[b0 + bb]);
        tT[e] = __ldg(&item_emb[id * 128 + k]);
    }
    __syncthreads();

    const int j  = tid & 127;
    const int kq = tid >> 7;
    float acc[16];
    #pragma unroll
    for (int r = 0; r < 16; ++r) acc[r] = 0.0f;

    #pragma unroll 8
    for (int kk = 0; kk < 32; ++kk) {
        int k = kq * 32 + kk;
        float w = __ldg(&aw1[k * 128 + j]) + __ldg(&aw1[(256 + k) * 128 + j]);
        const float4* tp = reinterpret_cast<const float4*>(tT + k * 16);
        #pragma unroll
        for (int q = 0; q < 4; ++q) {
            float4 tv = tp[q];
            acc[q * 4 + 0] += tv.x * w;
            acc[q * 4 + 1] += tv.y * w;
            acc[q * 4 + 2] += tv.z * w;
            acc[q * 4 + 3] += tv.w * w;
        }
    }
    #pragma unroll
    for (int r = 0; r < 16; ++r)
        part[(kq * 16 + r) * 128 + j] = acc[r];
    __syncthreads();

    for (int e = tid; e < 16 * 128; e += 512) {
        int bb = e >> 7, jj = e & 127;
        float s = part[(0 * 16 + bb) * 128 + jj] + part[(1 * 16 + bb) * 128 + jj]
                + part[(2 * 16 + bb) * 128 + jj] + part[(3 * 16 + bb) * 128 + jj]
                + __ldg(&ab1[jj]);
        g_cvec[(b0 + bb) * 128 + jj] = s;
    }
}

// ---- smem byte offsets (din) ----
#define OFF_SA0_HI  0         // chunk0 seq [128][64] b32-pairs (fp16 hi)
#define OFF_SA0_LO  32768
#define OFF_SA1_HI  65536     // chunk1 seq (80-row alloc, 72 used)
#define OFF_SA1_LO  86016
#define OFF_B1      106496    // Mb   [n=128][kpair=64] fp16 (single plane)
#define OFF_B2      139264    // aw2  [n=64][kpair=64]  fp16 (single plane)
#define OFF_T       155648
#define OFF_CVEC    156160
#define OFF_SCORE   156672
#define OFF_AB2     157184
#define OFF_AFW     157440
#define OFF_RED     157696
#define SMEM_BYTES  158208

template<int CR>
__device__ __forceinline__ void gather_chunk(char* smem, int offHI, int offLO,
                                             const int* __restrict__ ids,
                                             const float* __restrict__ item_emb,
                                             int tid)
{
    uint32_t* dHI = (uint32_t*)(smem + offHI);
    uint32_t* dLO = (uint32_t*)(smem + offLO);
    constexpr int NIT = CR * 32 / 256;
    int idv[NIT];
    #pragma unroll
    for (int i = 0; i < NIT; ++i)
        idv[i] = __ldg(&ids[(tid + i * 256) >> 5]);
    #pragma unroll
    for (int i = 0; i < NIT; ++i) {
        int e = tid + i * 256, row = e >> 5, q = e & 31;
        float4 v = __ldg(reinterpret_cast<const float4*>(item_emb + (long)idv[i] * 128) + q);
        uint32_t h0, l0, h1, l1;
        split2h(v.x, v.y, h0, l0);
        split2h(v.z, v.w, h1, l1);
        int a = pidx(row, q * 2);
        *(uint2*)(dHI + a) = make_uint2(h0, h1);
        *(uint2*)(dLO + a) = make_uint2(l0, l1);
    }
}

template<int CR>
__device__ __forceinline__ void compute_chunk(char* smem, int offHI, int offLO,
                                              const int* __restrict__ ids,
                                              float afb0, float& attnReg,
                                              int tid, int wid, int g, int tg, int sx,
                                              int rA, int dAt, int half)
{
    uint32_t* saHI = (uint32_t*)(smem + offHI);
    uint32_t* saLO = (uint32_t*)(smem + offLO);
    uint32_t* b1P  = (uint32_t*)(smem + OFF_B1);
    uint32_t* b2P  = (uint32_t*)(smem + OFF_B2);
    float* cvec   = (float*)(smem + OFF_CVEC);
    float* scoreS = (float*)(smem + OFF_SCORE);
    float* ab2S   = (float*)(smem + OFF_AB2);
    float* afwS   = (float*)(smem + OFF_AFW);

    const bool act = (wid * 16 < CR);

    uint32_t hT_hi[16], hT_lo[16], hB_hi[16], hB_lo[16];

    if (act) {
        // ===== GEMM1: D1 = s @ Mb  (A = hi+lo fp16, B = single fp16) =====
        float acc[16][4];
        #pragma unroll
        for (int nt = 0; nt < 16; ++nt)
            #pragma unroll
            for (int i = 0; i < 4; ++i) acc[nt][i] = 0.0f;

        const int rTop = rA * 64, rBot = (rA + 8) * 64;
        #pragma unroll
        for (int ks = 0; ks < 8; ++ks) {
            const int p0 = (8 * ks + tg) ^ sx;
            const int p1 = p0 ^ 4;
            uint32_t ah0 = saHI[rTop + p0], ah1 = saHI[rBot + p0];
            uint32_t ah2 = saHI[rTop + p1], ah3 = saHI[rBot + p1];
            uint32_t al0 = saLO[rTop + p0], al1 = saLO[rBot + p0];
            uint32_t al2 = saLO[rTop + p1], al3 = saLO[rBot + p1];
            #pragma unroll
            for (int nt = 0; nt < 16; ++nt) {
                const int nb = (8 * nt + g) * 64;
                uint32_t b0 = b1P[nb + p0], b1 = b1P[nb + p1];
                mma_f16(acc[nt], ah0, ah1, ah2, ah3, b0, b1);
                mma_f16(acc[nt], al0, al1, al2, al3, b0, b1);
            }
        }
        #pragma unroll
        for (int nt = 0; nt < 16; ++nt) {
            const int c0 = 8 * nt + 2 * tg;
            float t0 = sigm(acc[nt][0] + cvec[c0]);
            float t1 = sigm(acc[nt][1] + cvec[c0 + 1]);
            float b0 = sigm(acc[nt][2] + cvec[c0]);
            float b1 = sigm(acc[nt][3] + cvec[c0 + 1]);
            split2h(t0, t1, hT_hi[nt], hT_lo[nt]);
            split2h(b0, b1, hB_hi[nt], hB_lo[nt]);
        }
    }

    float acc2[8][4];
    #pragma unroll
    for (int nt = 0; nt < 8; ++nt)
        #pragma unroll
        for (int i = 0; i < 4; ++i) acc2[nt][i] = 0.0f;

    if (act) {
        // ===== GEMM2: D2 = h1 @ aw2 (A = reg hi+lo, B = single fp16) =====
        #pragma unroll
        for (int ks = 0; ks < 8; ++ks) {
            const int p0 = (8 * ks + tg) ^ sx;
            const int p1 = p0 ^ 4;
            uint32_t ah0 = hT_hi[2 * ks],     ah1 = hB_hi[2 * ks];
            uint32_t ah2 = hT_hi[2 * ks + 1], ah3 = hB_hi[2 * ks + 1];
            uint32_t al0 = hT_lo[2 * ks],     al1 = hB_lo[2 * ks];
            uint32_t al2 = hT_lo[2 * ks + 1], al3 = hB_lo[2 * ks + 1];
            #pragma unroll
            for (int nt = 0; nt < 8; ++nt) {
                const int nb = (8 * nt + g) * 64;
                uint32_t b0 = b2P[nb + p0], b1 = b2P[nb + p1];
                mma_f16(acc2[nt], ah0, ah1, ah2, ah3, b0, b1);
                mma_f16(acc2[nt], al0, al1, al2, al3, b0, b1);
            }
        }
    }

    {
        float vT = 0.0f, vB = 0.0f;
        #pragma unroll
        for (int nt = 0; nt < 8; ++nt) {
            const int c0 = 8 * nt + 2 * tg;
            vT += sigm(acc2[nt][0] + ab2S[c0])     * afwS[c0];
            vT += sigm(acc2[nt][1] + ab2S[c0 + 1]) * afwS[c0 + 1];
            vB += sigm(acc2[nt][2] + ab2S[c0])     * afwS[c0];
            vB += sigm(acc2[nt][3] + ab2S[c0 + 1]) * afwS[c0 + 1];
        }
        vT += __shfl_xor_sync(0xffffffffu, vT, 1);
        vT += __shfl_xor_sync(0xffffffffu, vT, 2);
        vB += __shfl_xor_sync(0xffffffffu, vB, 1);
        vB += __shfl_xor_sync(0xffffffffu, vB, 2);
        if (tg == 0) {
            int r0 = rA, r1 = rA + 8;
            float s0 = 0.0f, s1 = 0.0f;
            if (act && r0 < CR) {
                int id = __ldg(&ids[r0]);
                s0 = (id == 0) ? 0.0f : (vT + afb0);
            }
            if (act && r1 < CR) {
                int id = __ldg(&ids[r1]);
                s1 = (id == 0) ? 0.0f : (vB + afb0);
            }
            scoreS[r0] = s0;
            if (r1 < 128) scoreS[r1] = s1;
        }
    }
    __syncthreads();

    {
        const int h0 = half * (CR >> 1);
        const int h1 = h0 + (CR >> 1);
        const int pr = dAt >> 1, sel = (dAt & 1) * 16;
        for (int row = h0; row < h1; ++row) {
            float sc = scoreS[row];
            int a = pidx(row, pr);
            uint32_t whi = saHI[a], wlo = saLO[a];
            float s = __half2float(__ushort_as_half((unsigned short)(whi >> sel)))
                    + __half2float(__ushort_as_half((unsigned short)(wlo >> sel)));
            attnReg += sc * s;
        }
    }
    __syncthreads();
}

__global__ __launch_bounds__(256, 1)
void din_attention_mma(const int*   __restrict__ in_item_id,
                       const int*   __restrict__ item_id,
                       const float* __restrict__ item_emb,
                       const float* __restrict__ aw1,
                       const float* __restrict__ aw2,
                       const float* __restrict__ ab2,
                       const float* __restrict__ afw,
                       const float* __restrict__ afb)
{
    extern __shared__ char smem[];
    uint32_t* b1P = (uint32_t*)(smem + OFF_B1);
    uint32_t* b2P = (uint32_t*)(smem + OFF_B2);
    float* tS     = (float*)(smem + OFF_T);
    float* cvec   = (float*)(smem + OFF_CVEC);
    float* ab2S   = (float*)(smem + OFF_AB2);
    float* afwS   = (float*)(smem + OFF_AFW);
    float* redS   = (float*)(smem + OFF_RED);

    const int tid = threadIdx.x, wid = tid >> 5, lid = tid & 31;
    const int b = blockIdx.x;
    const int g  = lid >> 2;
    const int tg = lid & 3;
    const int sx = g << 2;

    if (tid < 128) {
        long id = (long)item_id[b];
        tS[tid]   = item_emb[id * 128 + tid];
        cvec[tid] = g_cvec[b * 128 + tid];
    }
    if (tid < 64) { ab2S[tid] = __ldg(&ab2[tid]); afwS[tid] = __ldg(&afw[tid]); }
    __syncthreads();

    // ---- single latency region: chunk0 gather + B1 build + B2 build ----
    gather_chunk<128>(smem, OFF_SA0_HI, OFF_SA0_LO,
                      in_item_id + b * LL, item_emb, tid);

    for (int e = tid; e < 128 * 64; e += 256) {
        int j = e & 127, kp = e >> 7;
        int k0 = kp * 2, k1 = k0 + 1;
        float v0 = tS[k0] * __ldg(&aw1[(128 + k0) * 128 + j]) - __ldg(&aw1[(256 + k0) * 128 + j]);
        float v1 = tS[k1] * __ldg(&aw1[(128 + k1) * 128 + j]) - __ldg(&aw1[(256 + k1) * 128 + j]);
        b1P[pidx(j, kp)] = pack2h(v0, v1);
    }
    for (int e = tid; e < 64 * 64; e += 256) {
        int n = e & 63, kp = e >> 6;
        float v0 = __ldg(&aw2[(kp * 2) * 64 + n]);
        float v1 = __ldg(&aw2[(kp * 2 + 1) * 64 + n]);
        b2P[pidx(n, kp)] = pack2h(v0, v1);
    }
    const float afb0 = __ldg(&afb[0]);
    __syncthreads();

    // ---- prefetch chunk1 gather: LDGs fly during chunk0 compute ----
    gather_chunk<72>(smem, OFF_SA1_HI, OFF_SA1_LO,
                     in_item_id + b * LL + 128, item_emb, tid);

    const int rA   = wid * 16 + g;
    const int dAt  = tid & 127;
    const int half = tid >> 7;
    float attnReg = 0.0f;

    compute_chunk<128>(smem, OFF_SA0_HI, OFF_SA0_LO, in_item_id + b * LL,
                       afb0, attnReg, tid, wid, g, tg, sx, rA, dAt, half);
    compute_chunk<72>(smem, OFF_SA1_HI, OFF_SA1_LO, in_item_id + b * LL + 128,
                      afb0, attnReg, tid, wid, g, tg, sx, rA, dAt, half);

    if (tid >= 128) redS[dAt] = attnReg;
    __syncthreads();
    if (tid < 128) g_attn[b * 128 + tid] = attnReg + redS[tid];
}

// ============================================================================
// Fused MLP tail: unchanged from R6 (4 batches/CTA, 4 CTAs/SM).
// ============================================================================
#define NB 4
#define TM_ATTN 0
#define TM_T    (NB*128)
#define TM_CAT  (2*NB*128)
#define TM_H1   (TM_CAT + NB*384)
#define TM_H2   (TM_H1 + NB*512)
#define TM_H3   (TM_H2 + NB*256)
#define TM_TOT  (TM_H3 + NB*128)   // 6144 floats = 24576 B

__global__ __launch_bounds__(256, 4)
void mlp_tail_kernel(const int*   __restrict__ item_id,
                     const float* __restrict__ item_emb,
                     const float* __restrict__ nw,
                     const float* __restrict__ nb,
                     const float* __restrict__ dw1,
                     const float* __restrict__ db1,
                     const float* __restrict__ dw2,
                     const float* __restrict__ db2,
                     const float* __restrict__ dw3,
                     const float* __restrict__ db3,
                     const float* __restrict__ fw,
                     const float* __restrict__ fb,
                     const float* __restrict__ item_bias_tab,
                     float*       __restrict__ out)
{
    extern __shared__ float sm[];
    const int b0  = blockIdx.x * NB;
    const int tid = threadIdx.x;

    for (int e = tid; e < NB * 128; e += 256) {
        int bb = e >> 7, j = e & 127;
        sm[TM_ATTN + e] = g_attn[(b0 + bb) * 128 + j];
        long id = (long)__ldg(&item_id[b0 + bb]);
        sm[TM_T + e]    = __ldg(&item_emb[id * 128 + j]);
    }
    __syncthreads();

    // Phase A
    {
        const int j = tid & 127;
        const int rbase = (tid >> 7) * 2;
        float acc[2];
        float nbj = __ldg(&nb[j]);
        acc[0] = nbj; acc[1] = nbj;
        #pragma unroll 4
        for (int k = 0; k < 128; k += 4) {
            float w0 = __ldg(&nw[(k + 0) * 128 + j]);
            float w1 = __ldg(&nw[(k + 1) * 128 + j]);
            float w2 = __ldg(&nw[(k + 2) * 128 + j]);
            float w3 = __ldg(&nw[(k + 3) * 128 + j]);
            #pragma unroll
            for (int i = 0; i < 2; ++i) {
                float4 a = *reinterpret_cast<const float4*>(sm + TM_ATTN + (rbase + i) * 128 + k);
                acc[i] += a.x * w0 + a.y * w1 + a.z * w2 + a.w * w3;
            }
        }
        #pragma unroll
        for (int i = 0; i < 2; ++i) {
            int r = rbase + i;
            float a2 = acc[i];
            float t  = sm[TM_T + r * 128 + j];
            sm[TM_CAT + r * 384 + j]       = a2;
            sm[TM_CAT + r * 384 + 128 + j] = t;
            sm[TM_CAT + r * 384 + 256 + j] = t * a2;
        }
    }
    __syncthreads();

    // Phase B: 384 -> 512
    {
        const int j = tid;
        float acc0[NB], acc1[NB];
        float bj0 = __ldg(&db1[j]), bj1 = __ldg(&db1[j + 256]);
        #pragma unroll
        for (int r = 0; r < NB; ++r) { acc0[r] = bj0; acc1[r] = bj1; }
        #pragma unroll 4
        for (int k = 0; k < 384; k += 4) {
            float w0a = __ldg(&dw1[(k + 0) * 512 + j]);
            float w1a = __ldg(&dw1[(k + 1) * 512 + j]);
            float w2a = __ldg(&dw1[(k + 2) * 512 + j]);
            float w3a = __ldg(&dw1[(k + 3) * 512 + j]);
            float w0b = __ldg(&dw1[(k + 0) * 512 + j + 256]);
            float w1b = __ldg(&dw1[(k + 1) * 512 + j + 256]);
            float w2b = __ldg(&dw1[(k + 2) * 512 + j + 256]);
            float w3b = __ldg(&dw1[(k + 3) * 512 + j + 256]);
            #pragma unroll
            for (int r = 0; r < NB; ++r) {
                float4 a = *reinterpret_cast<const float4*>(sm + TM_CAT + r * 384 + k);
                acc0[r] += a.x * w0a + a.y * w1a + a.z * w2a + a.w * w3a;
                acc1[r] += a.x * w0b + a.y * w1b + a.z * w2b + a.w * w3b;
            }
        }
        #pragma unroll
        for (int r = 0; r < NB; ++r) {
            sm[TM_H1 + r * 512 + j]       = sigm(acc0[r]);
            sm[TM_H1 + r * 512 + j + 256] = sigm(acc1[r]);
        }
    }
    __syncthreads();

    // Phase C: 512 -> 256
    {
        const int j = tid;
        float acc[NB];
        float bj = __ldg(&db2[j]);
        #pragma unroll
        for (int r = 0; r < NB; ++r) acc[r] = bj;
        #pragma unroll 4
        for (int k = 0; k < 512; k += 4) {
            float w0 = __ldg(&dw2[(k + 0) * 256 + j]);
            float w1 = __ldg(&dw2[(k + 1) * 256 + j]);
            float w2 = __ldg(&dw2[(k + 2) * 256 + j]);
            float w3 = __ldg(&dw2[(k + 3) * 256 + j]);
            #pragma unroll
            for (int r = 0; r < NB; ++r) {
                float4 a = *reinterpret_cast<const float4*>(sm + TM_H1 + r * 512 + k);
                acc[r] += a.x * w0 + a.y * w1 + a.z * w2 + a.w * w3;
            }
        }
        #pragma unroll
        for (int r = 0; r < NB; ++r)
            sm[TM_H2 + r * 256 + j] = sigm(acc[r]);
    }
    __syncthreads();

    // Phase D: 256 -> 128
    {
        const int j = tid & 127;
        const int rbase = (tid >> 7) * 2;
        float acc[2];
        float bj = __ldg(&db3[j]);
        acc[0] = bj; acc[1] = bj;
        #pragma unroll 4
        for (int k = 0; k < 256; k += 4) {
            float w0 = __ldg(&dw3[(k + 0) * 128 + j]);
            float w1 = __ldg(&dw3[(k + 1) * 128 + j]);
            float w2 = __ldg(&dw3[(k + 2) * 128 + j]);
            float w3 = __ldg(&dw3[(k + 3) * 128 + j]);
            #pragma unroll
            for (int i = 0; i < 2; ++i) {
                float4 a = *reinterpret_cast<const float4*>(sm + TM_H2 + (rbase + i) * 256 + k);
                acc[i] += a.x * w0 + a.y * w1 + a.z * w2 + a.w * w3;
            }
        }
        #pragma unroll
        for (int i = 0; i < 2; ++i)
            sm[TM_H3 + (rbase + i) * 128 + j] = sigm(acc[i]);
    }
    __syncthreads();

    // Phase E
    {
        const int wid  = tid >> 5;
        const int lane = tid & 31;
        if (wid < NB) {
            float v = 0.0f;
            #pragma unroll
            for (int q = 0; q < 4; ++q)
                v += sm[TM_H3 + wid * 128 + lane + 32 * q] * __ldg(&fw[lane + 32 * q]);
            #pragma unroll
            for (int m = 16; m > 0; m >>= 1) v += __shfl_xor_sync(0xffffffffu, v, m);
            if (lane == 0) {
                int b = b0 + wid;
                out[b] = v + __ldg(&fb[0]) + __ldg(&item_bias_tab[item_id[b]]);
            }
        }
    }
}

// ============================================================================
extern "C" void kernel_launch(void* const* d_in, const int* in_sizes, int n_in,
                              void* d_out, int out_size)
{
    const int*   in_item_id    = (const int*)  d_in[0];
    const int*   item_id       = (const int*)  d_in[1];
    const float* item_emb      = (const float*)d_in[2];
    const float* item_bias_tab = (const float*)d_in[3];
    const float* aw1 = (const float*)d_in[4];
    const float* ab1 = (const float*)d_in[5];
    const float* aw2 = (const float*)d_in[6];
    const float* ab2 = (const float*)d_in[7];
    const float* afw = (const float*)d_in[8];
    const float* afb = (const float*)d_in[9];
    const float* nw  = (const float*)d_in[10];
    const float* nb  = (const float*)d_in[11];
    const float* dw1 = (const float*)d_in[12];
    const float* db1 = (const float*)d_in[13];
    const float* dw2 = (const float*)d_in[14];
    const float* db2 = (const float*)d_in[15];
    const float* dw3 = (const float*)d_in[16];
    const float* db3 = (const float*)d_in[17];
    const float* fw  = (const float*)d_in[18];
    const float* fb  = (const float*)d_in[19];
    float* out = (float*)d_out;

    cudaFuncSetAttribute(din_attention_mma,
                         cudaFuncAttributeMaxDynamicSharedMemorySize, SMEM_BYTES);
    cudaFuncSetAttribute(mlp_tail_kernel,
                         cudaFuncAttributeMaxDynamicSharedMemorySize,
                         (int)(TM_TOT * sizeof(float)));

    cvec_kernel<<<BB / 16, 512>>>(item_id, item_emb, aw1, ab1);
    din_attention_mma<<<BB, 256, SMEM_BYTES>>>(in_item_id, item_id, item_emb,
                                               aw1, aw2, ab2, afw, afb);
    mlp_tail_kernel<<<BB / NB, 256, TM_TOT * sizeof(float)>>>(
        item_id, item_emb, nw, nb, dw1, db1, dw2, db2, dw3, db3,
        fw, fb, item_bias_tab, out);
}

// round 9
// speedup vs baseline: 3.3565x; 1.1427x over previous
#include <cuda_runtime.h>
#include <cuda_fp16.h>
#include <cstdint>

// ============================================================================
// DIN scorer R8: single-plane fp16 MMAs in both GEMMs (A lo-plane kept in
// smem only for the exact attn reconstruction). MMA count halved vs R7.
// Evidence-calibrated accuracy: R7 showed B-plane fp16 quantization adds
// ~5e-8 rel_err; A-plane adds the same magnitude -> expect ~2e-7.
// ============================================================================

#define BB 2048
#define LL 200

__device__ float g_attn[BB * 128];
__device__ float g_cvec[BB * 128];

__device__ __forceinline__ float sigm(float x) {
    return __fdividef(1.0f, 1.0f + __expf(-x));
}

// fp16 hi/lo split of two floats, packed low-first into half2 words
__device__ __forceinline__ void split2h(float a, float b, uint32_t& hi, uint32_t& lo) {
    __half ah = __float2half_rn(a);
    __half bh = __float2half_rn(b);
    __half al = __float2half_rn(a - __half2float(ah));
    __half bl = __float2half_rn(b - __half2float(bh));
    hi = ((uint32_t)__half_as_ushort(bh) << 16) | (uint32_t)__half_as_ushort(ah);
    lo = ((uint32_t)__half_as_ushort(bl) << 16) | (uint32_t)__half_as_ushort(al);
}
// single-plane fp16 quantization of two floats
__device__ __forceinline__ uint32_t pack2h(float a, float b) {
    return ((uint32_t)__half_as_ushort(__float2half_rn(b)) << 16)
         |  (uint32_t)__half_as_ushort(__float2half_rn(a));
}

// m16n8k16 fp16 MMA, fp32 accumulate (in-place C)
__device__ __forceinline__ void mma_f16(float* c, uint32_t a0, uint32_t a1,
                                        uint32_t a2, uint32_t a3,
                                        uint32_t b0, uint32_t b1) {
    asm("mma.sync.aligned.m16n8k16.row.col.f32.f16.f16.f32 "
        "{%0,%1,%2,%3}, {%4,%5,%6,%7}, {%8,%9}, {%0,%1,%2,%3};"
        : "+f"(c[0]), "+f"(c[1]), "+f"(c[2]), "+f"(c[3])
        : "r"(a0), "r"(a1), "r"(a2), "r"(a3), "r"(b0), "r"(b1));
}

__device__ __forceinline__ int pidx(int row, int pair) {
    return row * 64 + (pair ^ ((row & 7) << 2));
}

// ============================================================================
// cvec_kernel: unchanged (11.4us)
// ============================================================================
__global__ __launch_bounds__(512, 2)
void cvec_kernel(const int*   __restrict__ item_id,
                 const float* __restrict__ item_emb,
                 const float* __restrict__ aw1,
                 const float* __restrict__ ab1)
{
    __shared__ float tT[128 * 16];
    __shared__ float part[4 * 16 * 128];
    const int b0  = blockIdx.x * 16;
    const int tid = threadIdx.x;

    for (int e = tid; e < 128 * 16; e += 512) {
        int k = e >> 4, bb = e & 15;
        long id = (long)__ldg(&item_id[b0 + bb]);
        tT[e] = __ldg(&item_emb[id * 128 + k]);
    }
    __syncthreads();

    const int j  = tid & 127;
    const int kq = tid >> 7;
    float acc[16];
    #pragma unroll
    for (int r = 0; r < 16; ++r) acc[r] = 0.0f;

    #pragma unroll 8
    for (int kk = 0; kk < 32; ++kk) {
        int k = kq * 32 + kk;
        float w = __ldg(&aw1[k * 128 + j]) + __ldg(&aw1[(256 + k) * 128 + j]);
        const float4* tp = reinterpret_cast<const float4*>(tT + k * 16);
        #pragma unroll
        for (int q = 0; q < 4; ++q) {
            float4 tv = tp[q];
            acc[q * 4 + 0] += tv.x * w;
            acc[q * 4 + 1] += tv.y * w;
            acc[q * 4 + 2] += tv.z * w;
            acc[q * 4 + 3] += tv.w * w;
        }
    }
    #pragma unroll
    for (int r = 0; r < 16; ++r)
        part[(kq * 16 + r) * 128 + j] = acc[r];
    __syncthreads();

    for (int e = tid; e < 16 * 128; e += 512) {
        int bb = e >> 7, jj = e & 127;
        float s = part[(0 * 16 + bb) * 128 + jj] + part[(1 * 16 + bb) * 128 + jj]
                + part[(2 * 16 + bb) * 128 + jj] + part[(3 * 16 + bb) * 128 + jj]
                + __ldg(&ab1[jj]);
        g_cvec[(b0 + bb) * 128 + jj] = s;
    }
}

// ---- smem byte offsets (din) ----
#define OFF_SA0_HI  0         // chunk0 seq [128][64] b32-pairs (fp16 hi)
#define OFF_SA0_LO  32768     // lo plane: attn reconstruction only
#define OFF_SA1_HI  65536
#define OFF_SA1_LO  86016
#define OFF_B1      106496    // Mb   [n=128][kpair=64] fp16
#define OFF_B2      139264    // aw2  [n=64][kpair=64]  fp16
#define OFF_T       155648
#define OFF_CVEC    156160
#define OFF_SCORE   156672
#define OFF_AB2     157184
#define OFF_AFW     157440
#define OFF_RED     157696
#define SMEM_BYTES  158208

template<int CR>
__device__ __forceinline__ void gather_chunk(char* smem, int offHI, int offLO,
                                             const int* __restrict__ ids,
                                             const float* __restrict__ item_emb,
                                             int tid)
{
    uint32_t* dHI = (uint32_t*)(smem + offHI);
    uint32_t* dLO = (uint32_t*)(smem + offLO);
    constexpr int NIT = CR * 32 / 256;
    int idv[NIT];
    #pragma unroll
    for (int i = 0; i < NIT; ++i)
        idv[i] = __ldg(&ids[(tid + i * 256) >> 5]);
    #pragma unroll
    for (int i = 0; i < NIT; ++i) {
        int e = tid + i * 256, row = e >> 5, q = e & 31;
        float4 v = __ldg(reinterpret_cast<const float4*>(item_emb + (long)idv[i] * 128) + q);
        uint32_t h0, l0, h1, l1;
        split2h(v.x, v.y, h0, l0);
        split2h(v.z, v.w, h1, l1);
        int a = pidx(row, q * 2);
        *(uint2*)(dHI + a) = make_uint2(h0, h1);
        *(uint2*)(dLO + a) = make_uint2(l0, l1);
    }
}

template<int CR>
__device__ __forceinline__ void compute_chunk(char* smem, int offHI, int offLO,
                                              const int* __restrict__ ids,
                                              float afb0, float& attnReg,
                                              int tid, int wid, int g, int tg, int sx,
                                              int rA, int dAt, int half)
{
    uint32_t* saHI = (uint32_t*)(smem + offHI);
    uint32_t* saLO = (uint32_t*)(smem + offLO);
    uint32_t* b1P  = (uint32_t*)(smem + OFF_B1);
    uint32_t* b2P  = (uint32_t*)(smem + OFF_B2);
    float* cvec   = (float*)(smem + OFF_CVEC);
    float* scoreS = (float*)(smem + OFF_SCORE);
    float* ab2S   = (float*)(smem + OFF_AB2);
    float* afwS   = (float*)(smem + OFF_AFW);

    const bool act = (wid * 16 < CR);

    uint32_t hT[16], hB[16];    // h1 fragments, single fp16 plane

    if (act) {
        // ===== GEMM1: D1 = s @ Mb  (single-plane fp16, fp32 accum) =====
        float acc[16][4];
        #pragma unroll
        for (int nt = 0; nt < 16; ++nt)
            #pragma unroll
            for (int i = 0; i < 4; ++i) acc[nt][i] = 0.0f;

        const int rTop = rA * 64, rBot = (rA + 8) * 64;
        #pragma unroll
        for (int ks = 0; ks < 8; ++ks) {
            const int p0 = (8 * ks + tg) ^ sx;
            const int p1 = p0 ^ 4;
            uint32_t ah0 = saHI[rTop + p0], ah1 = saHI[rBot + p0];
            uint32_t ah2 = saHI[rTop + p1], ah3 = saHI[rBot + p1];
            #pragma unroll
            for (int nt = 0; nt < 16; ++nt) {
                const int nb = (8 * nt + g) * 64;
                mma_f16(acc[nt], ah0, ah1, ah2, ah3, b1P[nb + p0], b1P[nb + p1]);
            }
        }
        #pragma unroll
        for (int nt = 0; nt < 16; ++nt) {
            const int c0 = 8 * nt + 2 * tg;
            float t0 = sigm(acc[nt][0] + cvec[c0]);
            float t1 = sigm(acc[nt][1] + cvec[c0 + 1]);
            float b0 = sigm(acc[nt][2] + cvec[c0]);
            float b1 = sigm(acc[nt][3] + cvec[c0 + 1]);
            hT[nt] = pack2h(t0, t1);
            hB[nt] = pack2h(b0, b1);
        }
    }

    float acc2[8][4];
    #pragma unroll
    for (int nt = 0; nt < 8; ++nt)
        #pragma unroll
        for (int i = 0; i < 4; ++i) acc2[nt][i] = 0.0f;

    if (act) {
        // ===== GEMM2: D2 = h1 @ aw2 (single-plane fp16) =====
        #pragma unroll
        for (int ks = 0; ks < 8; ++ks) {
            const int p0 = (8 * ks + tg) ^ sx;
            const int p1 = p0 ^ 4;
            uint32_t ah0 = hT[2 * ks],     ah1 = hB[2 * ks];
            uint32_t ah2 = hT[2 * ks + 1], ah3 = hB[2 * ks + 1];
            #pragma unroll
            for (int nt = 0; nt < 8; ++nt) {
                const int nb = (8 * nt + g) * 64;
                mma_f16(acc2[nt], ah0, ah1, ah2, ah3, b2P[nb + p0], b2P[nb + p1]);
            }
        }
    }

    {
        float vT = 0.0f, vB = 0.0f;
        #pragma unroll
        for (int nt = 0; nt < 8; ++nt) {
            const int c0 = 8 * nt + 2 * tg;
            vT += sigm(acc2[nt][0] + ab2S[c0])     * afwS[c0];
            vT += sigm(acc2[nt][1] + ab2S[c0 + 1]) * afwS[c0 + 1];
            vB += sigm(acc2[nt][2] + ab2S[c0])     * afwS[c0];
            vB += sigm(acc2[nt][3] + ab2S[c0 + 1]) * afwS[c0 + 1];
        }
        vT += __shfl_xor_sync(0xffffffffu, vT, 1);
        vT += __shfl_xor_sync(0xffffffffu, vT, 2);
        vB += __shfl_xor_sync(0xffffffffu, vB, 1);
        vB += __shfl_xor_sync(0xffffffffu, vB, 2);
        if (tg == 0) {
            int r0 = rA, r1 = rA + 8;
            float s0 = 0.0f, s1 = 0.0f;
            if (act && r0 < CR) {
                int id = __ldg(&ids[r0]);
                s0 = (id == 0) ? 0.0f : (vT + afb0);
            }
            if (act && r1 < CR) {
                int id = __ldg(&ids[r1]);
                s1 = (id == 0) ? 0.0f : (vB + afb0);
            }
            scoreS[r0] = s0;
            if (r1 < 128) scoreS[r1] = s1;
        }
    }
    __syncthreads();

    // attn epilogue: exact hi+lo reconstruction of s
    {
        const int h0 = half * (CR >> 1);
        const int h1 = h0 + (CR >> 1);
        const int pr = dAt >> 1, sel = (dAt & 1) * 16;
        for (int row = h0; row < h1; ++row) {
            float sc = scoreS[row];
            int a = pidx(row, pr);
            uint32_t whi = saHI[a], wlo = saLO[a];
            float s = __half2float(__ushort_as_half((unsigned short)(whi >> sel)))
                    + __half2float(__ushort_as_half((unsigned short)(wlo >> sel)));
            attnReg += sc * s;
        }
    }
    __syncthreads();
}

__global__ __launch_bounds__(256, 1)
void din_attention_mma(const int*   __restrict__ in_item_id,
                       const int*   __restrict__ item_id,
                       const float* __restrict__ item_emb,
                       const float* __restrict__ aw1,
                       const float* __restrict__ aw2,
                       const float* __restrict__ ab2,
                       const float* __restrict__ afw,
                       const float* __restrict__ afb)
{
    extern __shared__ char smem[];
    uint32_t* b1P = (uint32_t*)(smem + OFF_B1);
    uint32_t* b2P = (uint32_t*)(smem + OFF_B2);
    float* tS     = (float*)(smem + OFF_T);
    float* cvec   = (float*)(smem + OFF_CVEC);
    float* ab2S   = (float*)(smem + OFF_AB2);
    float* afwS   = (float*)(smem + OFF_AFW);
    float* redS   = (float*)(smem + OFF_RED);

    const int tid = threadIdx.x, wid = tid >> 5, lid = tid & 31;
    const int b = blockIdx.x;
    const int g  = lid >> 2;
    const int tg = lid & 3;
    const int sx = g << 2;

    if (tid < 128) {
        long id = (long)item_id[b];
        tS[tid]   = item_emb[id * 128 + tid];
        cvec[tid] = g_cvec[b * 128 + tid];
    }
    if (tid < 64) { ab2S[tid] = __ldg(&ab2[tid]); afwS[tid] = __ldg(&afw[tid]); }
    __syncthreads();

    // ---- single latency region: chunk0 gather + B1 build + B2 build ----
    gather_chunk<128>(smem, OFF_SA0_HI, OFF_SA0_LO,
                      in_item_id + b * LL, item_emb, tid);

    for (int e = tid; e < 128 * 64; e += 256) {
        int j = e & 127, kp = e >> 7;
        int k0 = kp * 2, k1 = k0 + 1;
        float v0 = tS[k0] * __ldg(&aw1[(128 + k0) * 128 + j]) - __ldg(&aw1[(256 + k0) * 128 + j]);
        float v1 = tS[k1] * __ldg(&aw1[(128 + k1) * 128 + j]) - __ldg(&aw1[(256 + k1) * 128 + j]);
        b1P[pidx(j, kp)] = pack2h(v0, v1);
    }
    for (int e = tid; e < 64 * 64; e += 256) {
        int n = e & 63, kp = e >> 6;
        float v0 = __ldg(&aw2[(kp * 2) * 64 + n]);
        float v1 = __ldg(&aw2[(kp * 2 + 1) * 64 + n]);
        b2P[pidx(n, kp)] = pack2h(v0, v1);
    }
    const float afb0 = __ldg(&afb[0]);
    __syncthreads();

    // ---- prefetch chunk1 gather: LDGs fly during chunk0 compute ----
    gather_chunk<72>(smem, OFF_SA1_HI, OFF_SA1_LO,
                     in_item_id + b * LL + 128, item_emb, tid);

    const int rA   = wid * 16 + g;
    const int dAt  = tid & 127;
    const int half = tid >> 7;
    float attnReg = 0.0f;

    compute_chunk<128>(smem, OFF_SA0_HI, OFF_SA0_LO, in_item_id + b * LL,
                       afb0, attnReg, tid, wid, g, tg, sx, rA, dAt, half);
    compute_chunk<72>(smem, OFF_SA1_HI, OFF_SA1_LO, in_item_id + b * LL + 128,
                      afb0, attnReg, tid, wid, g, tg, sx, rA, dAt, half);

    if (tid >= 128) redS[dAt] = attnReg;
    __syncthreads();
    if (tid < 128) g_attn[b * 128 + tid] = attnReg + redS[tid];
}

// ============================================================================
// Fused MLP tail: unchanged (4 batches/CTA, 4 CTAs/SM).
// ============================================================================
#define NB 4
#define TM_ATTN 0
#define TM_T    (NB*128)
#define TM_CAT  (2*NB*128)
#define TM_H1   (TM_CAT + NB*384)
#define TM_H2   (TM_H1 + NB*512)
#define TM_H3   (TM_H2 + NB*256)
#define TM_TOT  (TM_H3 + NB*128)   // 6144 floats = 24576 B

__global__ __launch_bounds__(256, 4)
void mlp_tail_kernel(const int*   __restrict__ item_id,
                     const float* __restrict__ item_emb,
                     const float* __restrict__ nw,
                     const float* __restrict__ nb,
                     const float* __restrict__ dw1,
                     const float* __restrict__ db1,
                     const float* __restrict__ dw2,
                     const float* __restrict__ db2,
                     const float* __restrict__ dw3,
                     const float* __restrict__ db3,
                     const float* __restrict__ fw,
                     const float* __restrict__ fb,
                     const float* __restrict__ item_bias_tab,
                     float*       __restrict__ out)
{
    extern __shared__ float sm[];
    const int b0  = blockIdx.x * NB;
    const int tid = threadIdx.x;

    for (int e = tid; e < NB * 128; e += 256) {
        int bb = e >> 7, j = e & 127;
        sm[TM_ATTN + e] = g_attn[(b0 + bb) * 128 + j];
        long id = (long)__ldg(&item_id[b0 + bb]);
        sm[TM_T + e]    = __ldg(&item_emb[id * 128 + j]);
    }
    __syncthreads();

    // Phase A
    {
        const int j = tid & 127;
        const int rbase = (tid >> 7) * 2;
        float acc[2];
        float nbj = __ldg(&nb[j]);
        acc[0] = nbj; acc[1] = nbj;
        #pragma unroll 4
        for (int k = 0; k < 128; k += 4) {
            float w0 = __ldg(&nw[(k + 0) * 128 + j]);
            float w1 = __ldg(&nw[(k + 1) * 128 + j]);
            float w2 = __ldg(&nw[(k + 2) * 128 + j]);
            float w3 = __ldg(&nw[(k + 3) * 128 + j]);
            #pragma unroll
            for (int i = 0; i < 2; ++i) {
                float4 a = *reinterpret_cast<const float4*>(sm + TM_ATTN + (rbase + i) * 128 + k);
                acc[i] += a.x * w0 + a.y * w1 + a.z * w2 + a.w * w3;
            }
        }
        #pragma unroll
        for (int i = 0; i < 2; ++i) {
            int r = rbase + i;
            float a2 = acc[i];
            float t  = sm[TM_T + r * 128 + j];
            sm[TM_CAT + r * 384 + j]       = a2;
            sm[TM_CAT + r * 384 + 128 + j] = t;
            sm[TM_CAT + r * 384 + 256 + j] = t * a2;
        }
    }
    __syncthreads();

    // Phase B: 384 -> 512
    {
        const int j = tid;
        float acc0[NB], acc1[NB];
        float bj0 = __ldg(&db1[j]), bj1 = __ldg(&db1[j + 256]);
        #pragma unroll
        for (int r = 0; r < NB; ++r) { acc0[r] = bj0; acc1[r] = bj1; }
        #pragma unroll 4
        for (int k = 0; k < 384; k += 4) {
            float w0a = __ldg(&dw1[(k + 0) * 512 + j]);
            float w1a = __ldg(&dw1[(k + 1) * 512 + j]);
            float w2a = __ldg(&dw1[(k + 2) * 512 + j]);
            float w3a = __ldg(&dw1[(k + 3) * 512 + j]);
            float w0b = __ldg(&dw1[(k + 0) * 512 + j + 256]);
            float w1b = __ldg(&dw1[(k + 1) * 512 + j + 256]);
            float w2b = __ldg(&dw1[(k + 2) * 512 + j + 256]);
            float w3b = __ldg(&dw1[(k + 3) * 512 + j + 256]);
            #pragma unroll
            for (int r = 0; r < NB; ++r) {
                float4 a = *reinterpret_cast<const float4*>(sm + TM_CAT + r * 384 + k);
                acc0[r] += a.x * w0a + a.y * w1a + a.z * w2a + a.w * w3a;
                acc1[r] += a.x * w0b + a.y * w1b + a.z * w2b + a.w * w3b;
            }
        }
        #pragma unroll
        for (int r = 0; r < NB; ++r) {
            sm[TM_H1 + r * 512 + j]       = sigm(acc0[r]);
            sm[TM_H1 + r * 512 + j + 256] = sigm(acc1[r]);
        }
    }
    __syncthreads();

    // Phase C: 512 -> 256
    {
        const int j = tid;
        float acc[NB];
        float bj = __ldg(&db2[j]);
        #pragma unroll
        for (int r = 0; r < NB; ++r) acc[r] = bj;
        #pragma unroll 4
        for (int k = 0; k < 512; k += 4) {
            float w0 = __ldg(&dw2[(k + 0) * 256 + j]);
            float w1 = __ldg(&dw2[(k + 1) * 256 + j]);
            float w2 = __ldg(&dw2[(k + 2) * 256 + j]);
            float w3 = __ldg(&dw2[(k + 3) * 256 + j]);
            #pragma unroll
            for (int r = 0; r < NB; ++r) {
                float4 a = *reinterpret_cast<const float4*>(sm + TM_H1 + r * 512 + k);
                acc[r] += a.x * w0 + a.y * w1 + a.z * w2 + a.w * w3;
            }
        }
        #pragma unroll
        for (int r = 0; r < NB; ++r)
            sm[TM_H2 + r * 256 + j] = sigm(acc[r]);
    }
    __syncthreads();

    // Phase D: 256 -> 128
    {
        const int j = tid & 127;
        const int rbase = (tid >> 7) * 2;
        float acc[2];
        float bj = __ldg(&db3[j]);
        acc[0] = bj; acc[1] = bj;
        #pragma unroll 4
        for (int k = 0; k < 256; k += 4) {
            float w0 = __ldg(&dw3[(k + 0) * 128 + j]);
            float w1 = __ldg(&dw3[(k + 1) * 128 + j]);
            float w2 = __ldg(&dw3[(k + 2) * 128 + j]);
            float w3 = __ldg(&dw3[(k + 3) * 128 + j]);
            #pragma unroll
            for (int i = 0; i < 2; ++i) {
                float4 a = *reinterpret_cast<const float4*>(sm + TM_H2 + (rbase + i) * 256 + k);
                acc[i] += a.x * w0 + a.y * w1 + a.z * w2 + a.w * w3;
            }
        }
        #pragma unroll
        for (int i = 0; i < 2; ++i)
            sm[TM_H3 + (rbase + i) * 128 + j] = sigm(acc[i]);
    }
    __syncthreads();

    // Phase E
    {
        const int wid  = tid >> 5;
        const int lane = tid & 31;
        if (wid < NB) {
            float v = 0.0f;
            #pragma unroll
            for (int q = 0; q < 4; ++q)
                v += sm[TM_H3 + wid * 128 + lane + 32 * q] * __ldg(&fw[lane + 32 * q]);
            #pragma unroll
            for (int m = 16; m > 0; m >>= 1) v += __shfl_xor_sync(0xffffffffu, v, m);
            if (lane == 0) {
                int b = b0 + wid;
                out[b] = v + __ldg(&fb[0]) + __ldg(&item_bias_tab[item_id[b]]);
            }
        }
    }
}

// ============================================================================
extern "C" void kernel_launch(void* const* d_in, const int* in_sizes, int n_in,
                              void* d_out, int out_size)
{
    const int*   in_item_id    = (const int*)  d_in[0];
    const int*   item_id       = (const int*)  d_in[1];
    const float* item_emb      = (const float*)d_in[2];
    const float* item_bias_tab = (const float*)d_in[3];
    const float* aw1 = (const float*)d_in[4];
    const float* ab1 = (const float*)d_in[5];
    const float* aw2 = (const float*)d_in[6];
    const float* ab2 = (const float*)d_in[7];
    const float* afw = (const float*)d_in[8];
    const float* afb = (const float*)d_in[9];
    const float* nw  = (const float*)d_in[10];
    const float* nb  = (const float*)d_in[11];
    const float* dw1 = (const float*)d_in[12];
    const float* db1 = (const float*)d_in[13];
    const float* dw2 = (const float*)d_in[14];
    const float* db2 = (const float*)d_in[15];
    const float* dw3 = (const float*)d_in[16];
    const float* db3 = (const float*)d_in[17];
    const float* fw  = (const float*)d_in[18];
    const float* fb  = (const float*)d_in[19];
    float* out = (float*)d_out;

    cudaFuncSetAttribute(din_attention_mma,
                         cudaFuncAttributeMaxDynamicSharedMemorySize, SMEM_BYTES);
    cudaFuncSetAttribute(mlp_tail_kernel,
                         cudaFuncAttributeMaxDynamicSharedMemorySize,
                         (int)(TM_TOT * sizeof(float)));

    cvec_kernel<<<BB / 16, 512>>>(item_id, item_emb, aw1, ab1);
    din_attention_mma<<<BB, 256, SMEM_BYTES>>>(in_item_id, item_id, item_emb,
                                               aw1, aw2, ab2, afw, afb);
    mlp_tail_kernel<<<BB / NB, 256, TM_TOT * sizeof(float)>>>(
        item_id, item_emb, nw, nb, dw1, db1, dw2, db2, dw3, db3,
        fw, fb, item_bias_tab, out);
}

// round 10
// speedup vs baseline: 4.3420x; 1.2936x over previous
#include <cuda_runtime.h>
#include <cuda_fp16.h>
#include <cstdint>

// ============================================================================
// DIN scorer R9: drop SA lo-planes entirely (attn epilogue reconstructs s
// from the fp16 hi plane; measured attenuation says ~+2e-7 rel_err).
// smem 158KB -> 105KB  =>  2 CTAs/SM (16 warps): non-MMA latency of one CTA
// hides under the other's compute. Gather loses half its cvt/store work.
// ============================================================================

#define BB 2048
#define LL 200

__device__ float g_attn[BB * 128];
__device__ float g_cvec[BB * 128];

__device__ __forceinline__ float sigm(float x) {
    return __fdividef(1.0f, 1.0f + __expf(-x));
}

// single-plane fp16 quantization of two floats (packed low-first)
__device__ __forceinline__ uint32_t pack2h(float a, float b) {
    return ((uint32_t)__half_as_ushort(__float2half_rn(b)) << 16)
         |  (uint32_t)__half_as_ushort(__float2half_rn(a));
}

// m16n8k16 fp16 MMA, fp32 accumulate (in-place C)
__device__ __forceinline__ void mma_f16(float* c, uint32_t a0, uint32_t a1,
                                        uint32_t a2, uint32_t a3,
                                        uint32_t b0, uint32_t b1) {
    asm("mma.sync.aligned.m16n8k16.row.col.f32.f16.f16.f32 "
        "{%0,%1,%2,%3}, {%4,%5,%6,%7}, {%8,%9}, {%0,%1,%2,%3};"
        : "+f"(c[0]), "+f"(c[1]), "+f"(c[2]), "+f"(c[3])
        : "r"(a0), "r"(a1), "r"(a2), "r"(a3), "r"(b0), "r"(b1));
}

__device__ __forceinline__ int pidx(int row, int pair) {
    return row * 64 + (pair ^ ((row & 7) << 2));
}

// ============================================================================
// cvec_kernel: unchanged (11.5us)
// ============================================================================
__global__ __launch_bounds__(512, 2)
void cvec_kernel(const int*   __restrict__ item_id,
                 const float* __restrict__ item_emb,
                 const float* __restrict__ aw1,
                 const float* __restrict__ ab1)
{
    __shared__ float tT[128 * 16];
    __shared__ float part[4 * 16 * 128];
    const int b0  = blockIdx.x * 16;
    const int tid = threadIdx.x;

    for (int e = tid; e < 128 * 16; e += 512) {
        int k = e >> 4, bb = e & 15;
        long id = (long)__ldg(&item_id[b0 + bb]);
        tT[e] = __ldg(&item_emb[id * 128 + k]);
    }
    __syncthreads();

    const int j  = tid & 127;
    const int kq = tid >> 7;
    float acc[16];
    #pragma unroll
    for (int r = 0; r < 16; ++r) acc[r] = 0.0f;

    #pragma unroll 8
    for (int kk = 0; kk < 32; ++kk) {
        int k = kq * 32 + kk;
        float w = __ldg(&aw1[k * 128 + j]) + __ldg(&aw1[(256 + k) * 128 + j]);
        const float4* tp = reinterpret_cast<const float4*>(tT + k * 16);
        #pragma unroll
        for (int q = 0; q < 4; ++q) {
            float4 tv = tp[q];
            acc[q * 4 + 0] += tv.x * w;
            acc[q * 4 + 1] += tv.y * w;
            acc[q * 4 + 2] += tv.z * w;
            acc[q * 4 + 3] += tv.w * w;
        }
    }
    #pragma unroll
    for (int r = 0; r < 16; ++r)
        part[(kq * 16 + r) * 128 + j] = acc[r];
    __syncthreads();

    for (int e = tid; e < 16 * 128; e += 512) {
        int bb = e >> 7, jj = e & 127;
        float s = part[(0 * 16 + bb) * 128 + jj] + part[(1 * 16 + bb) * 128 + jj]
                + part[(2 * 16 + bb) * 128 + jj] + part[(3 * 16 + bb) * 128 + jj]
                + __ldg(&ab1[jj]);
        g_cvec[(b0 + bb) * 128 + jj] = s;
    }
}

// ---- smem byte offsets (din) — 105KB total, 2 CTAs/SM ----
#define OFF_SA0     0         // chunk0 seq [128][64] b32-pairs fp16
#define OFF_SA1     32768     // chunk1 seq (80-row alloc, 72 used)
#define OFF_B1      53248     // Mb   [n=128][kpair=64] fp16
#define OFF_B2      86016     // aw2  [n=64][kpair=64]  fp16
#define OFF_T       102400
#define OFF_CVEC    102912
#define OFF_SCORE   103424
#define OFF_AB2     103936
#define OFF_AFW     104192
#define OFF_RED     104448
#define SMEM_BYTES  104960

template<int CR>
__device__ __forceinline__ void gather_chunk(char* smem, int offHI,
                                             const int* __restrict__ ids,
                                             const float* __restrict__ item_emb,
                                             int tid)
{
    uint32_t* dHI = (uint32_t*)(smem + offHI);
    constexpr int NIT = CR * 32 / 256;
    int idv[NIT];
    #pragma unroll
    for (int i = 0; i < NIT; ++i)
        idv[i] = __ldg(&ids[(tid + i * 256) >> 5]);
    #pragma unroll
    for (int i = 0; i < NIT; ++i) {
        int e = tid + i * 256, row = e >> 5, q = e & 31;
        float4 v = __ldg(reinterpret_cast<const float4*>(item_emb + (long)idv[i] * 128) + q);
        int a = pidx(row, q * 2);
        *(uint2*)(dHI + a) = make_uint2(pack2h(v.x, v.y), pack2h(v.z, v.w));
    }
}

template<int CR>
__device__ __forceinline__ void compute_chunk(char* smem, int offHI,
                                              const int* __restrict__ ids,
                                              float afb0, float& attnReg,
                                              int tid, int wid, int g, int tg, int sx,
                                              int rA, int dAt, int half)
{
    uint32_t* saHI = (uint32_t*)(smem + offHI);
    uint32_t* b1P  = (uint32_t*)(smem + OFF_B1);
    uint32_t* b2P  = (uint32_t*)(smem + OFF_B2);
    float* cvec   = (float*)(smem + OFF_CVEC);
    float* scoreS = (float*)(smem + OFF_SCORE);
    float* ab2S   = (float*)(smem + OFF_AB2);
    float* afwS   = (float*)(smem + OFF_AFW);

    const bool act = (wid * 16 < CR);

    uint32_t hT[16], hB[16];    // h1 fragments, single fp16 plane

    if (act) {
        // ===== GEMM1: D1 = s @ Mb (single-plane fp16, fp32 accum) =====
        float acc[16][4];
        #pragma unroll
        for (int nt = 0; nt < 16; ++nt)
            #pragma unroll
            for (int i = 0; i < 4; ++i) acc[nt][i] = 0.0f;

        const int rTop = rA * 64, rBot = (rA + 8) * 64;
        #pragma unroll
        for (int ks = 0; ks < 8; ++ks) {
            const int p0 = (8 * ks + tg) ^ sx;
            const int p1 = p0 ^ 4;
            uint32_t ah0 = saHI[rTop + p0], ah1 = saHI[rBot + p0];
            uint32_t ah2 = saHI[rTop + p1], ah3 = saHI[rBot + p1];
            #pragma unroll
            for (int nt = 0; nt < 16; ++nt) {
                const int nb = (8 * nt + g) * 64;
                mma_f16(acc[nt], ah0, ah1, ah2, ah3, b1P[nb + p0], b1P[nb + p1]);
            }
        }
        #pragma unroll
        for (int nt = 0; nt < 16; ++nt) {
            const int c0 = 8 * nt + 2 * tg;
            float t0 = sigm(acc[nt][0] + cvec[c0]);
            float t1 = sigm(acc[nt][1] + cvec[c0 + 1]);
            float b0 = sigm(acc[nt][2] + cvec[c0]);
            float b1 = sigm(acc[nt][3] + cvec[c0 + 1]);
            hT[nt] = pack2h(t0, t1);
            hB[nt] = pack2h(b0, b1);
        }
    }

    float acc2[8][4];
    #pragma unroll
    for (int nt = 0; nt < 8; ++nt)
        #pragma unroll
        for (int i = 0; i < 4; ++i) acc2[nt][i] = 0.0f;

    if (act) {
        // ===== GEMM2: D2 = h1 @ aw2 (single-plane fp16) =====
        #pragma unroll
        for (int ks = 0; ks < 8; ++ks) {
            const int p0 = (8 * ks + tg) ^ sx;
            const int p1 = p0 ^ 4;
            uint32_t ah0 = hT[2 * ks],     ah1 = hB[2 * ks];
            uint32_t ah2 = hT[2 * ks + 1], ah3 = hB[2 * ks + 1];
            #pragma unroll
            for (int nt = 0; nt < 8; ++nt) {
                const int nb = (8 * nt + g) * 64;
                mma_f16(acc2[nt], ah0, ah1, ah2, ah3, b2P[nb + p0], b2P[nb + p1]);
            }
        }
    }

    {
        float vT = 0.0f, vB = 0.0f;
        #pragma unroll
        for (int nt = 0; nt < 8; ++nt) {
            const int c0 = 8 * nt + 2 * tg;
            vT += sigm(acc2[nt][0] + ab2S[c0])     * afwS[c0];
            vT += sigm(acc2[nt][1] + ab2S[c0 + 1]) * afwS[c0 + 1];
            vB += sigm(acc2[nt][2] + ab2S[c0])     * afwS[c0];
            vB += sigm(acc2[nt][3] + ab2S[c0 + 1]) * afwS[c0 + 1];
        }
        vT += __shfl_xor_sync(0xffffffffu, vT, 1);
        vT += __shfl_xor_sync(0xffffffffu, vT, 2);
        vB += __shfl_xor_sync(0xffffffffu, vB, 1);
        vB += __shfl_xor_sync(0xffffffffu, vB, 2);
        if (tg == 0) {
            int r0 = rA, r1 = rA + 8;
            float s0 = 0.0f, s1 = 0.0f;
            if (act && r0 < CR) {
                int id = __ldg(&ids[r0]);
                s0 = (id == 0) ? 0.0f : (vT + afb0);
            }
            if (act && r1 < CR) {
                int id = __ldg(&ids[r1]);
                s1 = (id == 0) ? 0.0f : (vB + afb0);
            }
            scoreS[r0] = s0;
            if (r1 < 128) scoreS[r1] = s1;
        }
    }
    __syncthreads();

    // attn epilogue: s reconstructed from fp16 hi plane
    {
        const int h0 = half * (CR >> 1);
        const int h1 = h0 + (CR >> 1);
        const int pr = dAt >> 1, sel = (dAt & 1) * 16;
        for (int row = h0; row < h1; ++row) {
            float sc = scoreS[row];
            uint32_t whi = saHI[pidx(row, pr)];
            float s = __half2float(__ushort_as_half((unsigned short)(whi >> sel)));
            attnReg += sc * s;
        }
    }
    __syncthreads();
}

__global__ __launch_bounds__(256, 2)
void din_attention_mma(const int*   __restrict__ in_item_id,
                       const int*   __restrict__ item_id,
                       const float* __restrict__ item_emb,
                       const float* __restrict__ aw1,
                       const float* __restrict__ aw2,
                       const float* __restrict__ ab2,
                       const float* __restrict__ afw,
                       const float* __restrict__ afb)
{
    extern __shared__ char smem[];
    uint32_t* b1P = (uint32_t*)(smem + OFF_B1);
    uint32_t* b2P = (uint32_t*)(smem + OFF_B2);
    float* tS     = (float*)(smem + OFF_T);
    float* cvec   = (float*)(smem + OFF_CVEC);
    float* ab2S   = (float*)(smem + OFF_AB2);
    float* afwS   = (float*)(smem + OFF_AFW);
    float* redS   = (float*)(smem + OFF_RED);

    const int tid = threadIdx.x, wid = tid >> 5, lid = tid & 31;
    const int b = blockIdx.x;
    const int g  = lid >> 2;
    const int tg = lid & 3;
    const int sx = g << 2;

    if (tid < 128) {
        long id = (long)item_id[b];
        tS[tid]   = item_emb[id * 128 + tid];
        cvec[tid] = g_cvec[b * 128 + tid];
    }
    if (tid < 64) { ab2S[tid] = __ldg(&ab2[tid]); afwS[tid] = __ldg(&afw[tid]); }
    __syncthreads();

    // ---- single latency region: chunk0 gather + B1 build + B2 build ----
    gather_chunk<128>(smem, OFF_SA0, in_item_id + b * LL, item_emb, tid);

    for (int e = tid; e < 128 * 64; e += 256) {
        int j = e & 127, kp = e >> 7;
        int k0 = kp * 2, k1 = k0 + 1;
        float v0 = tS[k0] * __ldg(&aw1[(128 + k0) * 128 + j]) - __ldg(&aw1[(256 + k0) * 128 + j]);
        float v1 = tS[k1] * __ldg(&aw1[(128 + k1) * 128 + j]) - __ldg(&aw1[(256 + k1) * 128 + j]);
        b1P[pidx(j, kp)] = pack2h(v0, v1);
    }
    for (int e = tid; e < 64 * 64; e += 256) {
        int n = e & 63, kp = e >> 6;
        float v0 = __ldg(&aw2[(kp * 2) * 64 + n]);
        float v1 = __ldg(&aw2[(kp * 2 + 1) * 64 + n]);
        b2P[pidx(n, kp)] = pack2h(v0, v1);
    }
    const float afb0 = __ldg(&afb[0]);
    __syncthreads();

    // ---- prefetch chunk1 gather: LDGs fly during chunk0 compute ----
    gather_chunk<72>(smem, OFF_SA1, in_item_id + b * LL + 128, item_emb, tid);

    const int rA   = wid * 16 + g;
    const int dAt  = tid & 127;
    const int half = tid >> 7;
    float attnReg = 0.0f;

    compute_chunk<128>(smem, OFF_SA0, in_item_id + b * LL,
                       afb0, attnReg, tid, wid, g, tg, sx, rA, dAt, half);
    compute_chunk<72>(smem, OFF_SA1, in_item_id + b * LL + 128,
                      afb0, attnReg, tid, wid, g, tg, sx, rA, dAt, half);

    if (tid >= 128) redS[dAt] = attnReg;
    __syncthreads();
    if (tid < 128) g_attn[b * 128 + tid] = attnReg + redS[tid];
}

// ============================================================================
// Fused MLP tail: unchanged (4 batches/CTA, 4 CTAs/SM).
// ============================================================================
#define NB 4
#define TM_ATTN 0
#define TM_T    (NB*128)
#define TM_CAT  (2*NB*128)
#define TM_H1   (TM_CAT + NB*384)
#define TM_H2   (TM_H1 + NB*512)
#define TM_H3   (TM_H2 + NB*256)
#define TM_TOT  (TM_H3 + NB*128)   // 6144 floats = 24576 B

__global__ __launch_bounds__(256, 4)
void mlp_tail_kernel(const int*   __restrict__ item_id,
                     const float* __restrict__ item_emb,
                     const float* __restrict__ nw,
                     const float* __restrict__ nb,
                     const float* __restrict__ dw1,
                     const float* __restrict__ db1,
                     const float* __restrict__ dw2,
                     const float* __restrict__ db2,
                     const float* __restrict__ dw3,
                     const float* __restrict__ db3,
                     const float* __restrict__ fw,
                     const float* __restrict__ fb,
                     const float* __restrict__ item_bias_tab,
                     float*       __restrict__ out)
{
    extern __shared__ float sm[];
    const int b0  = blockIdx.x * NB;
    const int tid = threadIdx.x;

    for (int e = tid; e < NB * 128; e += 256) {
        int bb = e >> 7, j = e & 127;
        sm[TM_ATTN + e] = g_attn[(b0 + bb) * 128 + j];
        long id = (long)__ldg(&item_id[b0 + bb]);
        sm[TM_T + e]    = __ldg(&item_emb[id * 128 + j]);
    }
    __syncthreads();

    // Phase A
    {
        const int j = tid & 127;
        const int rbase = (tid >> 7) * 2;
        float acc[2];
        float nbj = __ldg(&nb[j]);
        acc[0] = nbj; acc[1] = nbj;
        #pragma unroll 4
        for (int k = 0; k < 128; k += 4) {
            float w0 = __ldg(&nw[(k + 0) * 128 + j]);
            float w1 = __ldg(&nw[(k + 1) * 128 + j]);
            float w2 = __ldg(&nw[(k + 2) * 128 + j]);
            float w3 = __ldg(&nw[(k + 3) * 128 + j]);
            #pragma unroll
            for (int i = 0; i < 2; ++i) {
                float4 a = *reinterpret_cast<const float4*>(sm + TM_ATTN + (rbase + i) * 128 + k);
                acc[i] += a.x * w0 + a.y * w1 + a.z * w2 + a.w * w3;
            }
        }
        #pragma unroll
        for (int i = 0; i < 2; ++i) {
            int r = rbase + i;
            float a2 = acc[i];
            float t  = sm[TM_T + r * 128 + j];
            sm[TM_CAT + r * 384 + j]       = a2;
            sm[TM_CAT + r * 384 + 128 + j] = t;
            sm[TM_CAT + r * 384 + 256 + j] = t * a2;
        }
    }
    __syncthreads();

    // Phase B: 384 -> 512
    {
        const int j = tid;
        float acc0[NB], acc1[NB];
        float bj0 = __ldg(&db1[j]), bj1 = __ldg(&db1[j + 256]);
        #pragma unroll
        for (int r = 0; r < NB; ++r) { acc0[r] = bj0; acc1[r] = bj1; }
        #pragma unroll 4
        for (int k = 0; k < 384; k += 4) {
            float w0a = __ldg(&dw1[(k + 0) * 512 + j]);
            float w1a = __ldg(&dw1[(k + 1) * 512 + j]);
            float w2a = __ldg(&dw1[(k + 2) * 512 + j]);
            float w3a = __ldg(&dw1[(k + 3) * 512 + j]);
            float w0b = __ldg(&dw1[(k + 0) * 512 + j + 256]);
            float w1b = __ldg(&dw1[(k + 1) * 512 + j + 256]);
            float w2b = __ldg(&dw1[(k + 2) * 512 + j + 256]);
            float w3b = __ldg(&dw1[(k + 3) * 512 + j + 256]);
            #pragma unroll
            for (int r = 0; r < NB; ++r) {
                float4 a = *reinterpret_cast<const float4*>(sm + TM_CAT + r * 384 + k);
                acc0[r] += a.x * w0a + a.y * w1a + a.z * w2a + a.w * w3a;
                acc1[r] += a.x * w0b + a.y * w1b + a.z * w2b + a.w * w3b;
            }
        }
        #pragma unroll
        for (int r = 0; r < NB; ++r) {
            sm[TM_H1 + r * 512 + j]       = sigm(acc0[r]);
            sm[TM_H1 + r * 512 + j + 256] = sigm(acc1[r]);
        }
    }
    __syncthreads();

    // Phase C: 512 -> 256
    {
        const int j = tid;
        float acc[NB];
        float bj = __ldg(&db2[j]);
        #pragma unroll
        for (int r = 0; r < NB; ++r) acc[r] = bj;
        #pragma unroll 4
        for (int k = 0; k < 512; k += 4) {
            float w0 = __ldg(&dw2[(k + 0) * 256 + j]);
            float w1 = __ldg(&dw2[(k + 1) * 256 + j]);
            float w2 = __ldg(&dw2[(k + 2) * 256 + j]);
            float w3 = __ldg(&dw2[(k + 3) * 256 + j]);
            #pragma unroll
            for (int r = 0; r < NB; ++r) {
                float4 a = *reinterpret_cast<const float4*>(sm + TM_H1 + r * 512 + k);
                acc[r] += a.x * w0 + a.y * w1 + a.z * w2 + a.w * w3;
            }
        }
        #pragma unroll
        for (int r = 0; r < NB; ++r)
            sm[TM_H2 + r * 256 + j] = sigm(acc[r]);
    }
    __syncthreads();

    // Phase D: 256 -> 128
    {
        const int j = tid & 127;
        const int rbase = (tid >> 7) * 2;
        float acc[2];
        float bj = __ldg(&db3[j]);
        acc[0] = bj; acc[1] = bj;
        #pragma unroll 4
        for (int k = 0; k < 256; k += 4) {
            float w0 = __ldg(&dw3[(k + 0) * 128 + j]);
            float w1 = __ldg(&dw3[(k + 1) * 128 + j]);
            float w2 = __ldg(&dw3[(k + 2) * 128 + j]);
            float w3 = __ldg(&dw3[(k + 3) * 128 + j]);
            #pragma unroll
            for (int i = 0; i < 2; ++i) {
                float4 a = *reinterpret_cast<const float4*>(sm + TM_H2 + (rbase + i) * 256 + k);
                acc[i] += a.x * w0 + a.y * w1 + a.z * w2 + a.w * w3;
            }
        }
        #pragma unroll
        for (int i = 0; i < 2; ++i)
            sm[TM_H3 + (rbase + i) * 128 + j] = sigm(acc[i]);
    }
    __syncthreads();

    // Phase E
    {
        const int wid  = tid >> 5;
        const int lane = tid & 31;
        if (wid < NB) {
            float v = 0.0f;
            #pragma unroll
            for (int q = 0; q < 4; ++q)
                v += sm[TM_H3 + wid * 128 + lane + 32 * q] * __ldg(&fw[lane + 32 * q]);
            #pragma unroll
            for (int m = 16; m > 0; m >>= 1) v += __shfl_xor_sync(0xffffffffu, v, m);
            if (lane == 0) {
                int b = b0 + wid;
                out[b] = v + __ldg(&fb[0]) + __ldg(&item_bias_tab[item_id[b]]);
            }
        }
    }
}

// ============================================================================
extern "C" void kernel_launch(void* const* d_in, const int* in_sizes, int n_in,
                              void* d_out, int out_size)
{
    const int*   in_item_id    = (const int*)  d_in[0];
    const int*   item_id       = (const int*)  d_in[1];
    const float* item_emb      = (const float*)d_in[2];
    const float* item_bias_tab = (const float*)d_in[3];
    const float* aw1 = (const float*)d_in[4];
    const float* ab1 = (const float*)d_in[5];
    const float* aw2 = (const float*)d_in[6];
    const float* ab2 = (const float*)d_in[7];
    const float* afw = (const float*)d_in[8];
    const float* afb = (const float*)d_in[9];
    const float* nw  = (const float*)d_in[10];
    const float* nb  = (const float*)d_in[11];
    const float* dw1 = (const float*)d_in[12];
    const float* db1 = (const float*)d_in[13];
    const float* dw2 = (const float*)d_in[14];
    const float* db2 = (const float*)d_in[15];
    const float* dw3 = (const float*)d_in[16];
    const float* db3 = (const float*)d_in[17];
    const float* fw  = (const float*)d_in[18];
    const float* fb  = (const float*)d_in[19];
    float* out = (float*)d_out;

    cudaFuncSetAttribute(din_attention_mma,
                         cudaFuncAttributeMaxDynamicSharedMemorySize, SMEM_BYTES);
    cudaFuncSetAttribute(mlp_tail_kernel,
                         cudaFuncAttributeMaxDynamicSharedMemorySize,
                         (int)(TM_TOT * sizeof(float)));

    cvec_kernel<<<BB / 16, 512>>>(item_id, item_emb, aw1, ab1);
    din_attention_mma<<<BB, 256, SMEM_BYTES>>>(in_item_id, item_id, item_emb,
                                               aw1, aw2, ab2, afw, afb);
    mlp_tail_kernel<<<BB / NB, 256, TM_TOT * sizeof(float)>>>(
        item_id, item_emb, nw, nb, dw1, db1, dw2, db2, dw3, db3,
        fw, fb, item_bias_tab, out);
}

// round 12
// speedup vs baseline: 4.6244x; 1.0651x over previous
#include <cuda_runtime.h>
#include <cuda_fp16.h>
#include <cstdint>

// ============================================================================
// DIN scorer R11: din keeps tanh.approx sigmoid (attenuated path, measured
// safe); tail fully reverted to R9 (fp32 weights, __fdividef sigmoid) since
// tail-side errors reach the output unattenuated (R10 failure: 1.3e-3).
// ============================================================================

#define BB 2048
#define LL 200

__device__ float g_attn[BB * 128];
__device__ float g_cvec[BB * 128];

// din-side sigmoid: tanh.approx (errors attenuated through score/attn path)
__device__ __forceinline__ float sigm_fast(float x) {
    float y;
    asm("tanh.approx.f32 %0, %1;" : "=f"(y) : "f"(0.5f * x));
    return fmaf(0.5f, y, 0.5f);
}
// tail-side sigmoid: near-exact (errors unattenuated)
__device__ __forceinline__ float sigm(float x) {
    return __fdividef(1.0f, 1.0f + __expf(-x));
}

// single-plane fp16 quantization of two floats (packed low-first)
__device__ __forceinline__ uint32_t pack2h(float a, float b) {
    return ((uint32_t)__half_as_ushort(__float2half_rn(b)) << 16)
         |  (uint32_t)__half_as_ushort(__float2half_rn(a));
}

// m16n8k16 fp16 MMA, fp32 accumulate (in-place C)
__device__ __forceinline__ void mma_f16(float* c, uint32_t a0, uint32_t a1,
                                        uint32_t a2, uint32_t a3,
                                        uint32_t b0, uint32_t b1) {
    asm("mma.sync.aligned.m16n8k16.row.col.f32.f16.f16.f32 "
        "{%0,%1,%2,%3}, {%4,%5,%6,%7}, {%8,%9}, {%0,%1,%2,%3};"
        : "+f"(c[0]), "+f"(c[1]), "+f"(c[2]), "+f"(c[3])
        : "r"(a0), "r"(a1), "r"(a2), "r"(a3), "r"(b0), "r"(b1));
}

__device__ __forceinline__ int pidx(int row, int pair) {
    return row * 64 + (pair ^ ((row & 7) << 2));
}

// ============================================================================
// cvec_kernel (unchanged, 11.2us)
// ============================================================================
__global__ __launch_bounds__(512, 2)
void cvec_kernel(const int*   __restrict__ item_id,
                 const float* __restrict__ item_emb,
                 const float* __restrict__ aw1,
                 const float* __restrict__ ab1)
{
    __shared__ float tT[128 * 16];
    __shared__ float part[4 * 16 * 128];
    const int b0  = blockIdx.x * 16;
    const int tid = threadIdx.x;

    for (int e = tid; e < 128 * 16; e += 512) {
        int k = e >> 4, bb = e & 15;
        long id = (long)__ldg(&item_id[b0 + bb]);
        tT[e] = __ldg(&item_emb[id * 128 + k]);
    }
    __syncthreads();

    const int j  = tid & 127;
    const int kq = tid >> 7;
    float acc[16];
    #pragma unroll
    for (int r = 0; r < 16; ++r) acc[r] = 0.0f;

    #pragma unroll 8
    for (int kk = 0; kk < 32; ++kk) {
        int k = kq * 32 + kk;
        float w = __ldg(&aw1[k * 128 + j]) + __ldg(&aw1[(256 + k) * 128 + j]);
        const float4* tp = reinterpret_cast<const float4*>(tT + k * 16);
        #pragma unroll
        for (int q = 0; q < 4; ++q) {
            float4 tv = tp[q];
            acc[q * 4 + 0] += tv.x * w;
            acc[q * 4 + 1] += tv.y * w;
            acc[q * 4 + 2] += tv.z * w;
            acc[q * 4 + 3] += tv.w * w;
        }
    }
    #pragma unroll
    for (int r = 0; r < 16; ++r)
        part[(kq * 16 + r) * 128 + j] = acc[r];
    __syncthreads();

    for (int e = tid; e < 16 * 128; e += 512) {
        int bb = e >> 7, jj = e & 127;
        float s = part[(0 * 16 + bb) * 128 + jj] + part[(1 * 16 + bb) * 128 + jj]
                + part[(2 * 16 + bb) * 128 + jj] + part[(3 * 16 + bb) * 128 + jj]
                + __ldg(&ab1[jj]);
        g_cvec[(b0 + bb) * 128 + jj] = s;
    }
}

// ---- smem byte offsets (din) — 105KB, 2 CTAs/SM ----
#define OFF_SA0     0
#define OFF_SA1     32768
#define OFF_B1      53248
#define OFF_B2      86016
#define OFF_T       102400
#define OFF_CVEC    102912
#define OFF_SCORE   103424
#define OFF_AB2     103936
#define OFF_AFW     104192
#define OFF_RED     104448
#define SMEM_BYTES  104960

template<int CR>
__device__ __forceinline__ void gather_chunk(char* smem, int offHI,
                                             const int* __restrict__ ids,
                                             const float* __restrict__ item_emb,
                                             int tid)
{
    uint32_t* dHI = (uint32_t*)(smem + offHI);
    constexpr int NIT = CR * 32 / 256;
    int idv[NIT];
    #pragma unroll
    for (int i = 0; i < NIT; ++i)
        idv[i] = __ldg(&ids[(tid + i * 256) >> 5]);
    #pragma unroll
    for (int i = 0; i < NIT; ++i) {
        int e = tid + i * 256, row = e >> 5, q = e & 31;
        float4 v = __ldg(reinterpret_cast<const float4*>(item_emb + (long)idv[i] * 128) + q);
        int a = pidx(row, q * 2);
        *(uint2*)(dHI + a) = make_uint2(pack2h(v.x, v.y), pack2h(v.z, v.w));
    }
}

template<int CR>
__device__ __forceinline__ void compute_chunk(char* smem, int offHI,
                                              const int* __restrict__ ids,
                                              float afb0, float& attnReg,
                                              int tid, int wid, int g, int tg, int sx,
                                              int rA, int dAt, int half)
{
    uint32_t* saHI = (uint32_t*)(smem + offHI);
    uint32_t* b1P  = (uint32_t*)(smem + OFF_B1);
    uint32_t* b2P  = (uint32_t*)(smem + OFF_B2);
    float* cvec   = (float*)(smem + OFF_CVEC);
    float* scoreS = (float*)(smem + OFF_SCORE);
    float* ab2S   = (float*)(smem + OFF_AB2);
    float* afwS   = (float*)(smem + OFF_AFW);

    const bool act = (wid * 16 < CR);

    uint32_t hT[16], hB[16];

    if (act) {
        float acc[16][4];
        #pragma unroll
        for (int nt = 0; nt < 16; ++nt)
            #pragma unroll
            for (int i = 0; i < 4; ++i) acc[nt][i] = 0.0f;

        const int rTop = rA * 64, rBot = (rA + 8) * 64;
        #pragma unroll
        for (int ks = 0; ks < 8; ++ks) {
            const int p0 = (8 * ks + tg) ^ sx;
            const int p1 = p0 ^ 4;
            uint32_t ah0 = saHI[rTop + p0], ah1 = saHI[rBot + p0];
            uint32_t ah2 = saHI[rTop + p1], ah3 = saHI[rBot + p1];
            #pragma unroll
            for (int nt = 0; nt < 16; ++nt) {
                const int nb = (8 * nt + g) * 64;
                mma_f16(acc[nt], ah0, ah1, ah2, ah3, b1P[nb + p0], b1P[nb + p1]);
            }
        }
        #pragma unroll
        for (int nt = 0; nt < 16; ++nt) {
            const int c0 = 8 * nt + 2 * tg;
            float t0 = sigm_fast(acc[nt][0] + cvec[c0]);
            float t1 = sigm_fast(acc[nt][1] + cvec[c0 + 1]);
            float b0 = sigm_fast(acc[nt][2] + cvec[c0]);
            float b1 = sigm_fast(acc[nt][3] + cvec[c0 + 1]);
            hT[nt] = pack2h(t0, t1);
            hB[nt] = pack2h(b0, b1);
        }
    }

    float acc2[8][4];
    #pragma unroll
    for (int nt = 0; nt < 8; ++nt)
        #pragma unroll
        for (int i = 0; i < 4; ++i) acc2[nt][i] = 0.0f;

    if (act) {
        #pragma unroll
        for (int ks = 0; ks < 8; ++ks) {
            const int p0 = (8 * ks + tg) ^ sx;
            const int p1 = p0 ^ 4;
            uint32_t ah0 = hT[2 * ks],     ah1 = hB[2 * ks];
            uint32_t ah2 = hT[2 * ks + 1], ah3 = hB[2 * ks + 1];
            #pragma unroll
            for (int nt = 0; nt < 8; ++nt) {
                const int nb = (8 * nt + g) * 64;
                mma_f16(acc2[nt], ah0, ah1, ah2, ah3, b2P[nb + p0], b2P[nb + p1]);
            }
        }
    }

    {
        float vT = 0.0f, vB = 0.0f;
        #pragma unroll
        for (int nt = 0; nt < 8; ++nt) {
            const int c0 = 8 * nt + 2 * tg;
            vT += sigm_fast(acc2[nt][0] + ab2S[c0])     * afwS[c0];
            vT += sigm_fast(acc2[nt][1] + ab2S[c0 + 1]) * afwS[c0 + 1];
            vB += sigm_fast(acc2[nt][2] + ab2S[c0])     * afwS[c0];
            vB += sigm_fast(acc2[nt][3] + ab2S[c0 + 1]) * afwS[c0 + 1];
        }
        vT += __shfl_xor_sync(0xffffffffu, vT, 1);
        vT += __shfl_xor_sync(0xffffffffu, vT, 2);
        vB += __shfl_xor_sync(0xffffffffu, vB, 1);
        vB += __shfl_xor_sync(0xffffffffu, vB, 2);
        if (tg == 0) {
            int r0 = rA, r1 = rA + 8;
            float s0 = 0.0f, s1 = 0.0f;
            if (act && r0 < CR) {
                int id = __ldg(&ids[r0]);
                s0 = (id == 0) ? 0.0f : (vT + afb0);
            }
            if (act && r1 < CR) {
                int id = __ldg(&ids[r1]);
                s1 = (id == 0) ? 0.0f : (vB + afb0);
            }
            scoreS[r0] = s0;
            if (r1 < 128) scoreS[r1] = s1;
        }
    }
    __syncthreads();

    {
        const int h0 = half * (CR >> 1);
        const int h1 = h0 + (CR >> 1);
        const int pr = dAt >> 1, sel = (dAt & 1) * 16;
        for (int row = h0; row < h1; ++row) {
            float sc = scoreS[row];
            uint32_t whi = saHI[pidx(row, pr)];
            float s = __half2float(__ushort_as_half((unsigned short)(whi >> sel)));
            attnReg += sc * s;
        }
    }
    __syncthreads();
}

__global__ __launch_bounds__(256, 2)
void din_attention_mma(const int*   __restrict__ in_item_id,
                       const int*   __restrict__ item_id,
                       const float* __restrict__ item_emb,
                       const float* __restrict__ aw1,
                       const float* __restrict__ aw2,
                       const float* __restrict__ ab2,
                       const float* __restrict__ afw,
                       const float* __restrict__ afb)
{
    extern __shared__ char smem[];
    uint32_t* b1P = (uint32_t*)(smem + OFF_B1);
    uint32_t* b2P = (uint32_t*)(smem + OFF_B2);
    float* tS     = (float*)(smem + OFF_T);
    float* cvec   = (float*)(smem + OFF_CVEC);
    float* ab2S   = (float*)(smem + OFF_AB2);
    float* afwS   = (float*)(smem + OFF_AFW);
    float* redS   = (float*)(smem + OFF_RED);

    const int tid = threadIdx.x, wid = tid >> 5, lid = tid & 31;
    const int b = blockIdx.x;
    const int g  = lid >> 2;
    const int tg = lid & 3;
    const int sx = g << 2;

    if (tid < 128) {
        long id = (long)item_id[b];
        tS[tid]   = item_emb[id * 128 + tid];
        cvec[tid] = g_cvec[b * 128 + tid];
    }
    if (tid < 64) { ab2S[tid] = __ldg(&ab2[tid]); afwS[tid] = __ldg(&afw[tid]); }
    __syncthreads();

    gather_chunk<128>(smem, OFF_SA0, in_item_id + b * LL, item_emb, tid);

    for (int e = tid; e < 128 * 64; e += 256) {
        int j = e & 127, kp = e >> 7;
        int k0 = kp * 2, k1 = k0 + 1;
        float v0 = tS[k0] * __ldg(&aw1[(128 + k0) * 128 + j]) - __ldg(&aw1[(256 + k0) * 128 + j]);
        float v1 = tS[k1] * __ldg(&aw1[(128 + k1) * 128 + j]) - __ldg(&aw1[(256 + k1) * 128 + j]);
        b1P[pidx(j, kp)] = pack2h(v0, v1);
    }
    for (int e = tid; e < 64 * 64; e += 256) {
        int n = e & 63, kp = e >> 6;
        float v0 = __ldg(&aw2[(kp * 2) * 64 + n]);
        float v1 = __ldg(&aw2[(kp * 2 + 1) * 64 + n]);
        b2P[pidx(n, kp)] = pack2h(v0, v1);
    }
    const float afb0 = __ldg(&afb[0]);
    __syncthreads();

    gather_chunk<72>(smem, OFF_SA1, in_item_id + b * LL + 128, item_emb, tid);

    const int rA   = wid * 16 + g;
    const int dAt  = tid & 127;
    const int half = tid >> 7;
    float attnReg = 0.0f;

    compute_chunk<128>(smem, OFF_SA0, in_item_id + b * LL,
                       afb0, attnReg, tid, wid, g, tg, sx, rA, dAt, half);
    compute_chunk<72>(smem, OFF_SA1, in_item_id + b * LL + 128,
                      afb0, attnReg, tid, wid, g, tg, sx, rA, dAt, half);

    if (tid >= 128) redS[dAt] = attnReg;
    __syncthreads();
    if (tid < 128) g_attn[b * 128 + tid] = attnReg + redS[tid];
}

// ============================================================================
// Fused MLP tail: R9 version (fp32 weights, exact-ish sigmoid).
// ============================================================================
#define NB 4
#define TM_ATTN 0
#define TM_T    (NB*128)
#define TM_CAT  (2*NB*128)
#define TM_H1   (TM_CAT + NB*384)
#define TM_H2   (TM_H1 + NB*512)
#define TM_H3   (TM_H2 + NB*256)
#define TM_TOT  (TM_H3 + NB*128)   // 24576 B

__global__ __launch_bounds__(256, 4)
void mlp_tail_kernel(const int*   __restrict__ item_id,
                     const float* __restrict__ item_emb,
                     const float* __restrict__ nw,
                     const float* __restrict__ nb,
                     const float* __restrict__ dw1,
                     const float* __restrict__ db1,
                     const float* __restrict__ dw2,
                     const float* __restrict__ db2,
                     const float* __restrict__ dw3,
                     const float* __restrict__ db3,
                     const float* __restrict__ fw,
                     const float* __restrict__ fb,
                     const float* __restrict__ item_bias_tab,
                     float*       __restrict__ out)
{
    extern __shared__ float sm[];
    const int b0  = blockIdx.x * NB;
    const int tid = threadIdx.x;

    for (int e = tid; e < NB * 128; e += 256) {
        int bb = e >> 7, j = e & 127;
        sm[TM_ATTN + e] = g_attn[(b0 + bb) * 128 + j];
        long id = (long)__ldg(&item_id[b0 + bb]);
        sm[TM_T + e]    = __ldg(&item_emb[id * 128 + j]);
    }
    __syncthreads();

    // Phase A
    {
        const int j = tid & 127;
        const int rbase = (tid >> 7) * 2;
        float acc[2];
        float nbj = __ldg(&nb[j]);
        acc[0] = nbj; acc[1] = nbj;
        #pragma unroll 4
        for (int k = 0; k < 128; k += 4) {
            float w0 = __ldg(&nw[(k + 0) * 128 + j]);
            float w1 = __ldg(&nw[(k + 1) * 128 + j]);
            float w2 = __ldg(&nw[(k + 2) * 128 + j]);
            float w3 = __ldg(&nw[(k + 3) * 128 + j]);
            #pragma unroll
            for (int i = 0; i < 2; ++i) {
                float4 a = *reinterpret_cast<const float4*>(sm + TM_ATTN + (rbase + i) * 128 + k);
                acc[i] += a.x * w0 + a.y * w1 + a.z * w2 + a.w * w3;
            }
        }
        #pragma unroll
        for (int i = 0; i < 2; ++i) {
            int r = rbase + i;
            float a2 = acc[i];
            float t  = sm[TM_T + r * 128 + j];
            sm[TM_CAT + r * 384 + j]       = a2;
            sm[TM_CAT + r * 384 + 128 + j] = t;
            sm[TM_CAT + r * 384 + 256 + j] = t * a2;
        }
    }
    __syncthreads();

    // Phase B: 384 -> 512
    {
        const int j = tid;
        float acc0[NB], acc1[NB];
        float bj0 = __ldg(&db1[j]), bj1 = __ldg(&db1[j + 256]);
        #pragma unroll
        for (int r = 0; r < NB; ++r) { acc0[r] = bj0; acc1[r] = bj1; }
        #pragma unroll 4
        for (int k = 0; k < 384; k += 4) {
            float w0a = __ldg(&dw1[(k + 0) * 512 + j]);
            float w1a = __ldg(&dw1[(k + 1) * 512 + j]);
            float w2a = __ldg(&dw1[(k + 2) * 512 + j]);
            float w3a = __ldg(&dw1[(k + 3) * 512 + j]);
            float w0b = __ldg(&dw1[(k + 0) * 512 + j + 256]);
            float w1b = __ldg(&dw1[(k + 1) * 512 + j + 256]);
            float w2b = __ldg(&dw1[(k + 2) * 512 + j + 256]);
            float w3b = __ldg(&dw1[(k + 3) * 512 + j + 256]);
            #pragma unroll
            for (int r = 0; r < NB; ++r) {
                float4 a = *reinterpret_cast<const float4*>(sm + TM_CAT + r * 384 + k);
                acc0[r] += a.x * w0a + a.y * w1a + a.z * w2a + a.w * w3a;
                acc1[r] += a.x * w0b + a.y * w1b + a.z * w2b + a.w * w3b;
            }
        }
        #pragma unroll
        for (int r = 0; r < NB; ++r) {
            sm[TM_H1 + r * 512 + j]       = sigm(acc0[r]);
            sm[TM_H1 + r * 512 + j + 256] = sigm(acc1[r]);
        }
    }
    __syncthreads();

    // Phase C: 512 -> 256
    {
        const int j = tid;
        float acc[NB];
        float bj = __ldg(&db2[j]);
        #pragma unroll
        for (int r = 0; r < NB; ++r) acc[r] = bj;
        #pragma unroll 4
        for (int k = 0; k < 512; k += 4) {
            float w0 = __ldg(&dw2[(k + 0) * 256 + j]);
            float w1 = __ldg(&dw2[(k + 1) * 256 + j]);
            float w2 = __ldg(&dw2[(k + 2) * 256 + j]);
            float w3 = __ldg(&dw2[(k + 3) * 256 + j]);
            #pragma unroll
            for (int r = 0; r < NB; ++r) {
                float4 a = *reinterpret_cast<const float4*>(sm + TM_H1 + r * 512 + k);
                acc[r] += a.x * w0 + a.y * w1 + a.z * w2 + a.w * w3;
            }
        }
        #pragma unroll
        for (int r = 0; r < NB; ++r)
            sm[TM_H2 + r * 256 + j] = sigm(acc[r]);
    }
    __syncthreads();

    // Phase D: 256 -> 128
    {
        const int j = tid & 127;
        const int rbase = (tid >> 7) * 2;
        float acc[2];
        float bj = __ldg(&db3[j]);
        acc[0] = bj; acc[1] = bj;
        #pragma unroll 4
        for (int k = 0; k < 256; k += 4) {
            float w0 = __ldg(&dw3[(k + 0) * 128 + j]);
            float w1 = __ldg(&dw3[(k + 1) * 128 + j]);
            float w2 = __ldg(&dw3[(k + 2) * 128 + j]);
            float w3 = __ldg(&dw3[(k + 3) * 128 + j]);
            #pragma unroll
            for (int i = 0; i < 2; ++i) {
                float4 a = *reinterpret_cast<const float4*>(sm + TM_H2 + (rbase + i) * 256 + k);
                acc[i] += a.x * w0 + a.y * w1 + a.z * w2 + a.w * w3;
            }
        }
        #pragma unroll
        for (int i = 0; i < 2; ++i)
            sm[TM_H3 + (rbase + i) * 128 + j] = sigm(acc[i]);
    }
    __syncthreads();

    // Phase E
    {
        const int wid  = tid >> 5;
        const int lane = tid & 31;
        if (wid < NB) {
            float v = 0.0f;
            #pragma unroll
            for (int q = 0; q < 4; ++q)
                v += sm[TM_H3 + wid * 128 + lane + 32 * q] * __ldg(&fw[lane + 32 * q]);
            #pragma unroll
            for (int m = 16; m > 0; m >>= 1) v += __shfl_xor_sync(0xffffffffu, v, m);
            if (lane == 0) {
                int b = b0 + wid;
                out[b] = v + __ldg(&fb[0]) + __ldg(&item_bias_tab[item_id[b]]);
            }
        }
    }
}

// ============================================================================
extern "C" void kernel_launch(void* const* d_in, const int* in_sizes, int n_in,
                              void* d_out, int out_size)
{
    const int*   in_item_id    = (const int*)  d_in[0];
    const int*   item_id       = (const int*)  d_in[1];
    const float* item_emb      = (const float*)d_in[2];
    const float* item_bias_tab = (const float*)d_in[3];
    const float* aw1 = (const float*)d_in[4];
    const float* ab1 = (const float*)d_in[5];
    const float* aw2 = (const float*)d_in[6];
    const float* ab2 = (const float*)d_in[7];
    const float* afw = (const float*)d_in[8];
    const float* afb = (const float*)d_in[9];
    const float* nw  = (const float*)d_in[10];
    const float* nb  = (const float*)d_in[11];
    const float* dw1 = (const float*)d_in[12];
    const float* db1 = (const float*)d_in[13];
    const float* dw2 = (const float*)d_in[14];
    const float* db2 = (const float*)d_in[15];
    const float* dw3 = (const float*)d_in[16];
    const float* db3 = (const float*)d_in[17];
    const float* fw  = (const float*)d_in[18];
    const float* fb  = (const float*)d_in[19];
    float* out = (float*)d_out;

    cudaFuncSetAttribute(din_attention_mma,
                         cudaFuncAttributeMaxDynamicSharedMemorySize, SMEM_BYTES);
    cudaFuncSetAttribute(mlp_tail_kernel,
                         cudaFuncAttributeMaxDynamicSharedMemorySize,
                         (int)(TM_TOT * sizeof(float)));

    cvec_kernel<<<BB / 16, 512>>>(item_id, item_emb, aw1, ab1);
    din_attention_mma<<<BB, 256, SMEM_BYTES>>>(in_item_id, item_id, item_emb,
                                               aw1, aw2, ab2, afw, afb);
    mlp_tail_kernel<<<BB / NB, 256, TM_TOT * sizeof(float)>>>(
        item_id, item_emb, nw, nb, dw1, db1, dw2, db2, dw3, db3,
        fw, fb, item_bias_tab, out);
}

// round 14
// speedup vs baseline: 4.6346x; 1.0022x over previous
#include <cuda_runtime.h>
#include <cuda_fp16.h>
#include <cstdint>

// ============================================================================
// DIN scorer R13: back to known-good numerics.
//  - tail: exact R11 (fp32 weights, __fdividef sigmoid) — tail is
//    precision-critical end-to-end (R10: 1.3e-3, R12: 1.6e-3 both from
//    fp16/tanh in the tail). No precision tricks below g_attn, ever.
//  - cvec: R12 geometry (8 batches/CTA, grid 256) — fp32, same math.
//  - din: unchanged (fp16 single-plane MMAs + tanh.approx, measured 1.45e-7).
// ============================================================================

#define BB 2048
#define LL 200

__device__ float g_attn[BB * 128];
__device__ float g_cvec[BB * 128];

// din-side sigmoid (attenuated path, measured safe)
__device__ __forceinline__ float sigm_fast(float x) {
    float y;
    asm("tanh.approx.f32 %0, %1;" : "=f"(y) : "f"(0.5f * x));
    return fmaf(0.5f, y, 0.5f);
}
// tail-side sigmoid (unattenuated path, near-exact)
__device__ __forceinline__ float sigm(float x) {
    return __fdividef(1.0f, 1.0f + __expf(-x));
}

__device__ __forceinline__ uint32_t pack2h(float a, float b) {
    return ((uint32_t)__half_as_ushort(__float2half_rn(b)) << 16)
         |  (uint32_t)__half_as_ushort(__float2half_rn(a));
}

__device__ __forceinline__ void mma_f16(float* c, uint32_t a0, uint32_t a1,
                                        uint32_t a2, uint32_t a3,
                                        uint32_t b0, uint32_t b1) {
    asm("mma.sync.aligned.m16n8k16.row.col.f32.f16.f16.f32 "
        "{%0,%1,%2,%3}, {%4,%5,%6,%7}, {%8,%9}, {%0,%1,%2,%3};"
        : "+f"(c[0]), "+f"(c[1]), "+f"(c[2]), "+f"(c[3])
        : "r"(a0), "r"(a1), "r"(a2), "r"(a3), "r"(b0), "r"(b1));
}

__device__ __forceinline__ int pidx(int row, int pair) {
    return row * 64 + (pair ^ ((row & 7) << 2));
}

// ============================================================================
// cvec_kernel: 8 batches/CTA, grid 256 (full wave coverage), pure fp32
// ============================================================================
__global__ __launch_bounds__(512, 2)
void cvec_kernel(const int*   __restrict__ item_id,
                 const float* __restrict__ item_emb,
                 const float* __restrict__ aw1,
                 const float* __restrict__ ab1)
{
    __shared__ float tT[128 * 8];          // [k][b]
    __shared__ float part[4 * 8 * 128];
    const int b0  = blockIdx.x * 8;
    const int tid = threadIdx.x;

    for (int e = tid; e < 128 * 8; e += 512) {
        int k = e >> 3, bb = e & 7;
        long id = (long)__ldg(&item_id[b0 + bb]);
        tT[e] = __ldg(&item_emb[id * 128 + k]);
    }
    __syncthreads();

    const int j  = tid & 127;
    const int kq = tid >> 7;               // 0..3
    float acc[8];
    #pragma unroll
    for (int r = 0; r < 8; ++r) acc[r] = 0.0f;

    #pragma unroll 8
    for (int kk = 0; kk < 32; ++kk) {
        int k = kq * 32 + kk;
        float w = __ldg(&aw1[k * 128 + j]) + __ldg(&aw1[(256 + k) * 128 + j]);
        const float4* tp = reinterpret_cast<const float4*>(tT + k * 8);
        float4 t0 = tp[0], t1 = tp[1];
        acc[0] += t0.x * w; acc[1] += t0.y * w;
        acc[2] += t0.z * w; acc[3] += t0.w * w;
        acc[4] += t1.x * w; acc[5] += t1.y * w;
        acc[6] += t1.z * w; acc[7] += t1.w * w;
    }
    #pragma unroll
    for (int r = 0; r < 8; ++r)
        part[(kq * 8 + r) * 128 + j] = acc[r];
    __syncthreads();

    for (int e = tid; e < 8 * 128; e += 512) {
        int bb = e >> 7, jj = e & 127;
        float s = part[(0 * 8 + bb) * 128 + jj] + part[(1 * 8 + bb) * 128 + jj]
                + part[(2 * 8 + bb) * 128 + jj] + part[(3 * 8 + bb) * 128 + jj]
                + __ldg(&ab1[jj]);
        g_cvec[(b0 + bb) * 128 + jj] = s;
    }
}

// ---- smem byte offsets (din) — 105KB, 2 CTAs/SM ----
#define OFF_SA0     0
#define OFF_SA1     32768
#define OFF_B1      53248
#define OFF_B2      86016
#define OFF_T       102400
#define OFF_CVEC    102912
#define OFF_SCORE   103424
#define OFF_AB2     103936
#define OFF_AFW     104192
#define OFF_RED     104448
#define SMEM_BYTES  104960

template<int CR>
__device__ __forceinline__ void gather_chunk(char* smem, int offHI,
                                             const int* __restrict__ ids,
                                             const float* __restrict__ item_emb,
                                             int tid)
{
    uint32_t* dHI = (uint32_t*)(smem + offHI);
    constexpr int NIT = CR * 32 / 256;
    int idv[NIT];
    #pragma unroll
    for (int i = 0; i < NIT; ++i)
        idv[i] = __ldg(&ids[(tid + i * 256) >> 5]);
    #pragma unroll
    for (int i = 0; i < NIT; ++i) {
        int e = tid + i * 256, row = e >> 5, q = e & 31;
        float4 v = __ldg(reinterpret_cast<const float4*>(item_emb + (long)idv[i] * 128) + q);
        int a = pidx(row, q * 2);
        *(uint2*)(dHI + a) = make_uint2(pack2h(v.x, v.y), pack2h(v.z, v.w));
    }
}

template<int CR>
__device__ __forceinline__ void compute_chunk(char* smem, int offHI,
                                              const int* __restrict__ ids,
                                              float afb0, float& attnReg,
                                              int tid, int wid, int g, int tg, int sx,
                                              int rA, int dAt, int half)
{
    uint32_t* saHI = (uint32_t*)(smem + offHI);
    uint32_t* b1P  = (uint32_t*)(smem + OFF_B1);
    uint32_t* b2P  = (uint32_t*)(smem + OFF_B2);
    float* cvec   = (float*)(smem + OFF_CVEC);
    float* scoreS = (float*)(smem + OFF_SCORE);
    float* ab2S   = (float*)(smem + OFF_AB2);
    float* afwS   = (float*)(smem + OFF_AFW);

    const bool act = (wid * 16 < CR);

    uint32_t hT[16], hB[16];

    if (act) {
        float acc[16][4];
        #pragma unroll
        for (int nt = 0; nt < 16; ++nt)
            #pragma unroll
            for (int i = 0; i < 4; ++i) acc[nt][i] = 0.0f;

        const int rTop = rA * 64, rBot = (rA + 8) * 64;
        #pragma unroll
        for (int ks = 0; ks < 8; ++ks) {
            const int p0 = (8 * ks + tg) ^ sx;
            const int p1 = p0 ^ 4;
            uint32_t ah0 = saHI[rTop + p0], ah1 = saHI[rBot + p0];
            uint32_t ah2 = saHI[rTop + p1], ah3 = saHI[rBot + p1];
            #pragma unroll
            for (int nt = 0; nt < 16; ++nt) {
                const int nb = (8 * nt + g) * 64;
                mma_f16(acc[nt], ah0, ah1, ah2, ah3, b1P[nb + p0], b1P[nb + p1]);
            }
        }
        #pragma unroll
        for (int nt = 0; nt < 16; ++nt) {
            const int c0 = 8 * nt + 2 * tg;
            float t0 = sigm_fast(acc[nt][0] + cvec[c0]);
            float t1 = sigm_fast(acc[nt][1] + cvec[c0 + 1]);
            float b0 = sigm_fast(acc[nt][2] + cvec[c0]);
            float b1 = sigm_fast(acc[nt][3] + cvec[c0 + 1]);
            hT[nt] = pack2h(t0, t1);
            hB[nt] = pack2h(b0, b1);
        }
    }

    float acc2[8][4];
    #pragma unroll
    for (int nt = 0; nt < 8; ++nt)
        #pragma unroll
        for (int i = 0; i < 4; ++i) acc2[nt][i] = 0.0f;

    if (act) {
        #pragma unroll
        for (int ks = 0; ks < 8; ++ks) {
            const int p0 = (8 * ks + tg) ^ sx;
            const int p1 = p0 ^ 4;
            uint32_t ah0 = hT[2 * ks],     ah1 = hB[2 * ks];
            uint32_t ah2 = hT[2 * ks + 1], ah3 = hB[2 * ks + 1];
            #pragma unroll
            for (int nt = 0; nt < 8; ++nt) {
                const int nb = (8 * nt + g) * 64;
                mma_f16(acc2[nt], ah0, ah1, ah2, ah3, b2P[nb + p0], b2P[nb + p1]);
            }
        }
    }

    {
        float vT = 0.0f, vB = 0.0f;
        #pragma unroll
        for (int nt = 0; nt < 8; ++nt) {
            const int c0 = 8 * nt + 2 * tg;
            vT += sigm_fast(acc2[nt][0] + ab2S[c0])     * afwS[c0];
            vT += sigm_fast(acc2[nt][1] + ab2S[c0 + 1]) * afwS[c0 + 1];
            vB += sigm_fast(acc2[nt][2] + ab2S[c0])     * afwS[c0];
            vB += sigm_fast(acc2[nt][3] + ab2S[c0 + 1]) * afwS[c0 + 1];
        }
        vT += __shfl_xor_sync(0xffffffffu, vT, 1);
        vT += __shfl_xor_sync(0xffffffffu, vT, 2);
        vB += __shfl_xor_sync(0xffffffffu, vB, 1);
        vB += __shfl_xor_sync(0xffffffffu, vB, 2);
        if (tg == 0) {
            int r0 = rA, r1 = rA + 8;
            float s0 = 0.0f, s1 = 0.0f;
            if (act && r0 < CR) {
                int id = __ldg(&ids[r0]);
                s0 = (id == 0) ? 0.0f : (vT + afb0);
            }
            if (act && r1 < CR) {
                int id = __ldg(&ids[r1]);
                s1 = (id == 0) ? 0.0f : (vB + afb0);
            }
            scoreS[r0] = s0;
            if (r1 < 128) scoreS[r1] = s1;
        }
    }
    __syncthreads();

    {
        const int h0 = half * (CR >> 1);
        const int h1 = h0 + (CR >> 1);
        const int pr = dAt >> 1, sel = (dAt & 1) * 16;
        for (int row = h0; row < h1; ++row) {
            float sc = scoreS[row];
            uint32_t whi = saHI[pidx(row, pr)];
            float s = __half2float(__ushort_as_half((unsigned short)(whi >> sel)));
            attnReg += sc * s;
        }
    }
    __syncthreads();
}

__global__ __launch_bounds__(256, 2)
void din_attention_mma(const int*   __restrict__ in_item_id,
                       const int*   __restrict__ item_id,
                       const float* __restrict__ item_emb,
                       const float* __restrict__ aw1,
                       const float* __restrict__ aw2,
                       const float* __restrict__ ab2,
                       const float* __restrict__ afw,
                       const float* __restrict__ afb)
{
    extern __shared__ char smem[];
    uint32_t* b1P = (uint32_t*)(smem + OFF_B1);
    uint32_t* b2P = (uint32_t*)(smem + OFF_B2);
    float* tS     = (float*)(smem + OFF_T);
    float* cvec   = (float*)(smem + OFF_CVEC);
    float* ab2S   = (float*)(smem + OFF_AB2);
    float* afwS   = (float*)(smem + OFF_AFW);
    float* redS   = (float*)(smem + OFF_RED);

    const int tid = threadIdx.x, wid = tid >> 5, lid = tid & 31;
    const int b = blockIdx.x;
    const int g  = lid >> 2;
    const int tg = lid & 3;
    const int sx = g << 2;

    if (tid < 128) {
        long id = (long)item_id[b];
        tS[tid]   = item_emb[id * 128 + tid];
        cvec[tid] = g_cvec[b * 128 + tid];
    }
    if (tid < 64) { ab2S[tid] = __ldg(&ab2[tid]); afwS[tid] = __ldg(&afw[tid]); }
    __syncthreads();

    gather_chunk<128>(smem, OFF_SA0, in_item_id + b * LL, item_emb, tid);

    for (int e = tid; e < 128 * 64; e += 256) {
        int j = e & 127, kp = e >> 7;
        int k0 = kp * 2, k1 = k0 + 1;
        float v0 = tS[k0] * __ldg(&aw1[(128 + k0) * 128 + j]) - __ldg(&aw1[(256 + k0) * 128 + j]);
        float v1 = tS[k1] * __ldg(&aw1[(128 + k1) * 128 + j]) - __ldg(&aw1[(256 + k1) * 128 + j]);
        b1P[pidx(j, kp)] = pack2h(v0, v1);
    }
    for (int e = tid; e < 64 * 64; e += 256) {
        int n = e & 63, kp = e >> 6;
        float v0 = __ldg(&aw2[(kp * 2) * 64 + n]);
        float v1 = __ldg(&aw2[(kp * 2 + 1) * 64 + n]);
        b2P[pidx(n, kp)] = pack2h(v0, v1);
    }
    const float afb0 = __ldg(&afb[0]);
    __syncthreads();

    gather_chunk<72>(smem, OFF_SA1, in_item_id + b * LL + 128, item_emb, tid);

    const int rA   = wid * 16 + g;
    const int dAt  = tid & 127;
    const int half = tid >> 7;
    float attnReg = 0.0f;

    compute_chunk<128>(smem, OFF_SA0, in_item_id + b * LL,
                       afb0, attnReg, tid, wid, g, tg, sx, rA, dAt, half);
    compute_chunk<72>(smem, OFF_SA1, in_item_id + b * LL + 128,
                      afb0, attnReg, tid, wid, g, tg, sx, rA, dAt, half);

    if (tid >= 128) redS[dAt] = attnReg;
    __syncthreads();
    if (tid < 128) g_attn[b * 128 + tid] = attnReg + redS[tid];
}

// ============================================================================
// Fused MLP tail: R11/R9 exact version (fp32 weights, exact-ish sigmoid).
// ============================================================================
#define NB 4
#define TM_ATTN 0
#define TM_T    (NB*128)
#define TM_CAT  (2*NB*128)
#define TM_H1   (TM_CAT + NB*384)
#define TM_H2   (TM_H1 + NB*512)
#define TM_H3   (TM_H2 + NB*256)
#define TM_TOT  (TM_H3 + NB*128)   // 24576 B

__global__ __launch_bounds__(256, 4)
void mlp_tail_kernel(const int*   __restrict__ item_id,
                     const float* __restrict__ item_emb,
                     const float* __restrict__ nw,
                     const float* __restrict__ nb,
                     const float* __restrict__ dw1,
                     const float* __restrict__ db1,
                     const float* __restrict__ dw2,
                     const float* __restrict__ db2,
                     const float* __restrict__ dw3,
                     const float* __restrict__ db3,
                     const float* __restrict__ fw,
                     const float* __restrict__ fb,
                     const float* __restrict__ item_bias_tab,
                     float*       __restrict__ out)
{
    extern __shared__ float sm[];
    const int b0  = blockIdx.x * NB;
    const int tid = threadIdx.x;

    for (int e = tid; e < NB * 128; e += 256) {
        int bb = e >> 7, j = e & 127;
        sm[TM_ATTN + e] = g_attn[(b0 + bb) * 128 + j];
        long id = (long)__ldg(&item_id[b0 + bb]);
        sm[TM_T + e]    = __ldg(&item_emb[id * 128 + j]);
    }
    __syncthreads();

    // Phase A
    {
        const int j = tid & 127;
        const int rbase = (tid >> 7) * 2;
        float acc[2];
        float nbj = __ldg(&nb[j]);
        acc[0] = nbj; acc[1] = nbj;
        #pragma unroll 4
        for (int k = 0; k < 128; k += 4) {
            float w0 = __ldg(&nw[(k + 0) * 128 + j]);
            float w1 = __ldg(&nw[(k + 1) * 128 + j]);
            float w2 = __ldg(&nw[(k + 2) * 128 + j]);
            float w3 = __ldg(&nw[(k + 3) * 128 + j]);
            #pragma unroll
            for (int i = 0; i < 2; ++i) {
                float4 a = *reinterpret_cast<const float4*>(sm + TM_ATTN + (rbase + i) * 128 + k);
                acc[i] += a.x * w0 + a.y * w1 + a.z * w2 + a.w * w3;
            }
        }
        #pragma unroll
        for (int i = 0; i < 2; ++i) {
            int r = rbase + i;
            float a2 = acc[i];
            float t  = sm[TM_T + r * 128 + j];
            sm[TM_CAT + r * 384 + j]       = a2;
            sm[TM_CAT + r * 384 + 128 + j] = t;
            sm[TM_CAT + r * 384 + 256 + j] = t * a2;
        }
    }
    __syncthreads();

    // Phase B: 384 -> 512
    {
        const int j = tid;
        float acc0[NB], acc1[NB];
        float bj0 = __ldg(&db1[j]), bj1 = __ldg(&db1[j + 256]);
        #pragma unroll
        for (int r = 0; r < NB; ++r) { acc0[r] = bj0; acc1[r] = bj1; }
        #pragma unroll 4
        for (int k = 0; k < 384; k += 4) {
            float w0a = __ldg(&dw1[(k + 0) * 512 + j]);
            float w1a = __ldg(&dw1[(k + 1) * 512 + j]);
            float w2a = __ldg(&dw1[(k + 2) * 512 + j]);
            float w3a = __ldg(&dw1[(k + 3) * 512 + j]);
            float w0b = __ldg(&dw1[(k + 0) * 512 + j + 256]);
            float w1b = __ldg(&dw1[(k + 1) * 512 + j + 256]);
            float w2b = __ldg(&dw1[(k + 2) * 512 + j + 256]);
            float w3b = __ldg(&dw1[(k + 3) * 512 + j + 256]);
            #pragma unroll
            for (int r = 0; r < NB; ++r) {
                float4 a = *reinterpret_cast<const float4*>(sm + TM_CAT + r * 384 + k);
                acc0[r] += a.x * w0a + a.y * w1a + a.z * w2a + a.w * w3a;
                acc1[r] += a.x * w0b + a.y * w1b + a.z * w2b + a.w * w3b;
            }
        }
        #pragma unroll
        for (int r = 0; r < NB; ++r) {
            sm[TM_H1 + r * 512 + j]       = sigm(acc0[r]);
            sm[TM_H1 + r * 512 + j + 256] = sigm(acc1[r]);
        }
    }
    __syncthreads();

    // Phase C: 512 -> 256
    {
        const int j = tid;
        float acc[NB];
        float bj = __ldg(&db2[j]);
        #pragma unroll
        for (int r = 0; r < NB; ++r) acc[r] = bj;
        #pragma unroll 4
        for (int k = 0; k < 512; k += 4) {
            float w0 = __ldg(&dw2[(k + 0) * 256 + j]);
            float w1 = __ldg(&dw2[(k + 1) * 256 + j]);
            float w2 = __ldg(&dw2[(k + 2) * 256 + j]);
            float w3 = __ldg(&dw2[(k + 3) * 256 + j]);
            #pragma unroll
            for (int r = 0; r < NB; ++r) {
                float4 a = *reinterpret_cast<const float4*>(sm + TM_H1 + r * 512 + k);
                acc[r] += a.x * w0 + a.y * w1 + a.z * w2 + a.w * w3;
            }
        }
        #pragma unroll
        for (int r = 0; r < NB; ++r)
            sm[TM_H2 + r * 256 + j] = sigm(acc[r]);
    }
    __syncthreads();

    // Phase D: 256 -> 128
    {
        const int j = tid & 127;
        const int rbase = (tid >> 7) * 2;
        float acc[2];
        float bj = __ldg(&db3[j]);
        acc[0] = bj; acc[1] = bj;
        #pragma unroll 4
        for (int k = 0; k < 256; k += 4) {
            float w0 = __ldg(&dw3[(k + 0) * 128 + j]);
            float w1 = __ldg(&dw3[(k + 1) * 128 + j]);
            float w2 = __ldg(&dw3[(k + 2) * 128 + j]);
            float w3 = __ldg(&dw3[(k + 3) * 128 + j]);
            #pragma unroll
            for (int i = 0; i < 2; ++i) {
                float4 a = *reinterpret_cast<const float4*>(sm + TM_H2 + (rbase + i) * 256 + k);
                acc[i] += a.x * w0 + a.y * w1 + a.z * w2 + a.w * w3;
            }
        }
        #pragma unroll
        for (int i = 0; i < 2; ++i)
            sm[TM_H3 + (rbase + i) * 128 + j] = sigm(acc[i]);
    }
    __syncthreads();

    // Phase E
    {
        const int wid  = tid >> 5;
        const int lane = tid & 31;
        if (wid < NB) {
            float v = 0.0f;
            #pragma unroll
            for (int q = 0; q < 4; ++q)
                v += sm[TM_H3 + wid * 128 + lane + 32 * q] * __ldg(&fw[lane + 32 * q]);
            #pragma unroll
            for (int m = 16; m > 0; m >>= 1) v += __shfl_xor_sync(0xffffffffu, v, m);
            if (lane == 0) {
                int b = b0 + wid;
                out[b] = v + __ldg(&fb[0]) + __ldg(&item_bias_tab[item_id[b]]);
            }
        }
    }
}

// ============================================================================
extern "C" void kernel_launch(void* const* d_in, const int* in_sizes, int n_in,
                              void* d_out, int out_size)
{
    const int*   in_item_id    = (const int*)  d_in[0];
    const int*   item_id       = (const int*)  d_in[1];
    const float* item_emb      = (const float*)d_in[2];
    const float* item_bias_tab = (const float*)d_in[3];
    const float* aw1 = (const float*)d_in[4];
    const float* ab1 = (const float*)d_in[5];
    const float* aw2 = (const float*)d_in[6];
    const float* ab2 = (const float*)d_in[7];
    const float* afw = (const float*)d_in[8];
    const float* afb = (const float*)d_in[9];
    const float* nw  = (const float*)d_in[10];
    const float* nb  = (const float*)d_in[11];
    const float* dw1 = (const float*)d_in[12];
    const float* db1 = (const float*)d_in[13];
    const float* dw2 = (const float*)d_in[14];
    const float* db2 = (const float*)d_in[15];
    const float* dw3 = (const float*)d_in[16];
    const float* db3 = (const float*)d_in[17];
    const float* fw  = (const float*)d_in[18];
    const float* fb  = (const float*)d_in[19];
    float* out = (float*)d_out;

    cudaFuncSetAttribute(din_attention_mma,
                         cudaFuncAttributeMaxDynamicSharedMemorySize, SMEM_BYTES);
    cudaFuncSetAttribute(mlp_tail_kernel,
                         cudaFuncAttributeMaxDynamicSharedMemorySize,
                         (int)(TM_TOT * sizeof(float)));

    cvec_kernel<<<BB / 8, 512>>>(item_id, item_emb, aw1, ab1);
    din_attention_mma<<<BB, 256, SMEM_BYTES>>>(in_item_id, item_id, item_emb,
                                               aw1, aw2, ab2, afw, afb);
    mlp_tail_kernel<<<BB / NB, 256, TM_TOT * sizeof(float)>>>(
        item_id, item_emb, nw, nb, dw1, db1, dw2, db2, dw3, db3,
        fw, fb, item_bias_tab, out);
}

// round 16
// speedup vs baseline: 5.0329x; 1.0859x over previous
#include <cuda_runtime.h>
#include <cuda_fp16.h>
#include <cstdint>

// ============================================================================
// DIN scorer R15 (= R14 with the dead-code compile error removed):
// din fragment loads via ldmatrix.m8n8.x4 (4 fragments per LSU instruction;
// 416 -> 104 shared loads per thread per chunk). Loaded words and MMA
// sequence are bit-identical to R13, so rel_err must match 1.448514e-07.
// Tail/cvec unchanged (tail precision-critical, fp32 end-to-end).
// ============================================================================

#define BB 2048
#define LL 200

__device__ float g_attn[BB * 128];
__device__ float g_cvec[BB * 128];

__device__ __forceinline__ float sigm_fast(float x) {
    float y;
    asm("tanh.approx.f32 %0, %1;" : "=f"(y) : "f"(0.5f * x));
    return fmaf(0.5f, y, 0.5f);
}
__device__ __forceinline__ float sigm(float x) {
    return __fdividef(1.0f, 1.0f + __expf(-x));
}

__device__ __forceinline__ uint32_t pack2h(float a, float b) {
    return ((uint32_t)__half_as_ushort(__float2half_rn(b)) << 16)
         |  (uint32_t)__half_as_ushort(__float2half_rn(a));
}

__device__ __forceinline__ void mma_f16(float* c, uint32_t a0, uint32_t a1,
                                        uint32_t a2, uint32_t a3,
                                        uint32_t b0, uint32_t b1) {
    asm("mma.sync.aligned.m16n8k16.row.col.f32.f16.f16.f32 "
        "{%0,%1,%2,%3}, {%4,%5,%6,%7}, {%8,%9}, {%0,%1,%2,%3};"
        : "+f"(c[0]), "+f"(c[1]), "+f"(c[2]), "+f"(c[3])
        : "r"(a0), "r"(a1), "r"(a2), "r"(a3), "r"(b0), "r"(b1));
}

__device__ __forceinline__ void ldsm_x4(uint32_t& r0, uint32_t& r1,
                                        uint32_t& r2, uint32_t& r3,
                                        uint32_t saddr) {
    asm volatile("ldmatrix.sync.aligned.m8n8.x4.shared.b16 {%0,%1,%2,%3}, [%4];"
        : "=r"(r0), "=r"(r1), "=r"(r2), "=r"(r3) : "r"(saddr));
}

__device__ __forceinline__ int pidx(int row, int pair) {
    return row * 64 + (pair ^ ((row & 7) << 2));
}

// ============================================================================
// cvec_kernel: 8 batches/CTA, grid 256 (9.7us)
// ============================================================================
__global__ __launch_bounds__(512, 2)
void cvec_kernel(const int*   __restrict__ item_id,
                 const float* __restrict__ item_emb,
                 const float* __restrict__ aw1,
                 const float* __restrict__ ab1)
{
    __shared__ float tT[128 * 8];
    __shared__ float part[4 * 8 * 128];
    const int b0  = blockIdx.x * 8;
    const int tid = threadIdx.x;

    for (int e = tid; e < 128 * 8; e += 512) {
        int k = e >> 3, bb = e & 7;
        long id = (long)__ldg(&item_id[b0 + bb]);
        tT[e] = __ldg(&item_emb[id * 128 + k]);
    }
    __syncthreads();

    const int j  = tid & 127;
    const int kq = tid >> 7;
    float acc[8];
    #pragma unroll
    for (int r = 0; r < 8; ++r) acc[r] = 0.0f;

    #pragma unroll 8
    for (int kk = 0; kk < 32; ++kk) {
        int k = kq * 32 + kk;
        float w = __ldg(&aw1[k * 128 + j]) + __ldg(&aw1[(256 + k) * 128 + j]);
        const float4* tp = reinterpret_cast<const float4*>(tT + k * 8);
        float4 t0 = tp[0], t1 = tp[1];
        acc[0] += t0.x * w; acc[1] += t0.y * w;
        acc[2] += t0.z * w; acc[3] += t0.w * w;
        acc[4] += t1.x * w; acc[5] += t1.y * w;
        acc[6] += t1.z * w; acc[7] += t1.w * w;
    }
    #pragma unroll
    for (int r = 0; r < 8; ++r)
        part[(kq * 8 + r) * 128 + j] = acc[r];
    __syncthreads();

    for (int e = tid; e < 8 * 128; e += 512) {
        int bb = e >> 7, jj = e & 127;
        float s = part[(0 * 8 + bb) * 128 + jj] + part[(1 * 8 + bb) * 128 + jj]
                + part[(2 * 8 + bb) * 128 + jj] + part[(3 * 8 + bb) * 128 + jj]
                + __ldg(&ab1[jj]);
        g_cvec[(b0 + bb) * 128 + jj] = s;
    }
}

// ---- smem byte offsets (din) — 105KB, 2 CTAs/SM ----
#define OFF_SA0     0
#define OFF_SA1     32768
#define OFF_B1      53248
#define OFF_B2      86016
#define OFF_T       102400
#define OFF_CVEC    102912
#define OFF_SCORE   103424
#define OFF_AB2     103936
#define OFF_AFW     104192
#define OFF_RED     104448
#define SMEM_BYTES  104960

template<int CR>
__device__ __forceinline__ void gather_chunk(char* smem, int offHI,
                                             const int* __restrict__ ids,
                                             const float* __restrict__ item_emb,
                                             int tid)
{
    uint32_t* dHI = (uint32_t*)(smem + offHI);
    constexpr int NIT = CR * 32 / 256;
    int idv[NIT];
    #pragma unroll
    for (int i = 0; i < NIT; ++i)
        idv[i] = __ldg(&ids[(tid + i * 256) >> 5]);
    #pragma unroll
    for (int i = 0; i < NIT; ++i) {
        int e = tid + i * 256, row = e >> 5, q = e & 31;
        float4 v = __ldg(reinterpret_cast<const float4*>(item_emb + (long)idv[i] * 128) + q);
        int a = pidx(row, q * 2);
        *(uint2*)(dHI + a) = make_uint2(pack2h(v.x, v.y), pack2h(v.z, v.w));
    }
}

template<int CR>
__device__ __forceinline__ void compute_chunk(char* smem, int offHI,
                                              const int* __restrict__ ids,
                                              float afb0, float& attnReg,
                                              int tid, int wid, int g, int tg,
                                              int rA, int dAt, int half)
{
    uint32_t* saHI = (uint32_t*)(smem + offHI);
    float* cvec   = (float*)(smem + OFF_CVEC);
    float* scoreS = (float*)(smem + OFF_SCORE);
    float* ab2S   = (float*)(smem + OFF_AB2);
    float* afwS   = (float*)(smem + OFF_AFW);

    const int lid = tid & 31;
    const uint32_t saSH = (uint32_t)__cvta_generic_to_shared(saHI);
    const uint32_t b1SH = (uint32_t)__cvta_generic_to_shared(smem + OFF_B1);
    const uint32_t b2SH = (uint32_t)__cvta_generic_to_shared(smem + OFF_B2);

    // ldmatrix lane roles: lane addresses matrix lid>>3, row lid&7
    const int n_local = lid & 7;
    const int mtx     = lid >> 3;                              // 0..3
    const int rowA    = wid * 16 + 8 * (mtx & 1) + n_local;    // A: {top,bot} x {klo,khi}
    const int khA     = mtx >> 1;
    const int ntoff   = mtx >> 1;                              // B: {nt,nt+1} x {klo,khi}
    const int khB     = mtx & 1;

    const bool act = (wid * 16 < CR);

    uint32_t hT[16], hB[16];

    if (act) {
        // ===== GEMM1: D1 = s @ Mb (ldmatrix fragments, fp32 accum) =====
        float acc[16][4];
        #pragma unroll
        for (int nt = 0; nt < 16; ++nt)
            #pragma unroll
            for (int i = 0; i < 4; ++i) acc[nt][i] = 0.0f;

        #pragma unroll
        for (int ks = 0; ks < 8; ++ks) {
            uint32_t a0, a1, a2, a3;
            ldsm_x4(a0, a1, a2, a3,
                    saSH + 4u * (uint32_t)pidx(rowA, 8 * ks + 4 * khA));
            #pragma unroll
            for (int nt2 = 0; nt2 < 8; ++nt2) {
                const int nt = 2 * nt2;
                const int rowB = 8 * (nt + ntoff) + n_local;
                uint32_t b0, b1, b2, b3;
                ldsm_x4(b0, b1, b2, b3,
                        b1SH + 4u * (uint32_t)pidx(rowB, 8 * ks + 4 * khB));
                mma_f16(acc[nt],     a0, a1, a2, a3, b0, b1);
                mma_f16(acc[nt + 1], a0, a1, a2, a3, b2, b3);
            }
        }
        #pragma unroll
        for (int nt = 0; nt < 16; ++nt) {
            const int c0 = 8 * nt + 2 * tg;
            float t0 = sigm_fast(acc[nt][0] + cvec[c0]);
            float t1 = sigm_fast(acc[nt][1] + cvec[c0 + 1]);
            float b0 = sigm_fast(acc[nt][2] + cvec[c0]);
            float b1 = sigm_fast(acc[nt][3] + cvec[c0 + 1]);
            hT[nt] = pack2h(t0, t1);
            hB[nt] = pack2h(b0, b1);
        }
    }

    float acc2[8][4];
    #pragma unroll
    for (int nt = 0; nt < 8; ++nt)
        #pragma unroll
        for (int i = 0; i < 4; ++i) acc2[nt][i] = 0.0f;

    if (act) {
        // ===== GEMM2: D2 = h1 @ aw2 (A in regs, B via ldmatrix) =====
        #pragma unroll
        for (int ks = 0; ks < 8; ++ks) {
            uint32_t ah0 = hT[2 * ks],     ah1 = hB[2 * ks];
            uint32_t ah2 = hT[2 * ks + 1], ah3 = hB[2 * ks + 1];
            #pragma unroll
            for (int nt2 = 0; nt2 < 4; ++nt2) {
                const int nt = 2 * nt2;
                const int rowB = 8 * (nt + ntoff) + n_local;
                uint32_t b0, b1, b2, b3;
                ldsm_x4(b0, b1, b2, b3,
                        b2SH + 4u * (uint32_t)pidx(rowB, 8 * ks + 4 * khB));
                mma_f16(acc2[nt],     ah0, ah1, ah2, ah3, b0, b1);
                mma_f16(acc2[nt + 1], ah0, ah1, ah2, ah3, b2, b3);
            }
        }
    }

    {
        float vT = 0.0f, vB = 0.0f;
        #pragma unroll
        for (int nt = 0; nt < 8; ++nt) {
            const int c0 = 8 * nt + 2 * tg;
            vT += sigm_fast(acc2[nt][0] + ab2S[c0])     * afwS[c0];
            vT += sigm_fast(acc2[nt][1] + ab2S[c0 + 1]) * afwS[c0 + 1];
            vB += sigm_fast(acc2[nt][2] + ab2S[c0])     * afwS[c0];
            vB += sigm_fast(acc2[nt][3] + ab2S[c0 + 1]) * afwS[c0 + 1];
        }
        vT += __shfl_xor_sync(0xffffffffu, vT, 1);
        vT += __shfl_xor_sync(0xffffffffu, vT, 2);
        vB += __shfl_xor_sync(0xffffffffu, vB, 1);
        vB += __shfl_xor_sync(0xffffffffu, vB, 2);
        if (tg == 0) {
            int r0 = rA, r1 = rA + 8;
            float s0 = 0.0f, s1 = 0.0f;
            if (act && r0 < CR) {
                int id = __ldg(&ids[r0]);
                s0 = (id == 0) ? 0.0f : (vT + afb0);
            }
            if (act && r1 < CR) {
                int id = __ldg(&ids[r1]);
                s1 = (id == 0) ? 0.0f : (vB + afb0);
            }
            scoreS[r0] = s0;
            if (r1 < 128) scoreS[r1] = s1;
        }
    }
    __syncthreads();

    {
        const int h0 = half * (CR >> 1);
        const int h1 = h0 + (CR >> 1);
        const int pr = dAt >> 1, sel = (dAt & 1) * 16;
        for (int row = h0; row < h1; ++row) {
            float sc = scoreS[row];
            uint32_t whi = saHI[pidx(row, pr)];
            float s = __half2float(__ushort_as_half((unsigned short)(whi >> sel)));
            attnReg += sc * s;
        }
    }
    __syncthreads();
}

__global__ __launch_bounds__(256, 2)
void din_attention_mma(const int*   __restrict__ in_item_id,
                       const int*   __restrict__ item_id,
                       const float* __restrict__ item_emb,
                       const float* __restrict__ aw1,
                       const float* __restrict__ aw2,
                       const float* __restrict__ ab2,
                       const float* __restrict__ afw,
                       const float* __restrict__ afb)
{
    extern __shared__ char smem[];
    uint32_t* b1P = (uint32_t*)(smem + OFF_B1);
    uint32_t* b2P = (uint32_t*)(smem + OFF_B2);
    float* tS     = (float*)(smem + OFF_T);
    float* cvec   = (float*)(smem + OFF_CVEC);
    float* ab2S   = (float*)(smem + OFF_AB2);
    float* afwS   = (float*)(smem + OFF_AFW);
    float* redS   = (float*)(smem + OFF_RED);

    const int tid = threadIdx.x, wid = tid >> 5, lid = tid & 31;
    const int b = blockIdx.x;
    const int g  = lid >> 2;
    const int tg = lid & 3;

    if (tid < 128) {
        long id = (long)item_id[b];
        tS[tid]   = item_emb[id * 128 + tid];
        cvec[tid] = g_cvec[b * 128 + tid];
    }
    if (tid < 64) { ab2S[tid] = __ldg(&ab2[tid]); afwS[tid] = __ldg(&afw[tid]); }
    __syncthreads();

    gather_chunk<128>(smem, OFF_SA0, in_item_id + b * LL, item_emb, tid);

    for (int e = tid; e < 128 * 64; e += 256) {
        int j = e & 127, kp = e >> 7;
        int k0 = kp * 2, k1 = k0 + 1;
        float v0 = tS[k0] * __ldg(&aw1[(128 + k0) * 128 + j]) - __ldg(&aw1[(256 + k0) * 128 + j]);
        float v1 = tS[k1] * __ldg(&aw1[(128 + k1) * 128 + j]) - __ldg(&aw1[(256 + k1) * 128 + j]);
        b1P[pidx(j, kp)] = pack2h(v0, v1);
    }
    for (int e = tid; e < 64 * 64; e += 256) {
        int n = e & 63, kp = e >> 6;
        float v0 = __ldg(&aw2[(kp * 2) * 64 + n]);
        float v1 = __ldg(&aw2[(kp * 2 + 1) * 64 + n]);
        b2P[pidx(n, kp)] = pack2h(v0, v1);
    }
    const float afb0 = __ldg(&afb[0]);
    __syncthreads();

    gather_chunk<72>(smem, OFF_SA1, in_item_id + b * LL + 128, item_emb, tid);

    const int rA   = wid * 16 + g;
    const int dAt  = tid & 127;
    const int half = tid >> 7;
    float attnReg = 0.0f;

    compute_chunk<128>(smem, OFF_SA0, in_item_id + b * LL,
                       afb0, attnReg, tid, wid, g, tg, rA, dAt, half);
    compute_chunk<72>(smem, OFF_SA1, in_item_id + b * LL + 128,
                      afb0, attnReg, tid, wid, g, tg, rA, dAt, half);

    if (tid >= 128) redS[dAt] = attnReg;
    __syncthreads();
    if (tid < 128) g_attn[b * 128 + tid] = attnReg + redS[tid];
}

// ============================================================================
// Fused MLP tail: exact fp32 version (precision-critical; do not change).
// ============================================================================
#define NB 4
#define TM_ATTN 0
#define TM_T    (NB*128)
#define TM_CAT  (2*NB*128)
#define TM_H1   (TM_CAT + NB*384)
#define TM_H2   (TM_H1 + NB*512)
#define TM_H3   (TM_H2 + NB*256)
#define TM_TOT  (TM_H3 + NB*128)   // 24576 B

__global__ __launch_bounds__(256, 4)
void mlp_tail_kernel(const int*   __restrict__ item_id,
                     const float* __restrict__ item_emb,
                     const float* __restrict__ nw,
                     const float* __restrict__ nb,
                     const float* __restrict__ dw1,
                     const float* __restrict__ db1,
                     const float* __restrict__ dw2,
                     const float* __restrict__ db2,
                     const float* __restrict__ dw3,
                     const float* __restrict__ db3,
                     const float* __restrict__ fw,
                     const float* __restrict__ fb,
                     const float* __restrict__ item_bias_tab,
                     float*       __restrict__ out)
{
    extern __shared__ float sm[];
    const int b0  = blockIdx.x * NB;
    const int tid = threadIdx.x;

    for (int e = tid; e < NB * 128; e += 256) {
        int bb = e >> 7, j = e & 127;
        sm[TM_ATTN + e] = g_attn[(b0 + bb) * 128 + j];
        long id = (long)__ldg(&item_id[b0 + bb]);
        sm[TM_T + e]    = __ldg(&item_emb[id * 128 + j]);
    }
    __syncthreads();

    // Phase A
    {
        const int j = tid & 127;
        const int rbase = (tid >> 7) * 2;
        float acc[2];
        float nbj = __ldg(&nb[j]);
        acc[0] = nbj; acc[1] = nbj;
        #pragma unroll 4
        for (int k = 0; k < 128; k += 4) {
            float w0 = __ldg(&nw[(k + 0) * 128 + j]);
            float w1 = __ldg(&nw[(k + 1) * 128 + j]);
            float w2 = __ldg(&nw[(k + 2) * 128 + j]);
            float w3 = __ldg(&nw[(k + 3) * 128 + j]);
            #pragma unroll
            for (int i = 0; i < 2; ++i) {
                float4 a = *reinterpret_cast<const float4*>(sm + TM_ATTN + (rbase + i) * 128 + k);
                acc[i] += a.x * w0 + a.y * w1 + a.z * w2 + a.w * w3;
            }
        }
        #pragma unroll
        for (int i = 0; i < 2; ++i) {
            int r = rbase + i;
            float a2 = acc[i];
            float t  = sm[TM_T + r * 128 + j];
            sm[TM_CAT + r * 384 + j]       = a2;
            sm[TM_CAT + r * 384 + 128 + j] = t;
            sm[TM_CAT + r * 384 + 256 + j] = t * a2;
        }
    }
    __syncthreads();

    // Phase B: 384 -> 512
    {
        const int j = tid;
        float acc0[NB], acc1[NB];
        float bj0 = __ldg(&db1[j]), bj1 = __ldg(&db1[j + 256]);
        #pragma unroll
        for (int r = 0; r < NB; ++r) { acc0[r] = bj0; acc1[r] = bj1; }
        #pragma unroll 4
        for (int k = 0; k < 384; k += 4) {
            float w0a = __ldg(&dw1[(k + 0) * 512 + j]);
            float w1a = __ldg(&dw1[(k + 1) * 512 + j]);
            float w2a = __ldg(&dw1[(k + 2) * 512 + j]);
            float w3a = __ldg(&dw1[(k + 3) * 512 + j]);
            float w0b = __ldg(&dw1[(k + 0) * 512 + j + 256]);
            float w1b = __ldg(&dw1[(k + 1) * 512 + j + 256]);
            float w2b = __ldg(&dw1[(k + 2) * 512 + j + 256]);
            float w3b = __ldg(&dw1[(k + 3) * 512 + j + 256]);
            #pragma unroll
            for (int r = 0; r < NB; ++r) {
                float4 a = *reinterpret_cast<const float4*>(sm + TM_CAT + r * 384 + k);
                acc0[r] += a.x * w0a + a.y * w1a + a.z * w2a + a.w * w3a;
                acc1[r] += a.x * w0b + a.y * w1b + a.z * w2b + a.w * w3b;
            }
        }
        #pragma unroll
        for (int r = 0; r < NB; ++r) {
            sm[TM_H1 + r * 512 + j]       = sigm(acc0[r]);
            sm[TM_H1 + r * 512 + j + 256] = sigm(acc1[r]);
        }
    }
    __syncthreads();

    // Phase C: 512 -> 256
    {
        const int j = tid;
        float acc[NB];
        float bj = __ldg(&db2[j]);
        #pragma unroll
        for (int r = 0; r < NB; ++r) acc[r] = bj;
        #pragma unroll 4
        for (int k = 0; k < 512; k += 4) {
            float w0 = __ldg(&dw2[(k + 0) * 256 + j]);
            float w1 = __ldg(&dw2[(k + 1) * 256 + j]);
            float w2 = __ldg(&dw2[(k + 2) * 256 + j]);
            float w3 = __ldg(&dw2[(k + 3) * 256 + j]);
            #pragma unroll
            for (int r = 0; r < NB; ++r) {
                float4 a = *reinterpret_cast<const float4*>(sm + TM_H1 + r * 512 + k);
                acc[r] += a.x * w0 + a.y * w1 + a.z * w2 + a.w * w3;
            }
        }
        #pragma unroll
        for (int r = 0; r < NB; ++r)
            sm[TM_H2 + r * 256 + j] = sigm(acc[r]);
    }
    __syncthreads();

    // Phase D: 256 -> 128
    {
        const int j = tid & 127;
        const int rbase = (tid >> 7) * 2;
        float acc[2];
        float bj = __ldg(&db3[j]);
        acc[0] = bj; acc[1] = bj;
        #pragma unroll 4
        for (int k = 0; k < 256; k += 4) {
            float w0 = __ldg(&dw3[(k + 0) * 128 + j]);
            float w1 = __ldg(&dw3[(k + 1) * 128 + j]);
            float w2 = __ldg(&dw3[(k + 2) * 128 + j]);
            float w3 = __ldg(&dw3[(k + 3) * 128 + j]);
            #pragma unroll
            for (int i = 0; i < 2; ++i) {
                float4 a = *reinterpret_cast<const float4*>(sm + TM_H2 + (rbase + i) * 256 + k);
                acc[i] += a.x * w0 + a.y * w1 + a.z * w2 + a.w * w3;
            }
        }
        #pragma unroll
        for (int i = 0; i < 2; ++i)
            sm[TM_H3 + (rbase + i) * 128 + j] = sigm(acc[i]);
    }
    __syncthreads();

    // Phase E
    {
        const int wid  = tid >> 5;
        const int lane = tid & 31;
        if (wid < NB) {
            float v = 0.0f;
            #pragma unroll
            for (int q = 0; q < 4; ++q)
                v += sm[TM_H3 + wid * 128 + lane + 32 * q] * __ldg(&fw[lane + 32 * q]);
            #pragma unroll
            for (int m = 16; m > 0; m >>= 1) v += __shfl_xor_sync(0xffffffffu, v, m);
            if (lane == 0) {
                int b = b0 + wid;
                out[b] = v + __ldg(&fb[0]) + __ldg(&item_bias_tab[item_id[b]]);
            }
        }
    }
}

// ============================================================================
extern "C" void kernel_launch(void* const* d_in, const int* in_sizes, int n_in,
                              void* d_out, int out_size)
{
    const int*   in_item_id    = (const int*)  d_in[0];
    const int*   item_id       = (const int*)  d_in[1];
    const float* item_emb      = (const float*)d_in[2];
    const float* item_bias_tab = (const float*)d_in[3];
    const float* aw1 = (const float*)d_in[4];
    const float* ab1 = (const float*)d_in[5];
    const float* aw2 = (const float*)d_in[6];
    const float* ab2 = (const float*)d_in[7];
    const float* afw = (const float*)d_in[8];
    const float* afb = (const float*)d_in[9];
    const float* nw  = (const float*)d_in[10];
    const float* nb  = (const float*)d_in[11];
    const float* dw1 = (const float*)d_in[12];
    const float* db1 = (const float*)d_in[13];
    const float* dw2 = (const float*)d_in[14];
    const float* db2 = (const float*)d_in[15];
    const float* dw3 = (const float*)d_in[16];
    const float* db3 = (const float*)d_in[17];
    const float* fw  = (const float*)d_in[18];
    const float* fb  = (const float*)d_in[19];
    float* out = (float*)d_out;

    cudaFuncSetAttribute(din_attention_mma,
                         cudaFuncAttributeMaxDynamicSharedMemorySize, SMEM_BYTES);
    cudaFuncSetAttribute(mlp_tail_kernel,
                         cudaFuncAttributeMaxDynamicSharedMemorySize,
                         (int)(TM_TOT * sizeof(float)));

    cvec_kernel<<<BB / 8, 512>>>(item_id, item_emb, aw1, ab1);
    din_attention_mma<<<BB, 256, SMEM_BYTES>>>(in_item_id, item_id, item_emb,
                                               aw1, aw2, ab2, afw, afb);
    mlp_tail_kernel<<<BB / NB, 256, TM_TOT * sizeof(float)>>>(
        item_id, item_emb, nw, nb, dw1, db1, dw2, db2, dw3, db3,
        fw, fb, item_bias_tab, out);
}